// round 7
// baseline (speedup 1.0000x reference)
/*
 * R7: R6 + tgemm 2 CTAs/SM (launch_bounds(256,2), reduced reg pressure)
 *     + attention widened to 8 warps per CTA.
 */
#include <cuda_runtime.h>
#include <cuda_bf16.h>
#include <math.h>
#include <stdint.h>

#define DIM   768
#define NHEAD 12
#define HDIM  64
#define WS    14
#define NTOK  196
#define NWIN  25
#define BATCH 8
#define NWB   200
#define TOKW  39200
#define TOKW_PAD 39296
#define TOKX  32768
#define BH    2400

// ---------------- device scratch ----------------
__device__ __nv_bfloat16 g_a_h[(size_t)TOKW_PAD * DIM];
__device__ __nv_bfloat16 g_a_l[(size_t)TOKW_PAD * DIM];
__device__ __nv_bfloat16 g_ao_h[(size_t)TOKW_PAD * DIM];
__device__ __nv_bfloat16 g_ao_l[(size_t)TOKW_PAD * DIM];
__device__ __nv_bfloat16 g_b_h[(size_t)TOKX * DIM];
__device__ __nv_bfloat16 g_b_l[(size_t)TOKX * DIM];
__device__ __nv_bfloat16 g_h1_h[(size_t)TOKX * 3072];
__device__ __nv_bfloat16 g_h1_l[(size_t)TOKX * 3072];
__device__ __nv_bfloat16 g_wqkv_h[(size_t)2304 * 768];
__device__ __nv_bfloat16 g_wqkv_l[(size_t)2304 * 768];
__device__ __nv_bfloat16 g_wproj_h[(size_t)768 * 768];
__device__ __nv_bfloat16 g_wproj_l[(size_t)768 * 768];
__device__ __nv_bfloat16 g_w1_h[(size_t)3072 * 768];
__device__ __nv_bfloat16 g_w1_l[(size_t)3072 * 768];
__device__ __nv_bfloat16 g_w2_h[(size_t)768 * 3072];
__device__ __nv_bfloat16 g_w2_l[(size_t)768 * 3072];
__device__ float g_q[(size_t)BH * NTOK * HDIM];
__device__ float g_k[(size_t)BH * NTOK * HDIM];
__device__ float g_v[(size_t)BH * NTOK * HDIM];
__device__ float g_x2[(size_t)TOKX * DIM];

// ---------------- PTX helpers ----------------
__device__ __forceinline__ uint32_t smem_u32(const void* p) {
    uint32_t a;
    asm("{ .reg .u64 t; cvta.to.shared.u64 t, %1; cvt.u32.u64 %0, t; }" : "=r"(a) : "l"(p));
    return a;
}
__device__ __forceinline__ void cp16(uint32_t dst, const void* src) {
    asm volatile("cp.async.cg.shared.global [%0], [%1], 16;" :: "r"(dst), "l"(src));
}
__device__ __forceinline__ void ldsm_x4(uint32_t* r, uint32_t addr) {
    asm volatile("ldmatrix.sync.aligned.m8n8.x4.shared.b16 {%0,%1,%2,%3}, [%4];"
        : "=r"(r[0]), "=r"(r[1]), "=r"(r[2]), "=r"(r[3]) : "r"(addr));
}
__device__ __forceinline__ void ldsm_x2(uint32_t* r, uint32_t addr) {
    asm volatile("ldmatrix.sync.aligned.m8n8.x2.shared.b16 {%0,%1}, [%2];"
        : "=r"(r[0]), "=r"(r[1]) : "r"(addr));
}
__device__ __forceinline__ void mma_bf16(float* c, const uint32_t* a, const uint32_t* b) {
    asm volatile(
        "mma.sync.aligned.m16n8k16.row.col.f32.bf16.bf16.f32 "
        "{%0,%1,%2,%3}, {%4,%5,%6,%7}, {%8,%9}, {%0,%1,%2,%3};"
        : "+f"(c[0]), "+f"(c[1]), "+f"(c[2]), "+f"(c[3])
        : "r"(a[0]), "r"(a[1]), "r"(a[2]), "r"(a[3]), "r"(b[0]), "r"(b[1]));
}
__device__ __forceinline__ void bf16split(float v, __nv_bfloat16& h, __nv_bfloat16& l) {
    h = __float2bfloat16(v);
    l = __float2bfloat16(v - __bfloat162float(h));
}

// ---------------- weight transpose + bf16 split ----------------
__global__ __launch_bounds__(256) void wsplit_kernel(const float* __restrict__ W,
                                                     __nv_bfloat16* __restrict__ Wh,
                                                     __nv_bfloat16* __restrict__ Wl,
                                                     int K, int N)
{
    __shared__ float tile[32][33];
    int k0 = blockIdx.y * 32, n0 = blockIdx.x * 32;
    int tx = threadIdx.x & 31, ty = threadIdx.x >> 5;
    #pragma unroll
    for (int j = 0; j < 32; j += 8)
        tile[ty + j][tx] = W[(size_t)(k0 + ty + j) * N + n0 + tx];
    __syncthreads();
    #pragma unroll
    for (int j = 0; j < 32; j += 8) {
        float v = tile[tx][ty + j];
        __nv_bfloat16 h, l;
        bf16split(v, h, l);
        size_t o = (size_t)(n0 + ty + j) * K + k0 + tx;
        Wh[o] = h; Wl[o] = l;
    }
}

// ---------------- LayerNorm 1 (window partition + pad + bf16 split) ----------------
__global__ __launch_bounds__(256) void ln1_kernel(const float* __restrict__ x,
                                                  const float* __restrict__ g,
                                                  const float* __restrict__ b)
{
    int widx = blockIdx.x;
    int win = widx / NTOK, tok = widx - win * NTOK;
    int bb = win / NWIN, rem = win - bb * NWIN;
    int y = (rem / 5) * WS + tok / WS;
    int xx = (rem % 5) * WS + tok % WS;
    size_t ob = (size_t)widx * DIM;
    int tid = threadIdx.x;
    if (y >= 64 || xx >= 64) {
        for (int i = tid; i < DIM; i += 256) {
            g_a_h[ob + i] = __float2bfloat16(0.f);
            g_a_l[ob + i] = __float2bfloat16(0.f);
        }
        return;
    }
    const float* row = x + ((size_t)(bb * 64 + y) * 64 + xx) * DIM;
    float v0 = row[tid], v1 = row[tid + 256], v2 = row[tid + 512];
    float s = v0 + v1 + v2, sq = v0 * v0 + v1 * v1 + v2 * v2;
    #pragma unroll
    for (int off = 16; off; off >>= 1) {
        s  += __shfl_xor_sync(0xffffffffu, s, off);
        sq += __shfl_xor_sync(0xffffffffu, sq, off);
    }
    __shared__ float rs[8], rq[8], smu, srs;
    int wid = tid >> 5, lane = tid & 31;
    if (!lane) { rs[wid] = s; rq[wid] = sq; }
    __syncthreads();
    if (tid == 0) {
        float S = 0, Q = 0;
        #pragma unroll
        for (int i = 0; i < 8; i++) { S += rs[i]; Q += rq[i]; }
        float mu = S * (1.f / 768.f);
        float var = Q * (1.f / 768.f) - mu * mu;
        smu = mu; srs = rsqrtf(var + 1e-5f);
    }
    __syncthreads();
    float mu = smu, r = srs;
    #pragma unroll
    for (int p = 0; p < 3; p++) {
        int i = tid + p * 256;
        float vv = ((p == 0 ? v0 : p == 1 ? v1 : v2) - mu) * r * g[i] + b[i];
        __nv_bfloat16 h, l;
        bf16split(vv, h, l);
        g_a_h[ob + i] = h; g_a_l[ob + i] = l;
    }
}

// ---------------- LayerNorm 2 (bf16 split out) ----------------
__global__ __launch_bounds__(256) void ln2_kernel(const float* __restrict__ g,
                                                  const float* __restrict__ b)
{
    int tid = threadIdx.x;
    const float* row = g_x2 + (size_t)blockIdx.x * DIM;
    size_t ob = (size_t)blockIdx.x * DIM;
    float v0 = row[tid], v1 = row[tid + 256], v2 = row[tid + 512];
    float s = v0 + v1 + v2, sq = v0 * v0 + v1 * v1 + v2 * v2;
    #pragma unroll
    for (int off = 16; off; off >>= 1) {
        s  += __shfl_xor_sync(0xffffffffu, s, off);
        sq += __shfl_xor_sync(0xffffffffu, sq, off);
    }
    __shared__ float rs[8], rq[8], smu, srs;
    int wid = tid >> 5, lane = tid & 31;
    if (!lane) { rs[wid] = s; rq[wid] = sq; }
    __syncthreads();
    if (tid == 0) {
        float S = 0, Q = 0;
        #pragma unroll
        for (int i = 0; i < 8; i++) { S += rs[i]; Q += rq[i]; }
        float mu = S * (1.f / 768.f);
        float var = Q * (1.f / 768.f) - mu * mu;
        smu = mu; srs = rsqrtf(var + 1e-5f);
    }
    __syncthreads();
    float mu = smu, r = srs;
    #pragma unroll
    for (int p = 0; p < 3; p++) {
        int i = tid + p * 256;
        float vv = ((p == 0 ? v0 : p == 1 ? v1 : v2) - mu) * r * g[i] + b[i];
        __nv_bfloat16 h, l;
        bf16split(vv, h, l);
        g_b_h[ob + i] = h; g_b_l[ob + i] = l;
    }
}

// ---------------- mma.sync GEMM: D[M,N] = A[M,K] x Wt[N,K]^T, bf16x3 ----------------
#define TG_STAGE_B  40960
#define TG_MAT_B    10240
#define SMEM_TG     (2 * TG_STAGE_B)

template <int MODE>
__global__ __launch_bounds__(256, 2) void tgemm_kernel(const float* __restrict__ bias,
                                                       const float* __restrict__ aux,
                                                       float* __restrict__ outp)
{
    constexpr int K      = (MODE == 3) ? 3072 : 768;
    constexpr int Mreal  = (MODE <= 1) ? TOKW : TOKX;
    constexpr int NCHUNK = K / 32;
    const __nv_bfloat16* gAh = (MODE == 0) ? g_a_h : (MODE == 1) ? g_ao_h : (MODE == 2) ? g_b_h : g_h1_h;
    const __nv_bfloat16* gAl = (MODE == 0) ? g_a_l : (MODE == 1) ? g_ao_l : (MODE == 2) ? g_b_l : g_h1_l;
    const __nv_bfloat16* gBh = (MODE == 0) ? g_wqkv_h : (MODE == 1) ? g_wproj_h : (MODE == 2) ? g_w1_h : g_w2_h;
    const __nv_bfloat16* gBl = (MODE == 0) ? g_wqkv_l : (MODE == 1) ? g_wproj_l : (MODE == 2) ? g_w1_l : g_w2_l;

    extern __shared__ char smem_raw[];
    const uint32_t sbase = smem_u32(smem_raw);

    const int t = threadIdx.x;
    const int m0 = blockIdx.y * 128;
    const int n0 = blockIdx.x * 128;
    const int warp = t >> 5, lane = t & 31;
    const int wm = warp >> 2, wn = warp & 3;

    float acc[4][4][4];
    #pragma unroll
    for (int a = 0; a < 4; a++)
        #pragma unroll
        for (int b2 = 0; b2 < 4; b2++)
            #pragma unroll
            for (int c = 0; c < 4; c++) acc[a][b2][c] = 0.f;

    const int ldrow = t >> 2, ldseg = t & 3;
    const uint32_t sm_off0 = (uint32_t)(ldrow * 80 + ldseg * 16);
    const uint32_t sm_off1 = (uint32_t)((ldrow + 64) * 80 + ldseg * 16);

    {
        const uint32_t so = sbase;
        size_t ga0 = (size_t)(m0 + ldrow) * K + ldseg * 8;
        size_t ga1 = (size_t)(m0 + ldrow + 64) * K + ldseg * 8;
        size_t gb0 = (size_t)(n0 + ldrow) * K + ldseg * 8;
        size_t gb1 = (size_t)(n0 + ldrow + 64) * K + ldseg * 8;
        cp16(so + 0 * TG_MAT_B + sm_off0, gAh + ga0);
        cp16(so + 0 * TG_MAT_B + sm_off1, gAh + ga1);
        cp16(so + 1 * TG_MAT_B + sm_off0, gAl + ga0);
        cp16(so + 1 * TG_MAT_B + sm_off1, gAl + ga1);
        cp16(so + 2 * TG_MAT_B + sm_off0, gBh + gb0);
        cp16(so + 2 * TG_MAT_B + sm_off1, gBh + gb1);
        cp16(so + 3 * TG_MAT_B + sm_off0, gBl + gb0);
        cp16(so + 3 * TG_MAT_B + sm_off1, gBl + gb1);
        asm volatile("cp.async.commit_group;" ::: "memory");
    }

    const int a_row_in = (lane & 7) + (lane & 8);
    const int a_koff   = (lane >> 4) * 8;
    const int b_row_in = lane & 7;
    const int b_koff   = ((lane >> 3) & 1) * 8;

    for (int i = 0; i < NCHUNK; i++) {
        const int s = i & 1;
        if (i + 1 < NCHUNK) {
            const int k0 = (i + 1) * 32;
            const uint32_t so = sbase + (uint32_t)((s ^ 1) * TG_STAGE_B);
            size_t ga0 = (size_t)(m0 + ldrow) * K + k0 + ldseg * 8;
            size_t ga1 = (size_t)(m0 + ldrow + 64) * K + k0 + ldseg * 8;
            size_t gb0 = (size_t)(n0 + ldrow) * K + k0 + ldseg * 8;
            size_t gb1 = (size_t)(n0 + ldrow + 64) * K + k0 + ldseg * 8;
            cp16(so + 0 * TG_MAT_B + sm_off0, gAh + ga0);
            cp16(so + 0 * TG_MAT_B + sm_off1, gAh + ga1);
            cp16(so + 1 * TG_MAT_B + sm_off0, gAl + ga0);
            cp16(so + 1 * TG_MAT_B + sm_off1, gAl + ga1);
            cp16(so + 2 * TG_MAT_B + sm_off0, gBh + gb0);
            cp16(so + 2 * TG_MAT_B + sm_off1, gBh + gb1);
            cp16(so + 3 * TG_MAT_B + sm_off0, gBl + gb0);
            cp16(so + 3 * TG_MAT_B + sm_off1, gBl + gb1);
            asm volatile("cp.async.commit_group;" ::: "memory");
            asm volatile("cp.async.wait_group 1;" ::: "memory");
        } else {
            asm volatile("cp.async.wait_group 0;" ::: "memory");
        }
        __syncthreads();

        const uint32_t soA = sbase + (uint32_t)(s * TG_STAGE_B);
        const uint32_t soB = soA + 2 * TG_MAT_B;
        #pragma unroll
        for (int ks = 0; ks < 2; ks++) {
            uint32_t bh[4][2], bl[4][2];
            #pragma unroll
            for (int nt = 0; nt < 4; nt++) {
                int nr = wn * 32 + nt * 8 + b_row_in;
                uint32_t bd = soB + (uint32_t)((nr * 40 + ks * 16 + b_koff) * 2);
                ldsm_x2(bh[nt], bd);
                ldsm_x2(bl[nt], bd + TG_MAT_B);
            }
            #pragma unroll
            for (int mt = 0; mt < 4; mt++) {
                uint32_t ah[4], al[4];
                int mr = wm * 64 + mt * 16 + a_row_in;
                uint32_t ad = soA + (uint32_t)((mr * 40 + ks * 16 + a_koff) * 2);
                ldsm_x4(ah, ad);
                ldsm_x4(al, ad + TG_MAT_B);
                #pragma unroll
                for (int nt = 0; nt < 4; nt++) {
                    mma_bf16(acc[mt][nt], ah, bh[nt]);
                    mma_bf16(acc[mt][nt], al, bh[nt]);
                    mma_bf16(acc[mt][nt], ah, bl[nt]);
                }
            }
        }
        __syncthreads();
    }

    // ---- epilogue ----
    const int g = lane >> 2, tq = lane & 3;
    #pragma unroll
    for (int mt = 0; mt < 4; mt++) {
        #pragma unroll
        for (int half = 0; half < 2; half++) {
            int m = m0 + wm * 64 + mt * 16 + g + half * 8;
            bool valid = (m < Mreal);
            int win = 0, tok = 0, yy = 0, xx = 0, bb = 0;
            if (MODE <= 1) {
                win = m / NTOK; tok = m - win * NTOK;
                if (MODE == 1) {
                    bb = win / NWIN; int rem = win - bb * NWIN;
                    yy = (rem / 5) * WS + tok / WS;
                    xx = (rem % 5) * WS + tok % WS;
                    valid = valid && (yy < 64) && (xx < 64);
                }
            }
            if (!valid) continue;
            #pragma unroll
            for (int nt = 0; nt < 4; nt++) {
                int n = n0 + wn * 32 + nt * 8 + 2 * tq;
                float v0 = acc[mt][nt][half * 2]     + bias[n];
                float v1 = acc[mt][nt][half * 2 + 1] + bias[n + 1];
                if (MODE == 0) {
                    int which = n / 768;
                    int dd = n - which * 768;
                    int head = dd >> 6, hd = dd & 63;
                    size_t o = ((size_t)(win * NHEAD + head) * NTOK + tok) * HDIM + hd;
                    if (which == 0)      { g_q[o] = v0 * 0.125f; g_q[o + 1] = v1 * 0.125f; }
                    else if (which == 1) { g_k[o] = v0; g_k[o + 1] = v1; }
                    else                 { g_v[o] = v0; g_v[o + 1] = v1; }
                } else if (MODE == 1) {
                    size_t o = ((size_t)(bb * 64 + yy) * 64 + xx) * DIM + n;
                    g_x2[o]     = aux[o] + v0;
                    g_x2[o + 1] = aux[o + 1] + v1;
                } else if (MODE == 2) {
                    float gl0 = 0.5f * v0 * (1.f + erff(v0 * 0.70710678118f));
                    float gl1 = 0.5f * v1 * (1.f + erff(v1 * 0.70710678118f));
                    __nv_bfloat16 h0, l0, h1, l1;
                    bf16split(gl0, h0, l0);
                    bf16split(gl1, h1, l1);
                    size_t o = (size_t)m * 3072 + n;
                    g_h1_h[o] = h0; g_h1_h[o + 1] = h1;
                    g_h1_l[o] = l0; g_h1_l[o + 1] = l1;
                } else {
                    size_t o = (size_t)m * DIM + n;
                    outp[o]     = v0 + g_x2[o];
                    outp[o + 1] = v1 + g_x2[o + 1];
                }
            }
        }
    }
}

// ---------------- attention: one CTA (8 warps) per (window, head) ----------------
#define ATT_W 8
#define KV_STRIDE 68
#define SM_KS   0
#define SM_VS   (NTOK * KV_STRIDE)
#define SM_PROW (2 * NTOK * KV_STRIDE)
#define SM_QROW (SM_PROW + ATT_W * 200)
#define SM_SH   (SM_QROW + ATT_W * KV_STRIDE)
#define SM_SW   (SM_SH + NTOK)
#define SM_RSH  (SM_SW + NTOK)
#define SM_RSW  (SM_RSH + 32)
#define SM_FLOATS (SM_RSW + 32)
#define SM_BYTES_F (SM_FLOATS * 4)
#define SM_ATT_TOTAL (SM_BYTES_F + 4 * NTOK + 16)

__global__ __launch_bounds__(256) void attn_kernel(const float* __restrict__ rel_h,
                                                   const float* __restrict__ rel_w,
                                                   const int* __restrict__ q_idx,
                                                   const int* __restrict__ k_idx)
{
    extern __shared__ float sm[];
    float* ks   = sm + SM_KS;
    float* vs   = sm + SM_VS;
    float* prow = sm + SM_PROW;
    float* qrow = sm + SM_QROW;
    float* Sh   = sm + SM_SH;
    float* Sw   = sm + SM_SW;
    float* rsh  = sm + SM_RSH;
    float* rsw  = sm + SM_RSW;
    unsigned char* qr8 = (unsigned char*)(sm + SM_FLOATS);
    unsigned char* qc8 = qr8 + NTOK;
    unsigned char* kr8 = qc8 + NTOK;
    unsigned char* kc8 = kr8 + NTOK;

    int bh = blockIdx.x;
    int win = bh / NHEAD, head = bh - win * NHEAD;
    int tid = threadIdx.x;

    const float* kg = g_k + (size_t)bh * NTOK * HDIM;
    const float* vg = g_v + (size_t)bh * NTOK * HDIM;
    for (int i = tid; i < NTOK * HDIM; i += 256) {
        int j = i >> 6, d = i & 63;
        ks[j * KV_STRIDE + d] = kg[i];
        vs[j * KV_STRIDE + d] = vg[i];
    }
    if (tid < 27) {
        const float* rp = rel_h + tid * HDIM;
        float s = 0;
        #pragma unroll 8
        for (int c = 0; c < HDIM; c++) s += rp[c];
        rsh[tid] = s;
    } else if (tid >= 32 && tid < 59) {
        const float* rp = rel_w + (tid - 32) * HDIM;
        float s = 0;
        #pragma unroll 8
        for (int c = 0; c < HDIM; c++) s += rp[c];
        rsw[tid - 32] = s;
    }
    for (int tt = tid; tt < NTOK; tt += 256) {
        int qi = q_idx[(size_t)bh * NTOK + tt];
        int ki = k_idx[(size_t)bh * NTOK + tt];
        qr8[tt] = (unsigned char)(qi / WS);
        qc8[tt] = (unsigned char)(qi % WS);
        kr8[tt] = (unsigned char)(ki / WS);
        kc8[tt] = (unsigned char)(ki % WS);
    }
    __syncthreads();
    for (int tt = tid; tt < NTOK; tt += 256) {
        int i = tt / WS, j = tt - i * WS;
        Sh[tt] = rsh[i - j + WS - 1];
        Sw[tt] = rsw[i - j + WS - 1];
    }
    __syncthreads();

    int w = tid >> 5, lane = tid & 31;
    float* qw = qrow + w * KV_STRIDE;
    float* pw = prow + w * 200;
    const float* qg = g_q + (size_t)bh * NTOK * HDIM;

    for (int row = w; row < NTOK; row += ATT_W) {
        qw[lane]      = qg[row * HDIM + lane];
        qw[lane + 32] = qg[row * HDIM + 32 + lane];
        __syncwarp();
        int qrr = qr8[row] * WS, qcc = qc8[row] * WS;
        float s[7];
        #pragma unroll
        for (int jj = 0; jj < 7; jj++) {
            int j = lane + jj * 32;
            if (j < NTOK) {
                const float4* kk = (const float4*)(ks + j * KV_STRIDE);
                float acc = 0;
                #pragma unroll
                for (int d4 = 0; d4 < 16; d4++) {
                    float4 kv = kk[d4];
                    float4 qv = *(const float4*)(qw + d4 * 4);
                    acc += kv.x * qv.x + kv.y * qv.y + kv.z * qv.z + kv.w * qv.w;
                }
                s[jj] = acc + Sh[qrr + kr8[j]] + Sw[qcc + kc8[j]];
            } else {
                s[jj] = -1e30f;
            }
        }
        float mx = s[0];
        #pragma unroll
        for (int jj = 1; jj < 7; jj++) mx = fmaxf(mx, s[jj]);
        #pragma unroll
        for (int off = 16; off; off >>= 1) mx = fmaxf(mx, __shfl_xor_sync(0xffffffffu, mx, off));
        float sum = 0;
        #pragma unroll
        for (int jj = 0; jj < 7; jj++) {
            int j = lane + jj * 32;
            float e = (j < NTOK) ? expf(s[jj] - mx) : 0.f;
            s[jj] = e;
            sum += e;
        }
        #pragma unroll
        for (int off = 16; off; off >>= 1) sum += __shfl_xor_sync(0xffffffffu, sum, off);
        float inv = 1.f / sum;
        #pragma unroll
        for (int jj = 0; jj < 7; jj++) {
            int j = lane + jj * 32;
            if (j < 200) pw[j] = s[jj];
        }
        __syncwarp();
        int d = 2 * lane;
        float o0 = 0, o1 = 0;
        #pragma unroll 7
        for (int j = 0; j < NTOK; j += 4) {
            float4 p4 = *(const float4*)(pw + j);
            const float* vb = vs + j * KV_STRIDE + d;
            float2 va  = *(const float2*)(vb);
            float2 vb1 = *(const float2*)(vb + KV_STRIDE);
            float2 vc  = *(const float2*)(vb + 2 * KV_STRIDE);
            float2 vd_ = *(const float2*)(vb + 3 * KV_STRIDE);
            o0 += p4.x * va.x + p4.y * vb1.x + p4.z * vc.x + p4.w * vd_.x;
            o1 += p4.x * va.y + p4.y * vb1.y + p4.z * vc.y + p4.w * vd_.y;
        }
        size_t og = ((size_t)(win * NTOK + row)) * DIM + head * HDIM;
        float r0 = o0 * inv, r1 = o1 * inv;
        __nv_bfloat16 h0, l0, h1, l1;
        bf16split(r0, h0, l0);
        bf16split(r1, h1, l1);
        g_ao_h[og + d] = h0; g_ao_l[og + d] = l0;
        g_ao_h[og + d + 1] = h1; g_ao_l[og + d + 1] = l1;
        __syncwarp();
    }
}

// ---------------- launch ----------------
extern "C" void kernel_launch(void* const* d_in, const int* in_sizes, int n_in,
                              void* d_out, int out_size)
{
    const float* x     = (const float*)d_in[0];
    const int*   qidx  = (const int*)d_in[1];
    const int*   kidx  = (const int*)d_in[2];
    const float* ln1w  = (const float*)d_in[3];
    const float* ln1b  = (const float*)d_in[4];
    const float* ln2w  = (const float*)d_in[5];
    const float* ln2b  = (const float*)d_in[6];
    const float* qkvw  = (const float*)d_in[7];
    const float* qkvb  = (const float*)d_in[8];
    const float* projw = (const float*)d_in[9];
    const float* projb = (const float*)d_in[10];
    const float* relh  = (const float*)d_in[11];
    const float* relw  = (const float*)d_in[12];
    const float* w1    = (const float*)d_in[13];
    const float* b1    = (const float*)d_in[14];
    const float* w2    = (const float*)d_in[15];
    const float* b2    = (const float*)d_in[16];
    float* out = (float*)d_out;

    cudaFuncSetAttribute(attn_kernel, cudaFuncAttributeMaxDynamicSharedMemorySize, SM_ATT_TOTAL);
    cudaFuncSetAttribute(tgemm_kernel<0>, cudaFuncAttributeMaxDynamicSharedMemorySize, SMEM_TG);
    cudaFuncSetAttribute(tgemm_kernel<1>, cudaFuncAttributeMaxDynamicSharedMemorySize, SMEM_TG);
    cudaFuncSetAttribute(tgemm_kernel<2>, cudaFuncAttributeMaxDynamicSharedMemorySize, SMEM_TG);
    cudaFuncSetAttribute(tgemm_kernel<3>, cudaFuncAttributeMaxDynamicSharedMemorySize, SMEM_TG);

    __nv_bfloat16 *wqkv_h, *wqkv_l, *wproj_h, *wproj_l, *w1_h, *w1_l, *w2_h, *w2_l;
    cudaGetSymbolAddress((void**)&wqkv_h, g_wqkv_h);
    cudaGetSymbolAddress((void**)&wqkv_l, g_wqkv_l);
    cudaGetSymbolAddress((void**)&wproj_h, g_wproj_h);
    cudaGetSymbolAddress((void**)&wproj_l, g_wproj_l);
    cudaGetSymbolAddress((void**)&w1_h, g_w1_h);
    cudaGetSymbolAddress((void**)&w1_l, g_w1_l);
    cudaGetSymbolAddress((void**)&w2_h, g_w2_h);
    cudaGetSymbolAddress((void**)&w2_l, g_w2_l);

    wsplit_kernel<<<dim3(2304 / 32, 768 / 32), 256>>>(qkvw, wqkv_h, wqkv_l, 768, 2304);
    wsplit_kernel<<<dim3(768 / 32, 768 / 32), 256>>>(projw, wproj_h, wproj_l, 768, 768);
    wsplit_kernel<<<dim3(3072 / 32, 768 / 32), 256>>>(w1, w1_h, w1_l, 768, 3072);
    wsplit_kernel<<<dim3(768 / 32, 3072 / 32), 256>>>(w2, w2_h, w2_l, 3072, 768);

    ln1_kernel<<<TOKW, 256>>>(x, ln1w, ln1b);
    tgemm_kernel<0><<<dim3(2304 / 128, TOKW_PAD / 128), 256, SMEM_TG>>>(qkvb, nullptr, nullptr);
    attn_kernel<<<BH, 256, SM_ATT_TOTAL>>>(relh, relw, qidx, kidx);
    tgemm_kernel<1><<<dim3(768 / 128, TOKW_PAD / 128), 256, SMEM_TG>>>(projb, x, nullptr);
    ln2_kernel<<<TOKX, 256>>>(ln2w, ln2b);
    tgemm_kernel<2><<<dim3(3072 / 128, TOKX / 128), 256, SMEM_TG>>>(b1, nullptr, nullptr);
    tgemm_kernel<3><<<dim3(768 / 128, TOKX / 128), 256, SMEM_TG>>>(b2, nullptr, out);
}

// round 8
// speedup vs baseline: 1.2081x; 1.2081x over previous
/*
 * R8: fp16-split GEMMs. qkv = fp16x3 (fp32-exact); proj/mlp = A-single fp16 +
 * B dual fp16, 2 MMAs/step (-24% MMA work, -25% smem traffic on those modes).
 * Launch order places tgemm<0> at index 3 so ncu profiles the GEMM.
 */
#include <cuda_runtime.h>
#include <cuda_fp16.h>
#include <math.h>
#include <stdint.h>

#define DIM   768
#define NHEAD 12
#define HDIM  64
#define WS    14
#define NTOK  196
#define NWIN  25
#define BATCH 8
#define NWB   200
#define TOKW  39200
#define TOKW_PAD 39296
#define TOKX  32768
#define BH    2400

// ---------------- device scratch ----------------
__device__ __half g_a_h[(size_t)TOKW_PAD * DIM];
__device__ __half g_a_l[(size_t)TOKW_PAD * DIM];
__device__ __half g_ao[(size_t)TOKW_PAD * DIM];
__device__ __half g_b[(size_t)TOKX * DIM];
__device__ __half g_h1[(size_t)TOKX * 3072];
__device__ __half g_wqkv_h[(size_t)2304 * 768];
__device__ __half g_wqkv_l[(size_t)2304 * 768];
__device__ __half g_wproj_h[(size_t)768 * 768];
__device__ __half g_wproj_l[(size_t)768 * 768];
__device__ __half g_w1_h[(size_t)3072 * 768];
__device__ __half g_w1_l[(size_t)3072 * 768];
__device__ __half g_w2_h[(size_t)768 * 3072];
__device__ __half g_w2_l[(size_t)768 * 3072];
__device__ float g_q[(size_t)BH * NTOK * HDIM];
__device__ float g_k[(size_t)BH * NTOK * HDIM];
__device__ float g_v[(size_t)BH * NTOK * HDIM];
__device__ float g_x2[(size_t)TOKX * DIM];

// ---------------- PTX helpers ----------------
__device__ __forceinline__ uint32_t smem_u32(const void* p) {
    uint32_t a;
    asm("{ .reg .u64 t; cvta.to.shared.u64 t, %1; cvt.u32.u64 %0, t; }" : "=r"(a) : "l"(p));
    return a;
}
__device__ __forceinline__ void cp16(uint32_t dst, const void* src) {
    asm volatile("cp.async.cg.shared.global [%0], [%1], 16;" :: "r"(dst), "l"(src));
}
__device__ __forceinline__ void ldsm_x4(uint32_t* r, uint32_t addr) {
    asm volatile("ldmatrix.sync.aligned.m8n8.x4.shared.b16 {%0,%1,%2,%3}, [%4];"
        : "=r"(r[0]), "=r"(r[1]), "=r"(r[2]), "=r"(r[3]) : "r"(addr));
}
__device__ __forceinline__ void ldsm_x2(uint32_t* r, uint32_t addr) {
    asm volatile("ldmatrix.sync.aligned.m8n8.x2.shared.b16 {%0,%1}, [%2];"
        : "=r"(r[0]), "=r"(r[1]) : "r"(addr));
}
__device__ __forceinline__ void mma_f16(float* c, const uint32_t* a, const uint32_t* b) {
    asm volatile(
        "mma.sync.aligned.m16n8k16.row.col.f32.f16.f16.f32 "
        "{%0,%1,%2,%3}, {%4,%5,%6,%7}, {%8,%9}, {%0,%1,%2,%3};"
        : "+f"(c[0]), "+f"(c[1]), "+f"(c[2]), "+f"(c[3])
        : "r"(a[0]), "r"(a[1]), "r"(a[2]), "r"(a[3]), "r"(b[0]), "r"(b[1]));
}
__device__ __forceinline__ void f16split(float v, __half& h, __half& l) {
    h = __float2half_rn(v);
    l = __float2half_rn(v - __half2float(h));
}

// ---------------- weight transpose + fp16 split: W[K,N] -> Wt_h/l[N,K] ----------------
__global__ __launch_bounds__(256) void wsplit_kernel(const float* __restrict__ W,
                                                     __half* __restrict__ Wh,
                                                     __half* __restrict__ Wl,
                                                     int K, int N)
{
    __shared__ float tile[32][33];
    int k0 = blockIdx.y * 32, n0 = blockIdx.x * 32;
    int tx = threadIdx.x & 31, ty = threadIdx.x >> 5;
    #pragma unroll
    for (int j = 0; j < 32; j += 8)
        tile[ty + j][tx] = W[(size_t)(k0 + ty + j) * N + n0 + tx];
    __syncthreads();
    #pragma unroll
    for (int j = 0; j < 32; j += 8) {
        float v = tile[tx][ty + j];
        __half h, l;
        f16split(v, h, l);
        size_t o = (size_t)(n0 + ty + j) * K + k0 + tx;
        Wh[o] = h; Wl[o] = l;
    }
}

// ---------------- LayerNorm 1 (window partition + pad + fp16 split) ----------------
__global__ __launch_bounds__(256) void ln1_kernel(const float* __restrict__ x,
                                                  const float* __restrict__ g,
                                                  const float* __restrict__ b)
{
    int widx = blockIdx.x;
    int win = widx / NTOK, tok = widx - win * NTOK;
    int bb = win / NWIN, rem = win - bb * NWIN;
    int y = (rem / 5) * WS + tok / WS;
    int xx = (rem % 5) * WS + tok % WS;
    size_t ob = (size_t)widx * DIM;
    int tid = threadIdx.x;
    if (y >= 64 || xx >= 64) {
        for (int i = tid; i < DIM; i += 256) {
            g_a_h[ob + i] = __float2half(0.f);
            g_a_l[ob + i] = __float2half(0.f);
        }
        return;
    }
    const float* row = x + ((size_t)(bb * 64 + y) * 64 + xx) * DIM;
    float v0 = row[tid], v1 = row[tid + 256], v2 = row[tid + 512];
    float s = v0 + v1 + v2, sq = v0 * v0 + v1 * v1 + v2 * v2;
    #pragma unroll
    for (int off = 16; off; off >>= 1) {
        s  += __shfl_xor_sync(0xffffffffu, s, off);
        sq += __shfl_xor_sync(0xffffffffu, sq, off);
    }
    __shared__ float rs[8], rq[8], smu, srs;
    int wid = tid >> 5, lane = tid & 31;
    if (!lane) { rs[wid] = s; rq[wid] = sq; }
    __syncthreads();
    if (tid == 0) {
        float S = 0, Q = 0;
        #pragma unroll
        for (int i = 0; i < 8; i++) { S += rs[i]; Q += rq[i]; }
        float mu = S * (1.f / 768.f);
        float var = Q * (1.f / 768.f) - mu * mu;
        smu = mu; srs = rsqrtf(var + 1e-5f);
    }
    __syncthreads();
    float mu = smu, r = srs;
    #pragma unroll
    for (int p = 0; p < 3; p++) {
        int i = tid + p * 256;
        float vv = ((p == 0 ? v0 : p == 1 ? v1 : v2) - mu) * r * g[i] + b[i];
        __half h, l;
        f16split(vv, h, l);
        g_a_h[ob + i] = h; g_a_l[ob + i] = l;
    }
}

// ---------------- LayerNorm 2 (single fp16 out) ----------------
__global__ __launch_bounds__(256) void ln2_kernel(const float* __restrict__ g,
                                                  const float* __restrict__ b)
{
    int tid = threadIdx.x;
    const float* row = g_x2 + (size_t)blockIdx.x * DIM;
    size_t ob = (size_t)blockIdx.x * DIM;
    float v0 = row[tid], v1 = row[tid + 256], v2 = row[tid + 512];
    float s = v0 + v1 + v2, sq = v0 * v0 + v1 * v1 + v2 * v2;
    #pragma unroll
    for (int off = 16; off; off >>= 1) {
        s  += __shfl_xor_sync(0xffffffffu, s, off);
        sq += __shfl_xor_sync(0xffffffffu, sq, off);
    }
    __shared__ float rs[8], rq[8], smu, srs;
    int wid = tid >> 5, lane = tid & 31;
    if (!lane) { rs[wid] = s; rq[wid] = sq; }
    __syncthreads();
    if (tid == 0) {
        float S = 0, Q = 0;
        #pragma unroll
        for (int i = 0; i < 8; i++) { S += rs[i]; Q += rq[i]; }
        float mu = S * (1.f / 768.f);
        float var = Q * (1.f / 768.f) - mu * mu;
        smu = mu; srs = rsqrtf(var + 1e-5f);
    }
    __syncthreads();
    float mu = smu, r = srs;
    #pragma unroll
    for (int p = 0; p < 3; p++) {
        int i = tid + p * 256;
        float vv = ((p == 0 ? v0 : p == 1 ? v1 : v2) - mu) * r * g[i] + b[i];
        g_b[ob + i] = __float2half_rn(vv);
    }
}

// ---------------- mma.sync GEMM: D[M,N] = A[M,K] x Wt[N,K]^T ----------------
// MODE 0: A dual fp16 (x3 MMAs, fp32-exact); MODEs 1-3: A single + B dual (x2 MMAs).
#define TG_MAT_B    10240

template <int MODE>
__global__ __launch_bounds__(256, 2) void tgemm_kernel(const float* __restrict__ bias,
                                                       const float* __restrict__ aux,
                                                       float* __restrict__ outp)
{
    constexpr int K      = (MODE == 3) ? 3072 : 768;
    constexpr int Mreal  = (MODE <= 1) ? TOKW : TOKX;
    constexpr int NCHUNK = K / 32;
    constexpr int NMATS  = (MODE == 0) ? 4 : 3;
    constexpr int STAGE  = NMATS * TG_MAT_B;
    const __half* gA  = (MODE == 0) ? g_a_h : (MODE == 1) ? g_ao : (MODE == 2) ? g_b : g_h1;
    const __half* gAl = g_a_l;  // mode 0 only
    const __half* gBh = (MODE == 0) ? g_wqkv_h : (MODE == 1) ? g_wproj_h : (MODE == 2) ? g_w1_h : g_w2_h;
    const __half* gBl = (MODE == 0) ? g_wqkv_l : (MODE == 1) ? g_wproj_l : (MODE == 2) ? g_w1_l : g_w2_l;

    extern __shared__ char smem_raw[];
    const uint32_t sbase = smem_u32(smem_raw);

    const int t = threadIdx.x;
    const int m0 = blockIdx.y * 128;
    const int n0 = blockIdx.x * 128;
    const int warp = t >> 5, lane = t & 31;
    const int wm = warp >> 2, wn = warp & 3;

    float acc[4][4][4];
    #pragma unroll
    for (int a = 0; a < 4; a++)
        #pragma unroll
        for (int b2 = 0; b2 < 4; b2++)
            #pragma unroll
            for (int c = 0; c < 4; c++) acc[a][b2][c] = 0.f;

    const int ldrow = t >> 2, ldseg = t & 3;
    const uint32_t sm_off0 = (uint32_t)(ldrow * 80 + ldseg * 16);
    const uint32_t sm_off1 = (uint32_t)((ldrow + 64) * 80 + ldseg * 16);

    {
        const uint32_t so = sbase;
        size_t ga0 = (size_t)(m0 + ldrow) * K + ldseg * 8;
        size_t ga1 = (size_t)(m0 + ldrow + 64) * K + ldseg * 8;
        size_t gb0 = (size_t)(n0 + ldrow) * K + ldseg * 8;
        size_t gb1 = (size_t)(n0 + ldrow + 64) * K + ldseg * 8;
        cp16(so + sm_off0, gA + ga0);
        cp16(so + sm_off1, gA + ga1);
        if (MODE == 0) {
            cp16(so + TG_MAT_B + sm_off0, gAl + ga0);
            cp16(so + TG_MAT_B + sm_off1, gAl + ga1);
        }
        const uint32_t bso = so + (NMATS - 2) * TG_MAT_B;
        cp16(bso + sm_off0, gBh + gb0);
        cp16(bso + sm_off1, gBh + gb1);
        cp16(bso + TG_MAT_B + sm_off0, gBl + gb0);
        cp16(bso + TG_MAT_B + sm_off1, gBl + gb1);
        asm volatile("cp.async.commit_group;" ::: "memory");
    }

    const int a_row_in = (lane & 7) + (lane & 8);
    const int a_koff   = (lane >> 4) * 8;
    const int b_row_in = lane & 7;
    const int b_koff   = ((lane >> 3) & 1) * 8;

    for (int i = 0; i < NCHUNK; i++) {
        const int s = i & 1;
        if (i + 1 < NCHUNK) {
            const int k0 = (i + 1) * 32;
            const uint32_t so = sbase + (uint32_t)((s ^ 1) * STAGE);
            size_t ga0 = (size_t)(m0 + ldrow) * K + k0 + ldseg * 8;
            size_t ga1 = (size_t)(m0 + ldrow + 64) * K + k0 + ldseg * 8;
            size_t gb0 = (size_t)(n0 + ldrow) * K + k0 + ldseg * 8;
            size_t gb1 = (size_t)(n0 + ldrow + 64) * K + k0 + ldseg * 8;
            cp16(so + sm_off0, gA + ga0);
            cp16(so + sm_off1, gA + ga1);
            if (MODE == 0) {
                cp16(so + TG_MAT_B + sm_off0, gAl + ga0);
                cp16(so + TG_MAT_B + sm_off1, gAl + ga1);
            }
            const uint32_t bso = so + (NMATS - 2) * TG_MAT_B;
            cp16(bso + sm_off0, gBh + gb0);
            cp16(bso + sm_off1, gBh + gb1);
            cp16(bso + TG_MAT_B + sm_off0, gBl + gb0);
            cp16(bso + TG_MAT_B + sm_off1, gBl + gb1);
            asm volatile("cp.async.commit_group;" ::: "memory");
            asm volatile("cp.async.wait_group 1;" ::: "memory");
        } else {
            asm volatile("cp.async.wait_group 0;" ::: "memory");
        }
        __syncthreads();

        const uint32_t soA = sbase + (uint32_t)(s * STAGE);
        const uint32_t soB = soA + (NMATS - 2) * TG_MAT_B;
        #pragma unroll
        for (int ks = 0; ks < 2; ks++) {
            uint32_t bh[4][2], bl[4][2];
            #pragma unroll
            for (int nt = 0; nt < 4; nt++) {
                int nr = wn * 32 + nt * 8 + b_row_in;
                uint32_t bd = soB + (uint32_t)((nr * 40 + ks * 16 + b_koff) * 2);
                ldsm_x2(bh[nt], bd);
                ldsm_x2(bl[nt], bd + TG_MAT_B);
            }
            #pragma unroll
            for (int mt = 0; mt < 4; mt++) {
                uint32_t ah[4];
                int mr = wm * 64 + mt * 16 + a_row_in;
                uint32_t ad = soA + (uint32_t)((mr * 40 + ks * 16 + a_koff) * 2);
                ldsm_x4(ah, ad);
                if (MODE == 0) {
                    uint32_t al[4];
                    ldsm_x4(al, ad + TG_MAT_B);
                    #pragma unroll
                    for (int nt = 0; nt < 4; nt++) {
                        mma_f16(acc[mt][nt], ah, bh[nt]);
                        mma_f16(acc[mt][nt], al, bh[nt]);
                        mma_f16(acc[mt][nt], ah, bl[nt]);
                    }
                } else {
                    #pragma unroll
                    for (int nt = 0; nt < 4; nt++) {
                        mma_f16(acc[mt][nt], ah, bh[nt]);
                        mma_f16(acc[mt][nt], ah, bl[nt]);
                    }
                }
            }
        }
        __syncthreads();
    }

    // ---- epilogue ----
    const int g = lane >> 2, tq = lane & 3;
    #pragma unroll
    for (int mt = 0; mt < 4; mt++) {
        #pragma unroll
        for (int half = 0; half < 2; half++) {
            int m = m0 + wm * 64 + mt * 16 + g + half * 8;
            bool valid = (m < Mreal);
            int win = 0, tok = 0, yy = 0, xx = 0, bb = 0;
            if (MODE <= 1) {
                win = m / NTOK; tok = m - win * NTOK;
                if (MODE == 1) {
                    bb = win / NWIN; int rem = win - bb * NWIN;
                    yy = (rem / 5) * WS + tok / WS;
                    xx = (rem % 5) * WS + tok % WS;
                    valid = valid && (yy < 64) && (xx < 64);
                }
            }
            if (!valid) continue;
            #pragma unroll
            for (int nt = 0; nt < 4; nt++) {
                int n = n0 + wn * 32 + nt * 8 + 2 * tq;
                float v0 = acc[mt][nt][half * 2]     + bias[n];
                float v1 = acc[mt][nt][half * 2 + 1] + bias[n + 1];
                if (MODE == 0) {
                    int which = n / 768;
                    int dd = n - which * 768;
                    int head = dd >> 6, hd = dd & 63;
                    size_t o = ((size_t)(win * NHEAD + head) * NTOK + tok) * HDIM + hd;
                    if (which == 0)      { g_q[o] = v0 * 0.125f; g_q[o + 1] = v1 * 0.125f; }
                    else if (which == 1) { g_k[o] = v0; g_k[o + 1] = v1; }
                    else                 { g_v[o] = v0; g_v[o + 1] = v1; }
                } else if (MODE == 1) {
                    size_t o = ((size_t)(bb * 64 + yy) * 64 + xx) * DIM + n;
                    g_x2[o]     = aux[o] + v0;
                    g_x2[o + 1] = aux[o + 1] + v1;
                } else if (MODE == 2) {
                    float gl0 = 0.5f * v0 * (1.f + erff(v0 * 0.70710678118f));
                    float gl1 = 0.5f * v1 * (1.f + erff(v1 * 0.70710678118f));
                    size_t o = (size_t)m * 3072 + n;
                    g_h1[o]     = __float2half_rn(gl0);
                    g_h1[o + 1] = __float2half_rn(gl1);
                } else {
                    size_t o = (size_t)m * DIM + n;
                    outp[o]     = v0 + g_x2[o];
                    outp[o + 1] = v1 + g_x2[o + 1];
                }
            }
        }
    }
}

// ---------------- attention: one CTA (8 warps) per (window, head) ----------------
#define ATT_W 8
#define KV_STRIDE 68
#define SM_KS   0
#define SM_VS   (NTOK * KV_STRIDE)
#define SM_PROW (2 * NTOK * KV_STRIDE)
#define SM_QROW (SM_PROW + ATT_W * 200)
#define SM_SH   (SM_QROW + ATT_W * KV_STRIDE)
#define SM_SW   (SM_SH + NTOK)
#define SM_RSH  (SM_SW + NTOK)
#define SM_RSW  (SM_RSH + 32)
#define SM_FLOATS (SM_RSW + 32)
#define SM_BYTES_F (SM_FLOATS * 4)
#define SM_ATT_TOTAL (SM_BYTES_F + 4 * NTOK + 16)

__global__ __launch_bounds__(256) void attn_kernel(const float* __restrict__ rel_h,
                                                   const float* __restrict__ rel_w,
                                                   const int* __restrict__ q_idx,
                                                   const int* __restrict__ k_idx)
{
    extern __shared__ float sm[];
    float* ks   = sm + SM_KS;
    float* vs   = sm + SM_VS;
    float* prow = sm + SM_PROW;
    float* qrow = sm + SM_QROW;
    float* Sh   = sm + SM_SH;
    float* Sw   = sm + SM_SW;
    float* rsh  = sm + SM_RSH;
    float* rsw  = sm + SM_RSW;
    unsigned char* qr8 = (unsigned char*)(sm + SM_FLOATS);
    unsigned char* qc8 = qr8 + NTOK;
    unsigned char* kr8 = qc8 + NTOK;
    unsigned char* kc8 = kr8 + NTOK;

    int bh = blockIdx.x;
    int win = bh / NHEAD, head = bh - win * NHEAD;
    int tid = threadIdx.x;

    const float* kg = g_k + (size_t)bh * NTOK * HDIM;
    const float* vg = g_v + (size_t)bh * NTOK * HDIM;
    for (int i = tid; i < NTOK * HDIM; i += 256) {
        int j = i >> 6, d = i & 63;
        ks[j * KV_STRIDE + d] = kg[i];
        vs[j * KV_STRIDE + d] = vg[i];
    }
    if (tid < 27) {
        const float* rp = rel_h + tid * HDIM;
        float s = 0;
        #pragma unroll 8
        for (int c = 0; c < HDIM; c++) s += rp[c];
        rsh[tid] = s;
    } else if (tid >= 32 && tid < 59) {
        const float* rp = rel_w + (tid - 32) * HDIM;
        float s = 0;
        #pragma unroll 8
        for (int c = 0; c < HDIM; c++) s += rp[c];
        rsw[tid - 32] = s;
    }
    for (int tt = tid; tt < NTOK; tt += 256) {
        int qi = q_idx[(size_t)bh * NTOK + tt];
        int ki = k_idx[(size_t)bh * NTOK + tt];
        qr8[tt] = (unsigned char)(qi / WS);
        qc8[tt] = (unsigned char)(qi % WS);
        kr8[tt] = (unsigned char)(ki / WS);
        kc8[tt] = (unsigned char)(ki % WS);
    }
    __syncthreads();
    for (int tt = tid; tt < NTOK; tt += 256) {
        int i = tt / WS, j = tt - i * WS;
        Sh[tt] = rsh[i - j + WS - 1];
        Sw[tt] = rsw[i - j + WS - 1];
    }
    __syncthreads();

    int w = tid >> 5, lane = tid & 31;
    float* qw = qrow + w * KV_STRIDE;
    float* pw = prow + w * 200;
    const float* qg = g_q + (size_t)bh * NTOK * HDIM;

    for (int row = w; row < NTOK; row += ATT_W) {
        qw[lane]      = qg[row * HDIM + lane];
        qw[lane + 32] = qg[row * HDIM + 32 + lane];
        __syncwarp();
        int qrr = qr8[row] * WS, qcc = qc8[row] * WS;
        float s[7];
        #pragma unroll
        for (int jj = 0; jj < 7; jj++) {
            int j = lane + jj * 32;
            if (j < NTOK) {
                const float4* kk = (const float4*)(ks + j * KV_STRIDE);
                float acc = 0;
                #pragma unroll
                for (int d4 = 0; d4 < 16; d4++) {
                    float4 kv = kk[d4];
                    float4 qv = *(const float4*)(qw + d4 * 4);
                    acc += kv.x * qv.x + kv.y * qv.y + kv.z * qv.z + kv.w * qv.w;
                }
                s[jj] = acc + Sh[qrr + kr8[j]] + Sw[qcc + kc8[j]];
            } else {
                s[jj] = -1e30f;
            }
        }
        float mx = s[0];
        #pragma unroll
        for (int jj = 1; jj < 7; jj++) mx = fmaxf(mx, s[jj]);
        #pragma unroll
        for (int off = 16; off; off >>= 1) mx = fmaxf(mx, __shfl_xor_sync(0xffffffffu, mx, off));
        float sum = 0;
        #pragma unroll
        for (int jj = 0; jj < 7; jj++) {
            int j = lane + jj * 32;
            float e = (j < NTOK) ? expf(s[jj] - mx) : 0.f;
            s[jj] = e;
            sum += e;
        }
        #pragma unroll
        for (int off = 16; off; off >>= 1) sum += __shfl_xor_sync(0xffffffffu, sum, off);
        float inv = 1.f / sum;
        #pragma unroll
        for (int jj = 0; jj < 7; jj++) {
            int j = lane + jj * 32;
            if (j < 200) pw[j] = s[jj];
        }
        __syncwarp();
        int d = 2 * lane;
        float o0 = 0, o1 = 0;
        #pragma unroll 7
        for (int j = 0; j < NTOK; j += 4) {
            float4 p4 = *(const float4*)(pw + j);
            const float* vb = vs + j * KV_STRIDE + d;
            float2 va  = *(const float2*)(vb);
            float2 vb1 = *(const float2*)(vb + KV_STRIDE);
            float2 vc  = *(const float2*)(vb + 2 * KV_STRIDE);
            float2 vd_ = *(const float2*)(vb + 3 * KV_STRIDE);
            o0 += p4.x * va.x + p4.y * vb1.x + p4.z * vc.x + p4.w * vd_.x;
            o1 += p4.x * va.y + p4.y * vb1.y + p4.z * vc.y + p4.w * vd_.y;
        }
        size_t og = ((size_t)(win * NTOK + row)) * DIM + head * HDIM;
        g_ao[og + d]     = __float2half_rn(o0 * inv);
        g_ao[og + d + 1] = __float2half_rn(o1 * inv);
        __syncwarp();
    }
}

// ---------------- launch ----------------
extern "C" void kernel_launch(void* const* d_in, const int* in_sizes, int n_in,
                              void* d_out, int out_size)
{
    const float* x     = (const float*)d_in[0];
    const int*   qidx  = (const int*)d_in[1];
    const int*   kidx  = (const int*)d_in[2];
    const float* ln1w  = (const float*)d_in[3];
    const float* ln1b  = (const float*)d_in[4];
    const float* ln2w  = (const float*)d_in[5];
    const float* ln2b  = (const float*)d_in[6];
    const float* qkvw  = (const float*)d_in[7];
    const float* qkvb  = (const float*)d_in[8];
    const float* projw = (const float*)d_in[9];
    const float* projb = (const float*)d_in[10];
    const float* relh  = (const float*)d_in[11];
    const float* relw  = (const float*)d_in[12];
    const float* w1    = (const float*)d_in[13];
    const float* b1    = (const float*)d_in[14];
    const float* w2    = (const float*)d_in[15];
    const float* b2    = (const float*)d_in[16];
    float* out = (float*)d_out;

    cudaFuncSetAttribute(attn_kernel, cudaFuncAttributeMaxDynamicSharedMemorySize, SM_ATT_TOTAL);
    cudaFuncSetAttribute(tgemm_kernel<0>, cudaFuncAttributeMaxDynamicSharedMemorySize, 2 * 4 * TG_MAT_B);
    cudaFuncSetAttribute(tgemm_kernel<1>, cudaFuncAttributeMaxDynamicSharedMemorySize, 2 * 3 * TG_MAT_B);
    cudaFuncSetAttribute(tgemm_kernel<2>, cudaFuncAttributeMaxDynamicSharedMemorySize, 2 * 3 * TG_MAT_B);
    cudaFuncSetAttribute(tgemm_kernel<3>, cudaFuncAttributeMaxDynamicSharedMemorySize, 2 * 3 * TG_MAT_B);

    __half *wqkv_h, *wqkv_l, *wproj_h, *wproj_l, *w1_h, *w1_l, *w2_h, *w2_l;
    cudaGetSymbolAddress((void**)&wqkv_h, g_wqkv_h);
    cudaGetSymbolAddress((void**)&wqkv_l, g_wqkv_l);
    cudaGetSymbolAddress((void**)&wproj_h, g_wproj_h);
    cudaGetSymbolAddress((void**)&wproj_l, g_wproj_l);
    cudaGetSymbolAddress((void**)&w1_h, g_w1_h);
    cudaGetSymbolAddress((void**)&w1_l, g_w1_l);
    cudaGetSymbolAddress((void**)&w2_h, g_w2_h);
    cudaGetSymbolAddress((void**)&w2_l, g_w2_l);

    // order chosen so launch index 3 (the one ncu profiles) is tgemm<0>
    wsplit_kernel<<<dim3(2304 / 32, 768 / 32), 256>>>(qkvw, wqkv_h, wqkv_l, 768, 2304);   // 0
    wsplit_kernel<<<dim3(3072 / 32, 768 / 32), 256>>>(w1, w1_h, w1_l, 768, 3072);         // 1
    ln1_kernel<<<TOKW, 256>>>(x, ln1w, ln1b);                                              // 2
    tgemm_kernel<0><<<dim3(2304 / 128, TOKW_PAD / 128), 256, 2 * 4 * TG_MAT_B>>>(qkvb, nullptr, nullptr); // 3
    attn_kernel<<<BH, 256, SM_ATT_TOTAL>>>(relh, relw, qidx, kidx);                        // 4
    wsplit_kernel<<<dim3(768 / 32, 768 / 32), 256>>>(projw, wproj_h, wproj_l, 768, 768);   // 5
    tgemm_kernel<1><<<dim3(768 / 128, TOKW_PAD / 128), 256, 2 * 3 * TG_MAT_B>>>(projb, x, nullptr); // 6
    ln2_kernel<<<TOKX, 256>>>(ln2w, ln2b);                                                 // 7
    wsplit_kernel<<<dim3(768 / 32, 3072 / 32), 256>>>(w2, w2_h, w2_l, 3072, 768);          // 8
    tgemm_kernel<2><<<dim3(3072 / 128, TOKX / 128), 256, 2 * 3 * TG_MAT_B>>>(b1, nullptr, nullptr); // 9
    tgemm_kernel<3><<<dim3(768 / 128, TOKX / 128), 256, 2 * 3 * TG_MAT_B>>>(b2, nullptr, out);      // 10
}

// round 9
// speedup vs baseline: 1.2714x; 1.0524x over previous
/*
 * R9: all GEMMs 2 MMAs/step (A single fp16, B hi/lo fp16) + 3-stage cp.async
 * pipeline. attn_kernel placed at launch index 3 for ncu profiling.
 */
#include <cuda_runtime.h>
#include <cuda_fp16.h>
#include <math.h>
#include <stdint.h>

#define DIM   768
#define NHEAD 12
#define HDIM  64
#define WS    14
#define NTOK  196
#define NWIN  25
#define BATCH 8
#define NWB   200
#define TOKW  39200
#define TOKW_PAD 39296
#define TOKX  32768
#define BH    2400

// ---------------- device scratch ----------------
__device__ __half g_a[(size_t)TOKW_PAD * DIM];
__device__ __half g_ao[(size_t)TOKW_PAD * DIM];
__device__ __half g_b[(size_t)TOKX * DIM];
__device__ __half g_h1[(size_t)TOKX * 3072];
__device__ __half g_wqkv_h[(size_t)2304 * 768];
__device__ __half g_wqkv_l[(size_t)2304 * 768];
__device__ __half g_wproj_h[(size_t)768 * 768];
__device__ __half g_wproj_l[(size_t)768 * 768];
__device__ __half g_w1_h[(size_t)3072 * 768];
__device__ __half g_w1_l[(size_t)3072 * 768];
__device__ __half g_w2_h[(size_t)768 * 3072];
__device__ __half g_w2_l[(size_t)768 * 3072];
__device__ float g_q[(size_t)BH * NTOK * HDIM];
__device__ float g_k[(size_t)BH * NTOK * HDIM];
__device__ float g_v[(size_t)BH * NTOK * HDIM];
__device__ float g_x2[(size_t)TOKX * DIM];

// ---------------- PTX helpers ----------------
__device__ __forceinline__ uint32_t smem_u32(const void* p) {
    uint32_t a;
    asm("{ .reg .u64 t; cvta.to.shared.u64 t, %1; cvt.u32.u64 %0, t; }" : "=r"(a) : "l"(p));
    return a;
}
__device__ __forceinline__ void cp16(uint32_t dst, const void* src) {
    asm volatile("cp.async.cg.shared.global [%0], [%1], 16;" :: "r"(dst), "l"(src));
}
__device__ __forceinline__ void ldsm_x4(uint32_t* r, uint32_t addr) {
    asm volatile("ldmatrix.sync.aligned.m8n8.x4.shared.b16 {%0,%1,%2,%3}, [%4];"
        : "=r"(r[0]), "=r"(r[1]), "=r"(r[2]), "=r"(r[3]) : "r"(addr));
}
__device__ __forceinline__ void ldsm_x2(uint32_t* r, uint32_t addr) {
    asm volatile("ldmatrix.sync.aligned.m8n8.x2.shared.b16 {%0,%1}, [%2];"
        : "=r"(r[0]), "=r"(r[1]) : "r"(addr));
}
__device__ __forceinline__ void mma_f16(float* c, const uint32_t* a, const uint32_t* b) {
    asm volatile(
        "mma.sync.aligned.m16n8k16.row.col.f32.f16.f16.f32 "
        "{%0,%1,%2,%3}, {%4,%5,%6,%7}, {%8,%9}, {%0,%1,%2,%3};"
        : "+f"(c[0]), "+f"(c[1]), "+f"(c[2]), "+f"(c[3])
        : "r"(a[0]), "r"(a[1]), "r"(a[2]), "r"(a[3]), "r"(b[0]), "r"(b[1]));
}
__device__ __forceinline__ void f16split(float v, __half& h, __half& l) {
    h = __float2half_rn(v);
    l = __float2half_rn(v - __half2float(h));
}

// ---------------- weight transpose + fp16 split: W[K,N] -> Wt_h/l[N,K] ----------------
__global__ __launch_bounds__(256) void wsplit_kernel(const float* __restrict__ W,
                                                     __half* __restrict__ Wh,
                                                     __half* __restrict__ Wl,
                                                     int K, int N)
{
    __shared__ float tile[32][33];
    int k0 = blockIdx.y * 32, n0 = blockIdx.x * 32;
    int tx = threadIdx.x & 31, ty = threadIdx.x >> 5;
    #pragma unroll
    for (int j = 0; j < 32; j += 8)
        tile[ty + j][tx] = W[(size_t)(k0 + ty + j) * N + n0 + tx];
    __syncthreads();
    #pragma unroll
    for (int j = 0; j < 32; j += 8) {
        float v = tile[tx][ty + j];
        __half h, l;
        f16split(v, h, l);
        size_t o = (size_t)(n0 + ty + j) * K + k0 + tx;
        Wh[o] = h; Wl[o] = l;
    }
}

// ---------------- LayerNorm 1 (window partition + pad, fp16 out) ----------------
__global__ __launch_bounds__(256) void ln1_kernel(const float* __restrict__ x,
                                                  const float* __restrict__ g,
                                                  const float* __restrict__ b)
{
    int widx = blockIdx.x;
    int win = widx / NTOK, tok = widx - win * NTOK;
    int bb = win / NWIN, rem = win - bb * NWIN;
    int y = (rem / 5) * WS + tok / WS;
    int xx = (rem % 5) * WS + tok % WS;
    size_t ob = (size_t)widx * DIM;
    int tid = threadIdx.x;
    if (y >= 64 || xx >= 64) {
        for (int i = tid; i < DIM; i += 256) g_a[ob + i] = __float2half(0.f);
        return;
    }
    const float* row = x + ((size_t)(bb * 64 + y) * 64 + xx) * DIM;
    float v0 = row[tid], v1 = row[tid + 256], v2 = row[tid + 512];
    float s = v0 + v1 + v2, sq = v0 * v0 + v1 * v1 + v2 * v2;
    #pragma unroll
    for (int off = 16; off; off >>= 1) {
        s  += __shfl_xor_sync(0xffffffffu, s, off);
        sq += __shfl_xor_sync(0xffffffffu, sq, off);
    }
    __shared__ float rs[8], rq[8], smu, srs;
    int wid = tid >> 5, lane = tid & 31;
    if (!lane) { rs[wid] = s; rq[wid] = sq; }
    __syncthreads();
    if (tid == 0) {
        float S = 0, Q = 0;
        #pragma unroll
        for (int i = 0; i < 8; i++) { S += rs[i]; Q += rq[i]; }
        float mu = S * (1.f / 768.f);
        float var = Q * (1.f / 768.f) - mu * mu;
        smu = mu; srs = rsqrtf(var + 1e-5f);
    }
    __syncthreads();
    float mu = smu, r = srs;
    #pragma unroll
    for (int p = 0; p < 3; p++) {
        int i = tid + p * 256;
        float vv = ((p == 0 ? v0 : p == 1 ? v1 : v2) - mu) * r * g[i] + b[i];
        g_a[ob + i] = __float2half_rn(vv);
    }
}

// ---------------- LayerNorm 2 (fp16 out) ----------------
__global__ __launch_bounds__(256) void ln2_kernel(const float* __restrict__ g,
                                                  const float* __restrict__ b)
{
    int tid = threadIdx.x;
    const float* row = g_x2 + (size_t)blockIdx.x * DIM;
    size_t ob = (size_t)blockIdx.x * DIM;
    float v0 = row[tid], v1 = row[tid + 256], v2 = row[tid + 512];
    float s = v0 + v1 + v2, sq = v0 * v0 + v1 * v1 + v2 * v2;
    #pragma unroll
    for (int off = 16; off; off >>= 1) {
        s  += __shfl_xor_sync(0xffffffffu, s, off);
        sq += __shfl_xor_sync(0xffffffffu, sq, off);
    }
    __shared__ float rs[8], rq[8], smu, srs;
    int wid = tid >> 5, lane = tid & 31;
    if (!lane) { rs[wid] = s; rq[wid] = sq; }
    __syncthreads();
    if (tid == 0) {
        float S = 0, Q = 0;
        #pragma unroll
        for (int i = 0; i < 8; i++) { S += rs[i]; Q += rq[i]; }
        float mu = S * (1.f / 768.f);
        float var = Q * (1.f / 768.f) - mu * mu;
        smu = mu; srs = rsqrtf(var + 1e-5f);
    }
    __syncthreads();
    float mu = smu, r = srs;
    #pragma unroll
    for (int p = 0; p < 3; p++) {
        int i = tid + p * 256;
        float vv = ((p == 0 ? v0 : p == 1 ? v1 : v2) - mu) * r * g[i] + b[i];
        g_b[ob + i] = __float2half_rn(vv);
    }
}

// ---------------- mma.sync GEMM: D[M,N] = A[M,K] x Wt[N,K]^T ----------------
// All modes: A single fp16, B hi/lo fp16, 2 MMAs/step. 3-stage cp.async pipe.
#define TG_MAT_B   10240
#define TG_STAGE   (3 * TG_MAT_B)
#define SMEM_TG    (3 * TG_STAGE)

template <int MODE>
__global__ __launch_bounds__(256, 2) void tgemm_kernel(const float* __restrict__ bias,
                                                       const float* __restrict__ aux,
                                                       float* __restrict__ outp)
{
    constexpr int K      = (MODE == 3) ? 3072 : 768;
    constexpr int Mreal  = (MODE <= 1) ? TOKW : TOKX;
    constexpr int NCHUNK = K / 32;
    const __half* gA  = (MODE == 0) ? g_a : (MODE == 1) ? g_ao : (MODE == 2) ? g_b : g_h1;
    const __half* gBh = (MODE == 0) ? g_wqkv_h : (MODE == 1) ? g_wproj_h : (MODE == 2) ? g_w1_h : g_w2_h;
    const __half* gBl = (MODE == 0) ? g_wqkv_l : (MODE == 1) ? g_wproj_l : (MODE == 2) ? g_w1_l : g_w2_l;

    extern __shared__ char smem_raw[];
    const uint32_t sbase = smem_u32(smem_raw);

    const int t = threadIdx.x;
    const int m0 = blockIdx.y * 128;
    const int n0 = blockIdx.x * 128;
    const int warp = t >> 5, lane = t & 31;
    const int wm = warp >> 2, wn = warp & 3;

    float acc[4][4][4];
    #pragma unroll
    for (int a = 0; a < 4; a++)
        #pragma unroll
        for (int b2 = 0; b2 < 4; b2++)
            #pragma unroll
            for (int c = 0; c < 4; c++) acc[a][b2][c] = 0.f;

    const int ldrow = t >> 2, ldseg = t & 3;
    const uint32_t sm_off0 = (uint32_t)(ldrow * 80 + ldseg * 16);
    const uint32_t sm_off1 = (uint32_t)((ldrow + 64) * 80 + ldseg * 16);

    auto issue = [&](int chunk, int stg) {
        const int k0 = chunk * 32;
        const uint32_t so = sbase + (uint32_t)(stg * TG_STAGE);
        size_t ga0 = (size_t)(m0 + ldrow) * K + k0 + ldseg * 8;
        size_t ga1 = (size_t)(m0 + ldrow + 64) * K + k0 + ldseg * 8;
        size_t gb0 = (size_t)(n0 + ldrow) * K + k0 + ldseg * 8;
        size_t gb1 = (size_t)(n0 + ldrow + 64) * K + k0 + ldseg * 8;
        cp16(so + sm_off0, gA + ga0);
        cp16(so + sm_off1, gA + ga1);
        cp16(so + TG_MAT_B + sm_off0, gBh + gb0);
        cp16(so + TG_MAT_B + sm_off1, gBh + gb1);
        cp16(so + 2 * TG_MAT_B + sm_off0, gBl + gb0);
        cp16(so + 2 * TG_MAT_B + sm_off1, gBl + gb1);
        asm volatile("cp.async.commit_group;" ::: "memory");
    };

    issue(0, 0);
    issue(1, 1);

    const int a_row_in = (lane & 7) + (lane & 8);
    const int a_koff   = (lane >> 4) * 8;
    const int b_row_in = lane & 7;
    const int b_koff   = ((lane >> 3) & 1) * 8;

    for (int i = 0; i < NCHUNK; i++) {
        if (i + 1 < NCHUNK)
            asm volatile("cp.async.wait_group 1;" ::: "memory");
        else
            asm volatile("cp.async.wait_group 0;" ::: "memory");
        __syncthreads();
        if (i + 2 < NCHUNK) issue(i + 2, (i + 2) % 3);

        const uint32_t soA = sbase + (uint32_t)((i % 3) * TG_STAGE);
        const uint32_t soB = soA + TG_MAT_B;
        #pragma unroll
        for (int ks = 0; ks < 2; ks++) {
            uint32_t bh[4][2], bl[4][2];
            #pragma unroll
            for (int nt = 0; nt < 4; nt++) {
                int nr = wn * 32 + nt * 8 + b_row_in;
                uint32_t bd = soB + (uint32_t)((nr * 40 + ks * 16 + b_koff) * 2);
                ldsm_x2(bh[nt], bd);
                ldsm_x2(bl[nt], bd + TG_MAT_B);
            }
            #pragma unroll
            for (int mt = 0; mt < 4; mt++) {
                uint32_t ah[4];
                int mr = wm * 64 + mt * 16 + a_row_in;
                uint32_t ad = soA + (uint32_t)((mr * 40 + ks * 16 + a_koff) * 2);
                ldsm_x4(ah, ad);
                #pragma unroll
                for (int nt = 0; nt < 4; nt++) {
                    mma_f16(acc[mt][nt], ah, bh[nt]);
                    mma_f16(acc[mt][nt], ah, bl[nt]);
                }
            }
        }
        __syncthreads();
    }

    // ---- epilogue ----
    const int g = lane >> 2, tq = lane & 3;
    #pragma unroll
    for (int mt = 0; mt < 4; mt++) {
        #pragma unroll
        for (int half = 0; half < 2; half++) {
            int m = m0 + wm * 64 + mt * 16 + g + half * 8;
            bool valid = (m < Mreal);
            int win = 0, tok = 0, yy = 0, xx = 0, bb = 0;
            if (MODE <= 1) {
                win = m / NTOK; tok = m - win * NTOK;
                if (MODE == 1) {
                    bb = win / NWIN; int rem = win - bb * NWIN;
                    yy = (rem / 5) * WS + tok / WS;
                    xx = (rem % 5) * WS + tok % WS;
                    valid = valid && (yy < 64) && (xx < 64);
                }
            }
            if (!valid) continue;
            #pragma unroll
            for (int nt = 0; nt < 4; nt++) {
                int n = n0 + wn * 32 + nt * 8 + 2 * tq;
                float v0 = acc[mt][nt][half * 2]     + bias[n];
                float v1 = acc[mt][nt][half * 2 + 1] + bias[n + 1];
                if (MODE == 0) {
                    int which = n / 768;
                    int dd = n - which * 768;
                    int head = dd >> 6, hd = dd & 63;
                    size_t o = ((size_t)(win * NHEAD + head) * NTOK + tok) * HDIM + hd;
                    if (which == 0)      { g_q[o] = v0 * 0.125f; g_q[o + 1] = v1 * 0.125f; }
                    else if (which == 1) { g_k[o] = v0; g_k[o + 1] = v1; }
                    else                 { g_v[o] = v0; g_v[o + 1] = v1; }
                } else if (MODE == 1) {
                    size_t o = ((size_t)(bb * 64 + yy) * 64 + xx) * DIM + n;
                    g_x2[o]     = aux[o] + v0;
                    g_x2[o + 1] = aux[o + 1] + v1;
                } else if (MODE == 2) {
                    float gl0 = 0.5f * v0 * (1.f + erff(v0 * 0.70710678118f));
                    float gl1 = 0.5f * v1 * (1.f + erff(v1 * 0.70710678118f));
                    size_t o = (size_t)m * 3072 + n;
                    g_h1[o]     = __float2half_rn(gl0);
                    g_h1[o + 1] = __float2half_rn(gl1);
                } else {
                    size_t o = (size_t)m * DIM + n;
                    outp[o]     = v0 + g_x2[o];
                    outp[o + 1] = v1 + g_x2[o + 1];
                }
            }
        }
    }
}

// ---------------- attention: one CTA (8 warps) per (window, head) ----------------
#define ATT_W 8
#define KV_STRIDE 68
#define SM_KS   0
#define SM_VS   (NTOK * KV_STRIDE)
#define SM_PROW (2 * NTOK * KV_STRIDE)
#define SM_QROW (SM_PROW + ATT_W * 200)
#define SM_SH   (SM_QROW + ATT_W * KV_STRIDE)
#define SM_SW   (SM_SH + NTOK)
#define SM_RSH  (SM_SW + NTOK)
#define SM_RSW  (SM_RSH + 32)
#define SM_FLOATS (SM_RSW + 32)
#define SM_BYTES_F (SM_FLOATS * 4)
#define SM_ATT_TOTAL (SM_BYTES_F + 4 * NTOK + 16)

__global__ __launch_bounds__(256) void attn_kernel(const float* __restrict__ rel_h,
                                                   const float* __restrict__ rel_w,
                                                   const int* __restrict__ q_idx,
                                                   const int* __restrict__ k_idx)
{
    extern __shared__ float sm[];
    float* ks   = sm + SM_KS;
    float* vs   = sm + SM_VS;
    float* prow = sm + SM_PROW;
    float* qrow = sm + SM_QROW;
    float* Sh   = sm + SM_SH;
    float* Sw   = sm + SM_SW;
    float* rsh  = sm + SM_RSH;
    float* rsw  = sm + SM_RSW;
    unsigned char* qr8 = (unsigned char*)(sm + SM_FLOATS);
    unsigned char* qc8 = qr8 + NTOK;
    unsigned char* kr8 = qc8 + NTOK;
    unsigned char* kc8 = kr8 + NTOK;

    int bh = blockIdx.x;
    int win = bh / NHEAD, head = bh - win * NHEAD;
    int tid = threadIdx.x;

    const float* kg = g_k + (size_t)bh * NTOK * HDIM;
    const float* vg = g_v + (size_t)bh * NTOK * HDIM;
    for (int i = tid; i < NTOK * HDIM; i += 256) {
        int j = i >> 6, d = i & 63;
        ks[j * KV_STRIDE + d] = kg[i];
        vs[j * KV_STRIDE + d] = vg[i];
    }
    if (tid < 27) {
        const float* rp = rel_h + tid * HDIM;
        float s = 0;
        #pragma unroll 8
        for (int c = 0; c < HDIM; c++) s += rp[c];
        rsh[tid] = s;
    } else if (tid >= 32 && tid < 59) {
        const float* rp = rel_w + (tid - 32) * HDIM;
        float s = 0;
        #pragma unroll 8
        for (int c = 0; c < HDIM; c++) s += rp[c];
        rsw[tid - 32] = s;
    }
    for (int tt = tid; tt < NTOK; tt += 256) {
        int qi = q_idx[(size_t)bh * NTOK + tt];
        int ki = k_idx[(size_t)bh * NTOK + tt];
        qr8[tt] = (unsigned char)(qi / WS);
        qc8[tt] = (unsigned char)(qi % WS);
        kr8[tt] = (unsigned char)(ki / WS);
        kc8[tt] = (unsigned char)(ki % WS);
    }
    __syncthreads();
    for (int tt = tid; tt < NTOK; tt += 256) {
        int i = tt / WS, j = tt - i * WS;
        Sh[tt] = rsh[i - j + WS - 1];
        Sw[tt] = rsw[i - j + WS - 1];
    }
    __syncthreads();

    int w = tid >> 5, lane = tid & 31;
    float* qw = qrow + w * KV_STRIDE;
    float* pw = prow + w * 200;
    const float* qg = g_q + (size_t)bh * NTOK * HDIM;

    for (int row = w; row < NTOK; row += ATT_W) {
        qw[lane]      = qg[row * HDIM + lane];
        qw[lane + 32] = qg[row * HDIM + 32 + lane];
        __syncwarp();
        int qrr = qr8[row] * WS, qcc = qc8[row] * WS;
        float s[7];
        #pragma unroll
        for (int jj = 0; jj < 7; jj++) {
            int j = lane + jj * 32;
            if (j < NTOK) {
                const float4* kk = (const float4*)(ks + j * KV_STRIDE);
                float acc = 0;
                #pragma unroll
                for (int d4 = 0; d4 < 16; d4++) {
                    float4 kv = kk[d4];
                    float4 qv = *(const float4*)(qw + d4 * 4);
                    acc += kv.x * qv.x + kv.y * qv.y + kv.z * qv.z + kv.w * qv.w;
                }
                s[jj] = acc + Sh[qrr + kr8[j]] + Sw[qcc + kc8[j]];
            } else {
                s[jj] = -1e30f;
            }
        }
        float mx = s[0];
        #pragma unroll
        for (int jj = 1; jj < 7; jj++) mx = fmaxf(mx, s[jj]);
        #pragma unroll
        for (int off = 16; off; off >>= 1) mx = fmaxf(mx, __shfl_xor_sync(0xffffffffu, mx, off));
        float sum = 0;
        #pragma unroll
        for (int jj = 0; jj < 7; jj++) {
            int j = lane + jj * 32;
            float e = (j < NTOK) ? expf(s[jj] - mx) : 0.f;
            s[jj] = e;
            sum += e;
        }
        #pragma unroll
        for (int off = 16; off; off >>= 1) sum += __shfl_xor_sync(0xffffffffu, sum, off);
        float inv = 1.f / sum;
        #pragma unroll
        for (int jj = 0; jj < 7; jj++) {
            int j = lane + jj * 32;
            if (j < 200) pw[j] = s[jj];
        }
        __syncwarp();
        int d = 2 * lane;
        float o0 = 0, o1 = 0;
        #pragma unroll 7
        for (int j = 0; j < NTOK; j += 4) {
            float4 p4 = *(const float4*)(pw + j);
            const float* vb = vs + j * KV_STRIDE + d;
            float2 va  = *(const float2*)(vb);
            float2 vb1 = *(const float2*)(vb + KV_STRIDE);
            float2 vc  = *(const float2*)(vb + 2 * KV_STRIDE);
            float2 vd_ = *(const float2*)(vb + 3 * KV_STRIDE);
            o0 += p4.x * va.x + p4.y * vb1.x + p4.z * vc.x + p4.w * vd_.x;
            o1 += p4.x * va.y + p4.y * vb1.y + p4.z * vc.y + p4.w * vd_.y;
        }
        size_t og = ((size_t)(win * NTOK + row)) * DIM + head * HDIM;
        g_ao[og + d]     = __float2half_rn(o0 * inv);
        g_ao[og + d + 1] = __float2half_rn(o1 * inv);
        __syncwarp();
    }
}

// ---------------- launch ----------------
extern "C" void kernel_launch(void* const* d_in, const int* in_sizes, int n_in,
                              void* d_out, int out_size)
{
    const float* x     = (const float*)d_in[0];
    const int*   qidx  = (const int*)d_in[1];
    const int*   kidx  = (const int*)d_in[2];
    const float* ln1w  = (const float*)d_in[3];
    const float* ln1b  = (const float*)d_in[4];
    const float* ln2w  = (const float*)d_in[5];
    const float* ln2b  = (const float*)d_in[6];
    const float* qkvw  = (const float*)d_in[7];
    const float* qkvb  = (const float*)d_in[8];
    const float* projw = (const float*)d_in[9];
    const float* projb = (const float*)d_in[10];
    const float* relh  = (const float*)d_in[11];
    const float* relw  = (const float*)d_in[12];
    const float* w1    = (const float*)d_in[13];
    const float* b1    = (const float*)d_in[14];
    const float* w2    = (const float*)d_in[15];
    const float* b2    = (const float*)d_in[16];
    float* out = (float*)d_out;

    cudaFuncSetAttribute(attn_kernel, cudaFuncAttributeMaxDynamicSharedMemorySize, SM_ATT_TOTAL);
    cudaFuncSetAttribute(tgemm_kernel<0>, cudaFuncAttributeMaxDynamicSharedMemorySize, SMEM_TG);
    cudaFuncSetAttribute(tgemm_kernel<1>, cudaFuncAttributeMaxDynamicSharedMemorySize, SMEM_TG);
    cudaFuncSetAttribute(tgemm_kernel<2>, cudaFuncAttributeMaxDynamicSharedMemorySize, SMEM_TG);
    cudaFuncSetAttribute(tgemm_kernel<3>, cudaFuncAttributeMaxDynamicSharedMemorySize, SMEM_TG);

    __half *wqkv_h, *wqkv_l, *wproj_h, *wproj_l, *w1_h, *w1_l, *w2_h, *w2_l;
    cudaGetSymbolAddress((void**)&wqkv_h, g_wqkv_h);
    cudaGetSymbolAddress((void**)&wqkv_l, g_wqkv_l);
    cudaGetSymbolAddress((void**)&wproj_h, g_wproj_h);
    cudaGetSymbolAddress((void**)&wproj_l, g_wproj_l);
    cudaGetSymbolAddress((void**)&w1_h, g_w1_h);
    cudaGetSymbolAddress((void**)&w1_l, g_w1_l);
    cudaGetSymbolAddress((void**)&w2_h, g_w2_h);
    cudaGetSymbolAddress((void**)&w2_l, g_w2_l);

    // launch index 3 = attn_kernel (ncu profiles it this round)
    wsplit_kernel<<<dim3(2304 / 32, 768 / 32), 256>>>(qkvw, wqkv_h, wqkv_l, 768, 2304);   // 0
    ln1_kernel<<<TOKW, 256>>>(x, ln1w, ln1b);                                              // 1
    tgemm_kernel<0><<<dim3(2304 / 128, TOKW_PAD / 128), 256, SMEM_TG>>>(qkvb, nullptr, nullptr); // 2
    attn_kernel<<<BH, 256, SM_ATT_TOTAL>>>(relh, relw, qidx, kidx);                        // 3
    wsplit_kernel<<<dim3(768 / 32, 768 / 32), 256>>>(projw, wproj_h, wproj_l, 768, 768);   // 4
    tgemm_kernel<1><<<dim3(768 / 128, TOKW_PAD / 128), 256, SMEM_TG>>>(projb, x, nullptr); // 5
    ln2_kernel<<<TOKX, 256>>>(ln2w, ln2b);                                                 // 6
    wsplit_kernel<<<dim3(3072 / 32, 768 / 32), 256>>>(w1, w1_h, w1_l, 768, 3072);          // 7
    tgemm_kernel<2><<<dim3(3072 / 128, TOKX / 128), 256, SMEM_TG>>>(b1, nullptr, nullptr); // 8
    wsplit_kernel<<<dim3(768 / 32, 3072 / 32), 256>>>(w2, w2_h, w2_l, 3072, 768);          // 9
    tgemm_kernel<3><<<dim3(768 / 128, TOKX / 128), 256, SMEM_TG>>>(b2, nullptr, out);      // 10
}

// round 10
// speedup vs baseline: 1.8246x; 1.4352x over previous
/*
 * R10: tensor-core attention (mma.sync, FA2 fragment repack) + fp16 q/k/v.
 * GEMM path unchanged from R9 (A single fp16, B hi/lo, 3-stage cp.async).
 */
#include <cuda_runtime.h>
#include <cuda_fp16.h>
#include <math.h>
#include <stdint.h>

#define DIM   768
#define NHEAD 12
#define HDIM  64
#define WS    14
#define NTOK  196
#define NWIN  25
#define BATCH 8
#define NWB   200
#define TOKW  39200
#define TOKW_PAD 39296
#define TOKX  32768
#define BH    2400

// ---------------- device scratch ----------------
__device__ __half g_a[(size_t)TOKW_PAD * DIM];
__device__ __half g_ao[(size_t)TOKW_PAD * DIM];
__device__ __half g_b[(size_t)TOKX * DIM];
__device__ __half g_h1[(size_t)TOKX * 3072];
__device__ __half g_wqkv_h[(size_t)2304 * 768];
__device__ __half g_wqkv_l[(size_t)2304 * 768];
__device__ __half g_wproj_h[(size_t)768 * 768];
__device__ __half g_wproj_l[(size_t)768 * 768];
__device__ __half g_w1_h[(size_t)3072 * 768];
__device__ __half g_w1_l[(size_t)3072 * 768];
__device__ __half g_w2_h[(size_t)768 * 3072];
__device__ __half g_w2_l[(size_t)768 * 3072];
__device__ __half g_qh[(size_t)BH * NTOK * HDIM];
__device__ __half g_kh[(size_t)BH * NTOK * HDIM];
__device__ __half g_vh[(size_t)BH * NTOK * HDIM];
__device__ float g_x2[(size_t)TOKX * DIM];

// ---------------- PTX helpers ----------------
__device__ __forceinline__ uint32_t smem_u32(const void* p) {
    uint32_t a;
    asm("{ .reg .u64 t; cvta.to.shared.u64 t, %1; cvt.u32.u64 %0, t; }" : "=r"(a) : "l"(p));
    return a;
}
__device__ __forceinline__ void cp16(uint32_t dst, const void* src) {
    asm volatile("cp.async.cg.shared.global [%0], [%1], 16;" :: "r"(dst), "l"(src));
}
__device__ __forceinline__ void ldsm_x4(uint32_t* r, uint32_t addr) {
    asm volatile("ldmatrix.sync.aligned.m8n8.x4.shared.b16 {%0,%1,%2,%3}, [%4];"
        : "=r"(r[0]), "=r"(r[1]), "=r"(r[2]), "=r"(r[3]) : "r"(addr));
}
__device__ __forceinline__ void ldsm_x2(uint32_t* r, uint32_t addr) {
    asm volatile("ldmatrix.sync.aligned.m8n8.x2.shared.b16 {%0,%1}, [%2];"
        : "=r"(r[0]), "=r"(r[1]) : "r"(addr));
}
__device__ __forceinline__ void ldsm_x2t(uint32_t* r, uint32_t addr) {
    asm volatile("ldmatrix.sync.aligned.m8n8.x2.trans.shared.b16 {%0,%1}, [%2];"
        : "=r"(r[0]), "=r"(r[1]) : "r"(addr));
}
__device__ __forceinline__ void mma_f16(float* c, const uint32_t* a, const uint32_t* b) {
    asm volatile(
        "mma.sync.aligned.m16n8k16.row.col.f32.f16.f16.f32 "
        "{%0,%1,%2,%3}, {%4,%5,%6,%7}, {%8,%9}, {%0,%1,%2,%3};"
        : "+f"(c[0]), "+f"(c[1]), "+f"(c[2]), "+f"(c[3])
        : "r"(a[0]), "r"(a[1]), "r"(a[2]), "r"(a[3]), "r"(b[0]), "r"(b[1]));
}
__device__ __forceinline__ void f16split(float v, __half& h, __half& l) {
    h = __float2half_rn(v);
    l = __float2half_rn(v - __half2float(h));
}
__device__ __forceinline__ uint32_t packh2(float a, float b) {
    __half2 h = __floats2half2_rn(a, b);
    return *(uint32_t*)&h;
}

// ---------------- weight transpose + fp16 split: W[K,N] -> Wt_h/l[N,K] ----------------
__global__ __launch_bounds__(256) void wsplit_kernel(const float* __restrict__ W,
                                                     __half* __restrict__ Wh,
                                                     __half* __restrict__ Wl,
                                                     int K, int N)
{
    __shared__ float tile[32][33];
    int k0 = blockIdx.y * 32, n0 = blockIdx.x * 32;
    int tx = threadIdx.x & 31, ty = threadIdx.x >> 5;
    #pragma unroll
    for (int j = 0; j < 32; j += 8)
        tile[ty + j][tx] = W[(size_t)(k0 + ty + j) * N + n0 + tx];
    __syncthreads();
    #pragma unroll
    for (int j = 0; j < 32; j += 8) {
        float v = tile[tx][ty + j];
        __half h, l;
        f16split(v, h, l);
        size_t o = (size_t)(n0 + ty + j) * K + k0 + tx;
        Wh[o] = h; Wl[o] = l;
    }
}

// ---------------- LayerNorm 1 (window partition + pad, fp16 out) ----------------
__global__ __launch_bounds__(256) void ln1_kernel(const float* __restrict__ x,
                                                  const float* __restrict__ g,
                                                  const float* __restrict__ b)
{
    int widx = blockIdx.x;
    int win = widx / NTOK, tok = widx - win * NTOK;
    int bb = win / NWIN, rem = win - bb * NWIN;
    int y = (rem / 5) * WS + tok / WS;
    int xx = (rem % 5) * WS + tok % WS;
    size_t ob = (size_t)widx * DIM;
    int tid = threadIdx.x;
    if (y >= 64 || xx >= 64) {
        for (int i = tid; i < DIM; i += 256) g_a[ob + i] = __float2half(0.f);
        return;
    }
    const float* row = x + ((size_t)(bb * 64 + y) * 64 + xx) * DIM;
    float v0 = row[tid], v1 = row[tid + 256], v2 = row[tid + 512];
    float s = v0 + v1 + v2, sq = v0 * v0 + v1 * v1 + v2 * v2;
    #pragma unroll
    for (int off = 16; off; off >>= 1) {
        s  += __shfl_xor_sync(0xffffffffu, s, off);
        sq += __shfl_xor_sync(0xffffffffu, sq, off);
    }
    __shared__ float rs[8], rq[8], smu, srs;
    int wid = tid >> 5, lane = tid & 31;
    if (!lane) { rs[wid] = s; rq[wid] = sq; }
    __syncthreads();
    if (tid == 0) {
        float S = 0, Q = 0;
        #pragma unroll
        for (int i = 0; i < 8; i++) { S += rs[i]; Q += rq[i]; }
        float mu = S * (1.f / 768.f);
        float var = Q * (1.f / 768.f) - mu * mu;
        smu = mu; srs = rsqrtf(var + 1e-5f);
    }
    __syncthreads();
    float mu = smu, r = srs;
    #pragma unroll
    for (int p = 0; p < 3; p++) {
        int i = tid + p * 256;
        float vv = ((p == 0 ? v0 : p == 1 ? v1 : v2) - mu) * r * g[i] + b[i];
        g_a[ob + i] = __float2half_rn(vv);
    }
}

// ---------------- LayerNorm 2 (fp16 out) ----------------
__global__ __launch_bounds__(256) void ln2_kernel(const float* __restrict__ g,
                                                  const float* __restrict__ b)
{
    int tid = threadIdx.x;
    const float* row = g_x2 + (size_t)blockIdx.x * DIM;
    size_t ob = (size_t)blockIdx.x * DIM;
    float v0 = row[tid], v1 = row[tid + 256], v2 = row[tid + 512];
    float s = v0 + v1 + v2, sq = v0 * v0 + v1 * v1 + v2 * v2;
    #pragma unroll
    for (int off = 16; off; off >>= 1) {
        s  += __shfl_xor_sync(0xffffffffu, s, off);
        sq += __shfl_xor_sync(0xffffffffu, sq, off);
    }
    __shared__ float rs[8], rq[8], smu, srs;
    int wid = tid >> 5, lane = tid & 31;
    if (!lane) { rs[wid] = s; rq[wid] = sq; }
    __syncthreads();
    if (tid == 0) {
        float S = 0, Q = 0;
        #pragma unroll
        for (int i = 0; i < 8; i++) { S += rs[i]; Q += rq[i]; }
        float mu = S * (1.f / 768.f);
        float var = Q * (1.f / 768.f) - mu * mu;
        smu = mu; srs = rsqrtf(var + 1e-5f);
    }
    __syncthreads();
    float mu = smu, r = srs;
    #pragma unroll
    for (int p = 0; p < 3; p++) {
        int i = tid + p * 256;
        float vv = ((p == 0 ? v0 : p == 1 ? v1 : v2) - mu) * r * g[i] + b[i];
        g_b[ob + i] = __float2half_rn(vv);
    }
}

// ---------------- mma.sync GEMM: D[M,N] = A[M,K] x Wt[N,K]^T ----------------
#define TG_MAT_B   10240
#define TG_STAGE   (3 * TG_MAT_B)
#define SMEM_TG    (3 * TG_STAGE)

template <int MODE>
__global__ __launch_bounds__(256, 2) void tgemm_kernel(const float* __restrict__ bias,
                                                       const float* __restrict__ aux,
                                                       float* __restrict__ outp)
{
    constexpr int K      = (MODE == 3) ? 3072 : 768;
    constexpr int Mreal  = (MODE <= 1) ? TOKW : TOKX;
    constexpr int NCHUNK = K / 32;
    const __half* gA  = (MODE == 0) ? g_a : (MODE == 1) ? g_ao : (MODE == 2) ? g_b : g_h1;
    const __half* gBh = (MODE == 0) ? g_wqkv_h : (MODE == 1) ? g_wproj_h : (MODE == 2) ? g_w1_h : g_w2_h;
    const __half* gBl = (MODE == 0) ? g_wqkv_l : (MODE == 1) ? g_wproj_l : (MODE == 2) ? g_w1_l : g_w2_l;

    extern __shared__ char smem_raw[];
    const uint32_t sbase = smem_u32(smem_raw);

    const int t = threadIdx.x;
    const int m0 = blockIdx.y * 128;
    const int n0 = blockIdx.x * 128;
    const int warp = t >> 5, lane = t & 31;
    const int wm = warp >> 2, wn = warp & 3;

    float acc[4][4][4];
    #pragma unroll
    for (int a = 0; a < 4; a++)
        #pragma unroll
        for (int b2 = 0; b2 < 4; b2++)
            #pragma unroll
            for (int c = 0; c < 4; c++) acc[a][b2][c] = 0.f;

    const int ldrow = t >> 2, ldseg = t & 3;
    const uint32_t sm_off0 = (uint32_t)(ldrow * 80 + ldseg * 16);
    const uint32_t sm_off1 = (uint32_t)((ldrow + 64) * 80 + ldseg * 16);

    auto issue = [&](int chunk, int stg) {
        const int k0 = chunk * 32;
        const uint32_t so = sbase + (uint32_t)(stg * TG_STAGE);
        size_t ga0 = (size_t)(m0 + ldrow) * K + k0 + ldseg * 8;
        size_t ga1 = (size_t)(m0 + ldrow + 64) * K + k0 + ldseg * 8;
        size_t gb0 = (size_t)(n0 + ldrow) * K + k0 + ldseg * 8;
        size_t gb1 = (size_t)(n0 + ldrow + 64) * K + k0 + ldseg * 8;
        cp16(so + sm_off0, gA + ga0);
        cp16(so + sm_off1, gA + ga1);
        cp16(so + TG_MAT_B + sm_off0, gBh + gb0);
        cp16(so + TG_MAT_B + sm_off1, gBh + gb1);
        cp16(so + 2 * TG_MAT_B + sm_off0, gBl + gb0);
        cp16(so + 2 * TG_MAT_B + sm_off1, gBl + gb1);
        asm volatile("cp.async.commit_group;" ::: "memory");
    };

    issue(0, 0);
    issue(1, 1);

    const int a_row_in = (lane & 7) + (lane & 8);
    const int a_koff   = (lane >> 4) * 8;
    const int b_row_in = lane & 7;
    const int b_koff   = ((lane >> 3) & 1) * 8;

    for (int i = 0; i < NCHUNK; i++) {
        if (i + 1 < NCHUNK)
            asm volatile("cp.async.wait_group 1;" ::: "memory");
        else
            asm volatile("cp.async.wait_group 0;" ::: "memory");
        __syncthreads();
        if (i + 2 < NCHUNK) issue(i + 2, (i + 2) % 3);

        const uint32_t soA = sbase + (uint32_t)((i % 3) * TG_STAGE);
        const uint32_t soB = soA + TG_MAT_B;
        #pragma unroll
        for (int ks = 0; ks < 2; ks++) {
            uint32_t bh[4][2], bl[4][2];
            #pragma unroll
            for (int nt = 0; nt < 4; nt++) {
                int nr = wn * 32 + nt * 8 + b_row_in;
                uint32_t bd = soB + (uint32_t)((nr * 40 + ks * 16 + b_koff) * 2);
                ldsm_x2(bh[nt], bd);
                ldsm_x2(bl[nt], bd + TG_MAT_B);
            }
            #pragma unroll
            for (int mt = 0; mt < 4; mt++) {
                uint32_t ah[4];
                int mr = wm * 64 + mt * 16 + a_row_in;
                uint32_t ad = soA + (uint32_t)((mr * 40 + ks * 16 + a_koff) * 2);
                ldsm_x4(ah, ad);
                #pragma unroll
                for (int nt = 0; nt < 4; nt++) {
                    mma_f16(acc[mt][nt], ah, bh[nt]);
                    mma_f16(acc[mt][nt], ah, bl[nt]);
                }
            }
        }
        __syncthreads();
    }

    // ---- epilogue ----
    const int g = lane >> 2, tq = lane & 3;
    #pragma unroll
    for (int mt = 0; mt < 4; mt++) {
        #pragma unroll
        for (int half = 0; half < 2; half++) {
            int m = m0 + wm * 64 + mt * 16 + g + half * 8;
            bool valid = (m < Mreal);
            int win = 0, tok = 0, yy = 0, xx = 0, bb = 0;
            if (MODE <= 1) {
                win = m / NTOK; tok = m - win * NTOK;
                if (MODE == 1) {
                    bb = win / NWIN; int rem = win - bb * NWIN;
                    yy = (rem / 5) * WS + tok / WS;
                    xx = (rem % 5) * WS + tok % WS;
                    valid = valid && (yy < 64) && (xx < 64);
                }
            }
            if (!valid) continue;
            #pragma unroll
            for (int nt = 0; nt < 4; nt++) {
                int n = n0 + wn * 32 + nt * 8 + 2 * tq;
                float v0 = acc[mt][nt][half * 2]     + bias[n];
                float v1 = acc[mt][nt][half * 2 + 1] + bias[n + 1];
                if (MODE == 0) {
                    int which = n / 768;
                    int dd = n - which * 768;
                    int head = dd >> 6, hd = dd & 63;
                    size_t o = ((size_t)(win * NHEAD + head) * NTOK + tok) * HDIM + hd;
                    if (which == 0) {
                        g_qh[o]     = __float2half_rn(v0 * 0.125f);
                        g_qh[o + 1] = __float2half_rn(v1 * 0.125f);
                    } else if (which == 1) {
                        g_kh[o]     = __float2half_rn(v0);
                        g_kh[o + 1] = __float2half_rn(v1);
                    } else {
                        g_vh[o]     = __float2half_rn(v0);
                        g_vh[o + 1] = __float2half_rn(v1);
                    }
                } else if (MODE == 1) {
                    size_t o = ((size_t)(bb * 64 + yy) * 64 + xx) * DIM + n;
                    g_x2[o]     = aux[o] + v0;
                    g_x2[o + 1] = aux[o + 1] + v1;
                } else if (MODE == 2) {
                    float gl0 = 0.5f * v0 * (1.f + erff(v0 * 0.70710678118f));
                    float gl1 = 0.5f * v1 * (1.f + erff(v1 * 0.70710678118f));
                    size_t o = (size_t)m * 3072 + n;
                    g_h1[o]     = __float2half_rn(gl0);
                    g_h1[o + 1] = __float2half_rn(gl1);
                } else {
                    size_t o = (size_t)m * DIM + n;
                    outp[o]     = v0 + g_x2[o];
                    outp[o + 1] = v1 + g_x2[o + 1];
                }
            }
        }
    }
}

// ---------------- tensor-core attention: one CTA (8 warps) per (window, head) ----------------
// smem: qs[208][72] ks[200][72] vs[208][72] fp16, Sh/Sw[196] f32, rsh/rsw[32] f32, idx bytes
#define ATT_QS_H   0
#define ATT_KS_H   14976
#define ATT_VS_H   29376
#define ATT_F_OFF  88704
#define ATT_B_OFF  90528
#define SM_ATT_TOTAL 91328

__global__ __launch_bounds__(256) void attn_kernel(const float* __restrict__ rel_h,
                                                   const float* __restrict__ rel_w,
                                                   const int* __restrict__ q_idx,
                                                   const int* __restrict__ k_idx)
{
    extern __shared__ char smraw[];
    __half* qs  = (__half*)smraw;
    __half* ksm = qs + ATT_KS_H;
    __half* vsm = qs + ATT_VS_H;
    float* Shf  = (float*)(smraw + ATT_F_OFF);
    float* Swf  = Shf + 196;
    float* rshf = Swf + 196;
    float* rswf = rshf + 32;
    unsigned char* qr8 = (unsigned char*)(smraw + ATT_B_OFF);
    unsigned char* qc8 = qr8 + 196;
    unsigned char* kr8 = qc8 + 196;
    unsigned char* kc8 = kr8 + 196;

    const uint32_t sb = smem_u32(smraw);
    int bh = blockIdx.x;
    int win = bh / NHEAD, head = bh - win * NHEAD;
    int tid = threadIdx.x, warp = tid >> 5, lane = tid & 31;

    const __half* qg = g_qh + (size_t)bh * NTOK * HDIM;
    const __half* kg = g_kh + (size_t)bh * NTOK * HDIM;
    const __half* vg = g_vh + (size_t)bh * NTOK * HDIM;
    for (int i = tid; i < 196 * 8; i += 256) {
        int r = i >> 3, sg = i & 7;
        *(uint4*)(qs  + r * 72 + sg * 8) = *(const uint4*)(qg + r * 64 + sg * 8);
        *(uint4*)(ksm + r * 72 + sg * 8) = *(const uint4*)(kg + r * 64 + sg * 8);
        *(uint4*)(vsm + r * 72 + sg * 8) = *(const uint4*)(vg + r * 64 + sg * 8);
    }
    uint4 z = make_uint4(0, 0, 0, 0);
    for (int i = tid; i < 224; i += 256) {
        if (i < 96)       { int r = 196 + (i >> 3);        *(uint4*)(qs  + r * 72 + (i & 7) * 8) = z; }
        else if (i < 128) { int j = i - 96;  int r = 196 + (j >> 3); *(uint4*)(ksm + r * 72 + (j & 7) * 8) = z; }
        else              { int j = i - 128; int r = 196 + (j >> 3); *(uint4*)(vsm + r * 72 + (j & 7) * 8) = z; }
    }
    if (tid < 27) {
        const float* rp = rel_h + tid * HDIM;
        float s = 0;
        #pragma unroll 8
        for (int c = 0; c < HDIM; c++) s += rp[c];
        rshf[tid] = s;
    } else if (tid >= 32 && tid < 59) {
        const float* rp = rel_w + (tid - 32) * HDIM;
        float s = 0;
        #pragma unroll 8
        for (int c = 0; c < HDIM; c++) s += rp[c];
        rswf[tid - 32] = s;
    }
    if (tid < 196) {
        int qi = q_idx[(size_t)bh * NTOK + tid];
        int ki = k_idx[(size_t)bh * NTOK + tid];
        qr8[tid] = (unsigned char)(qi / WS);
        qc8[tid] = (unsigned char)(qi % WS);
        kr8[tid] = (unsigned char)(ki / WS);
        kc8[tid] = (unsigned char)(ki % WS);
    }
    __syncthreads();
    if (tid < 196) {
        int i = tid / WS, j = tid - i * WS;
        Shf[tid] = rshf[i - j + WS - 1];
        Swf[tid] = rswf[i - j + WS - 1];
    }
    __syncthreads();

    const int g = lane >> 2, tq = lane & 3;
    const int a_row_in = (lane & 7) + (lane & 8);
    const int a_koff   = (lane >> 4) * 8;
    const int b_row_in = lane & 7;
    const int b_koff   = ((lane >> 3) & 1) * 8;
    const uint32_t kbase = sb + ATT_KS_H * 2;
    const uint32_t vbase = sb + ATT_VS_H * 2;

    for (int mt = warp; mt < 13; mt += 8) {
        float sacc[25][4];
        #pragma unroll
        for (int nt = 0; nt < 25; nt++)
            #pragma unroll
            for (int c = 0; c < 4; c++) sacc[nt][c] = 0.f;

        #pragma unroll
        for (int kk = 0; kk < 4; kk++) {
            uint32_t af[4];
            uint32_t qa = sb + (uint32_t)(((mt * 16 + a_row_in) * 72 + kk * 16 + a_koff) * 2);
            ldsm_x4(af, qa);
            #pragma unroll
            for (int nt = 0; nt < 25; nt++) {
                uint32_t bf[2];
                uint32_t ka = kbase + (uint32_t)(((nt * 8 + b_row_in) * 72 + kk * 16 + b_koff) * 2);
                ldsm_x2(bf, ka);
                mma_f16(sacc[nt], af, bf);
            }
        }

        int row0 = mt * 16 + g;
        int row1 = row0 + 8;
        int qb0 = qr8[row0] * WS, qc0 = qc8[row0] * WS;
        int qb1 = qr8[row1] * WS, qc1 = qc8[row1] * WS;
        float mx0 = -1e30f, mx1 = -1e30f;
        #pragma unroll
        for (int nt = 0; nt < 25; nt++) {
            #pragma unroll
            for (int c = 0; c < 2; c++) {
                int col = nt * 8 + tq * 2 + c;
                float s0, s1;
                if (col < 196) {
                    int kr = kr8[col], kc = kc8[col];
                    s0 = sacc[nt][c]     + Shf[qb0 + kr] + Swf[qc0 + kc];
                    s1 = sacc[nt][2 + c] + Shf[qb1 + kr] + Swf[qc1 + kc];
                } else {
                    s0 = -1e30f; s1 = -1e30f;
                }
                sacc[nt][c] = s0; sacc[nt][2 + c] = s1;
                mx0 = fmaxf(mx0, s0); mx1 = fmaxf(mx1, s1);
            }
        }
        mx0 = fmaxf(mx0, __shfl_xor_sync(0xffffffffu, mx0, 1));
        mx0 = fmaxf(mx0, __shfl_xor_sync(0xffffffffu, mx0, 2));
        mx1 = fmaxf(mx1, __shfl_xor_sync(0xffffffffu, mx1, 1));
        mx1 = fmaxf(mx1, __shfl_xor_sync(0xffffffffu, mx1, 2));

        float sm0 = 0.f, sm1 = 0.f;
        uint32_t pf[13][4];
        #pragma unroll
        for (int nt = 0; nt < 25; nt++) {
            float e00 = expf(sacc[nt][0] - mx0);
            float e01 = expf(sacc[nt][1] - mx0);
            float e10 = expf(sacc[nt][2] - mx1);
            float e11 = expf(sacc[nt][3] - mx1);
            sm0 += e00 + e01;
            sm1 += e10 + e11;
            int kt = nt >> 1, hi = nt & 1;
            pf[kt][hi * 2 + 0] = packh2(e00, e01);
            pf[kt][hi * 2 + 1] = packh2(e10, e11);
        }
        pf[12][2] = 0u; pf[12][3] = 0u;
        sm0 += __shfl_xor_sync(0xffffffffu, sm0, 1);
        sm0 += __shfl_xor_sync(0xffffffffu, sm0, 2);
        sm1 += __shfl_xor_sync(0xffffffffu, sm1, 1);
        sm1 += __shfl_xor_sync(0xffffffffu, sm1, 2);
        float inv0 = 1.f / sm0, inv1 = 1.f / sm1;

        float oacc[8][4];
        #pragma unroll
        for (int dt = 0; dt < 8; dt++)
            #pragma unroll
            for (int c = 0; c < 4; c++) oacc[dt][c] = 0.f;
        #pragma unroll
        for (int kt = 0; kt < 13; kt++) {
            #pragma unroll
            for (int dt = 0; dt < 8; dt++) {
                uint32_t bf[2];
                uint32_t va = vbase + (uint32_t)(((kt * 16 + (lane & 15)) * 72 + dt * 8) * 2);
                ldsm_x2t(bf, va);
                mma_f16(oacc[dt], pf[kt], bf);
            }
        }

        bool ok0 = row0 < NTOK, ok1 = row1 < NTOK;
        size_t ob0 = ((size_t)(win * NTOK) + row0) * DIM + head * HDIM;
        #pragma unroll
        for (int dt = 0; dt < 8; dt++) {
            int d = dt * 8 + tq * 2;
            if (ok0) {
                __half2 hv = __floats2half2_rn(oacc[dt][0] * inv0, oacc[dt][1] * inv0);
                *(__half2*)(g_ao + ob0 + d) = hv;
            }
            if (ok1) {
                __half2 hv = __floats2half2_rn(oacc[dt][2] * inv1, oacc[dt][3] * inv1);
                *(__half2*)(g_ao + ob0 + (size_t)8 * DIM + d) = hv;
            }
        }
    }
}

// ---------------- launch ----------------
extern "C" void kernel_launch(void* const* d_in, const int* in_sizes, int n_in,
                              void* d_out, int out_size)
{
    const float* x     = (const float*)d_in[0];
    const int*   qidx  = (const int*)d_in[1];
    const int*   kidx  = (const int*)d_in[2];
    const float* ln1w  = (const float*)d_in[3];
    const float* ln1b  = (const float*)d_in[4];
    const float* ln2w  = (const float*)d_in[5];
    const float* ln2b  = (const float*)d_in[6];
    const float* qkvw  = (const float*)d_in[7];
    const float* qkvb  = (const float*)d_in[8];
    const float* projw = (const float*)d_in[9];
    const float* projb = (const float*)d_in[10];
    const float* relh  = (const float*)d_in[11];
    const float* relw  = (const float*)d_in[12];
    const float* w1    = (const float*)d_in[13];
    const float* b1    = (const float*)d_in[14];
    const float* w2    = (const float*)d_in[15];
    const float* b2    = (const float*)d_in[16];
    float* out = (float*)d_out;

    cudaFuncSetAttribute(attn_kernel, cudaFuncAttributeMaxDynamicSharedMemorySize, SM_ATT_TOTAL);
    cudaFuncSetAttribute(tgemm_kernel<0>, cudaFuncAttributeMaxDynamicSharedMemorySize, SMEM_TG);
    cudaFuncSetAttribute(tgemm_kernel<1>, cudaFuncAttributeMaxDynamicSharedMemorySize, SMEM_TG);
    cudaFuncSetAttribute(tgemm_kernel<2>, cudaFuncAttributeMaxDynamicSharedMemorySize, SMEM_TG);
    cudaFuncSetAttribute(tgemm_kernel<3>, cudaFuncAttributeMaxDynamicSharedMemorySize, SMEM_TG);

    __half *wqkv_h, *wqkv_l, *wproj_h, *wproj_l, *w1_h, *w1_l, *w2_h, *w2_l;
    cudaGetSymbolAddress((void**)&wqkv_h, g_wqkv_h);
    cudaGetSymbolAddress((void**)&wqkv_l, g_wqkv_l);
    cudaGetSymbolAddress((void**)&wproj_h, g_wproj_h);
    cudaGetSymbolAddress((void**)&wproj_l, g_wproj_l);
    cudaGetSymbolAddress((void**)&w1_h, g_w1_h);
    cudaGetSymbolAddress((void**)&w1_l, g_w1_l);
    cudaGetSymbolAddress((void**)&w2_h, g_w2_h);
    cudaGetSymbolAddress((void**)&w2_l, g_w2_l);

    // launch index 3 = attn_kernel (ncu profiles it)
    wsplit_kernel<<<dim3(2304 / 32, 768 / 32), 256>>>(qkvw, wqkv_h, wqkv_l, 768, 2304);   // 0
    ln1_kernel<<<TOKW, 256>>>(x, ln1w, ln1b);                                              // 1
    tgemm_kernel<0><<<dim3(2304 / 128, TOKW_PAD / 128), 256, SMEM_TG>>>(qkvb, nullptr, nullptr); // 2
    attn_kernel<<<BH, 256, SM_ATT_TOTAL>>>(relh, relw, qidx, kidx);                        // 3
    wsplit_kernel<<<dim3(768 / 32, 768 / 32), 256>>>(projw, wproj_h, wproj_l, 768, 768);   // 4
    tgemm_kernel<1><<<dim3(768 / 128, TOKW_PAD / 128), 256, SMEM_TG>>>(projb, x, nullptr); // 5
    ln2_kernel<<<TOKX, 256>>>(ln2w, ln2b);                                                 // 6
    wsplit_kernel<<<dim3(3072 / 32, 768 / 32), 256>>>(w1, w1_h, w1_l, 768, 3072);          // 7
    tgemm_kernel<2><<<dim3(3072 / 128, TOKX / 128), 256, SMEM_TG>>>(b1, nullptr, nullptr); // 8
    wsplit_kernel<<<dim3(768 / 32, 3072 / 32), 256>>>(w2, w2_h, w2_l, 3072, 768);          // 9
    tgemm_kernel<3><<<dim3(768 / 128, TOKX / 128), 256, SMEM_TG>>>(b2, nullptr, out);      // 10
}

// round 11
// speedup vs baseline: 2.3269x; 1.2753x over previous
/*
 * R11: MLP GEMMs drop B-lo (1 MMA/step, -31% total MMA work), single-barrier
 * 3-stage pipeline, wsplit skips Wl for MLP weights. Attention unchanged (R10).
 */
#include <cuda_runtime.h>
#include <cuda_fp16.h>
#include <math.h>
#include <stdint.h>

#define DIM   768
#define NHEAD 12
#define HDIM  64
#define WS    14
#define NTOK  196
#define NWIN  25
#define BATCH 8
#define NWB   200
#define TOKW  39200
#define TOKW_PAD 39296
#define TOKX  32768
#define BH    2400

// ---------------- device scratch ----------------
__device__ __half g_a[(size_t)TOKW_PAD * DIM];
__device__ __half g_ao[(size_t)TOKW_PAD * DIM];
__device__ __half g_b[(size_t)TOKX * DIM];
__device__ __half g_h1[(size_t)TOKX * 3072];
__device__ __half g_wqkv_h[(size_t)2304 * 768];
__device__ __half g_wqkv_l[(size_t)2304 * 768];
__device__ __half g_wproj_h[(size_t)768 * 768];
__device__ __half g_wproj_l[(size_t)768 * 768];
__device__ __half g_w1_h[(size_t)3072 * 768];
__device__ __half g_w2_h[(size_t)768 * 3072];
__device__ __half g_qh[(size_t)BH * NTOK * HDIM];
__device__ __half g_kh[(size_t)BH * NTOK * HDIM];
__device__ __half g_vh[(size_t)BH * NTOK * HDIM];
__device__ float g_x2[(size_t)TOKX * DIM];

// ---------------- PTX helpers ----------------
__device__ __forceinline__ uint32_t smem_u32(const void* p) {
    uint32_t a;
    asm("{ .reg .u64 t; cvta.to.shared.u64 t, %1; cvt.u32.u64 %0, t; }" : "=r"(a) : "l"(p));
    return a;
}
__device__ __forceinline__ void cp16(uint32_t dst, const void* src) {
    asm volatile("cp.async.cg.shared.global [%0], [%1], 16;" :: "r"(dst), "l"(src));
}
__device__ __forceinline__ void ldsm_x4(uint32_t* r, uint32_t addr) {
    asm volatile("ldmatrix.sync.aligned.m8n8.x4.shared.b16 {%0,%1,%2,%3}, [%4];"
        : "=r"(r[0]), "=r"(r[1]), "=r"(r[2]), "=r"(r[3]) : "r"(addr));
}
__device__ __forceinline__ void ldsm_x2(uint32_t* r, uint32_t addr) {
    asm volatile("ldmatrix.sync.aligned.m8n8.x2.shared.b16 {%0,%1}, [%2];"
        : "=r"(r[0]), "=r"(r[1]) : "r"(addr));
}
__device__ __forceinline__ void ldsm_x2t(uint32_t* r, uint32_t addr) {
    asm volatile("ldmatrix.sync.aligned.m8n8.x2.trans.shared.b16 {%0,%1}, [%2];"
        : "=r"(r[0]), "=r"(r[1]) : "r"(addr));
}
__device__ __forceinline__ void mma_f16(float* c, const uint32_t* a, const uint32_t* b) {
    asm volatile(
        "mma.sync.aligned.m16n8k16.row.col.f32.f16.f16.f32 "
        "{%0,%1,%2,%3}, {%4,%5,%6,%7}, {%8,%9}, {%0,%1,%2,%3};"
        : "+f"(c[0]), "+f"(c[1]), "+f"(c[2]), "+f"(c[3])
        : "r"(a[0]), "r"(a[1]), "r"(a[2]), "r"(a[3]), "r"(b[0]), "r"(b[1]));
}
__device__ __forceinline__ void f16split(float v, __half& h, __half& l) {
    h = __float2half_rn(v);
    l = __float2half_rn(v - __half2float(h));
}
__device__ __forceinline__ uint32_t packh2(float a, float b) {
    __half2 h = __floats2half2_rn(a, b);
    return *(uint32_t*)&h;
}

// ---------------- weight transpose + fp16 split: W[K,N] -> Wt_h(/l)[N,K] ----------------
__global__ __launch_bounds__(256) void wsplit_kernel(const float* __restrict__ W,
                                                     __half* __restrict__ Wh,
                                                     __half* __restrict__ Wl,
                                                     int K, int N)
{
    __shared__ float tile[32][33];
    int k0 = blockIdx.y * 32, n0 = blockIdx.x * 32;
    int tx = threadIdx.x & 31, ty = threadIdx.x >> 5;
    #pragma unroll
    for (int j = 0; j < 32; j += 8)
        tile[ty + j][tx] = W[(size_t)(k0 + ty + j) * N + n0 + tx];
    __syncthreads();
    #pragma unroll
    for (int j = 0; j < 32; j += 8) {
        float v = tile[tx][ty + j];
        __half h, l;
        f16split(v, h, l);
        size_t o = (size_t)(n0 + ty + j) * K + k0 + tx;
        Wh[o] = h;
        if (Wl) Wl[o] = l;
    }
}

// ---------------- LayerNorm 1 (window partition + pad, fp16 out) ----------------
__global__ __launch_bounds__(256) void ln1_kernel(const float* __restrict__ x,
                                                  const float* __restrict__ g,
                                                  const float* __restrict__ b)
{
    int widx = blockIdx.x;
    int win = widx / NTOK, tok = widx - win * NTOK;
    int bb = win / NWIN, rem = win - bb * NWIN;
    int y = (rem / 5) * WS + tok / WS;
    int xx = (rem % 5) * WS + tok % WS;
    size_t ob = (size_t)widx * DIM;
    int tid = threadIdx.x;
    if (y >= 64 || xx >= 64) {
        for (int i = tid; i < DIM; i += 256) g_a[ob + i] = __float2half(0.f);
        return;
    }
    const float* row = x + ((size_t)(bb * 64 + y) * 64 + xx) * DIM;
    float v0 = row[tid], v1 = row[tid + 256], v2 = row[tid + 512];
    float s = v0 + v1 + v2, sq = v0 * v0 + v1 * v1 + v2 * v2;
    #pragma unroll
    for (int off = 16; off; off >>= 1) {
        s  += __shfl_xor_sync(0xffffffffu, s, off);
        sq += __shfl_xor_sync(0xffffffffu, sq, off);
    }
    __shared__ float rs[8], rq[8], smu, srs;
    int wid = tid >> 5, lane = tid & 31;
    if (!lane) { rs[wid] = s; rq[wid] = sq; }
    __syncthreads();
    if (tid == 0) {
        float S = 0, Q = 0;
        #pragma unroll
        for (int i = 0; i < 8; i++) { S += rs[i]; Q += rq[i]; }
        float mu = S * (1.f / 768.f);
        float var = Q * (1.f / 768.f) - mu * mu;
        smu = mu; srs = rsqrtf(var + 1e-5f);
    }
    __syncthreads();
    float mu = smu, r = srs;
    #pragma unroll
    for (int p = 0; p < 3; p++) {
        int i = tid + p * 256;
        float vv = ((p == 0 ? v0 : p == 1 ? v1 : v2) - mu) * r * g[i] + b[i];
        g_a[ob + i] = __float2half_rn(vv);
    }
}

// ---------------- LayerNorm 2 (fp16 out) ----------------
__global__ __launch_bounds__(256) void ln2_kernel(const float* __restrict__ g,
                                                  const float* __restrict__ b)
{
    int tid = threadIdx.x;
    const float* row = g_x2 + (size_t)blockIdx.x * DIM;
    size_t ob = (size_t)blockIdx.x * DIM;
    float v0 = row[tid], v1 = row[tid + 256], v2 = row[tid + 512];
    float s = v0 + v1 + v2, sq = v0 * v0 + v1 * v1 + v2 * v2;
    #pragma unroll
    for (int off = 16; off; off >>= 1) {
        s  += __shfl_xor_sync(0xffffffffu, s, off);
        sq += __shfl_xor_sync(0xffffffffu, sq, off);
    }
    __shared__ float rs[8], rq[8], smu, srs;
    int wid = tid >> 5, lane = tid & 31;
    if (!lane) { rs[wid] = s; rq[wid] = sq; }
    __syncthreads();
    if (tid == 0) {
        float S = 0, Q = 0;
        #pragma unroll
        for (int i = 0; i < 8; i++) { S += rs[i]; Q += rq[i]; }
        float mu = S * (1.f / 768.f);
        float var = Q * (1.f / 768.f) - mu * mu;
        smu = mu; srs = rsqrtf(var + 1e-5f);
    }
    __syncthreads();
    float mu = smu, r = srs;
    #pragma unroll
    for (int p = 0; p < 3; p++) {
        int i = tid + p * 256;
        float vv = ((p == 0 ? v0 : p == 1 ? v1 : v2) - mu) * r * g[i] + b[i];
        g_b[ob + i] = __float2half_rn(vv);
    }
}

// ---------------- mma.sync GEMM: D[M,N] = A[M,K] x Wt[N,K]^T ----------------
// MODEs 0,1: B hi/lo (2 MMAs/step). MODEs 2,3: B hi only (1 MMA/step).
#define TG_MAT_B   10240

template <int MODE>
__global__ __launch_bounds__(256, 2) void tgemm_kernel(const float* __restrict__ bias,
                                                       const float* __restrict__ aux,
                                                       float* __restrict__ outp)
{
    constexpr int  K      = (MODE == 3) ? 3072 : 768;
    constexpr int  Mreal  = (MODE <= 1) ? TOKW : TOKX;
    constexpr int  NCHUNK = K / 32;
    constexpr bool BLO    = (MODE <= 1);
    constexpr int  NMATS  = BLO ? 3 : 2;
    constexpr int  STAGE  = NMATS * TG_MAT_B;
    const __half* gA  = (MODE == 0) ? g_a : (MODE == 1) ? g_ao : (MODE == 2) ? g_b : g_h1;
    const __half* gBh = (MODE == 0) ? g_wqkv_h : (MODE == 1) ? g_wproj_h : (MODE == 2) ? g_w1_h : g_w2_h;
    const __half* gBl = (MODE == 0) ? g_wqkv_l : g_wproj_l;

    extern __shared__ char smem_raw[];
    const uint32_t sbase = smem_u32(smem_raw);

    const int t = threadIdx.x;
    const int m0 = blockIdx.y * 128;
    const int n0 = blockIdx.x * 128;
    const int warp = t >> 5, lane = t & 31;
    const int wm = warp >> 2, wn = warp & 3;

    float acc[4][4][4];
    #pragma unroll
    for (int a = 0; a < 4; a++)
        #pragma unroll
        for (int b2 = 0; b2 < 4; b2++)
            #pragma unroll
            for (int c = 0; c < 4; c++) acc[a][b2][c] = 0.f;

    const int ldrow = t >> 2, ldseg = t & 3;
    const uint32_t sm_off0 = (uint32_t)(ldrow * 80 + ldseg * 16);
    const uint32_t sm_off1 = (uint32_t)((ldrow + 64) * 80 + ldseg * 16);

    auto issue = [&](int chunk, int stg) {
        const int k0 = chunk * 32;
        const uint32_t so = sbase + (uint32_t)(stg * STAGE);
        size_t ga0 = (size_t)(m0 + ldrow) * K + k0 + ldseg * 8;
        size_t ga1 = (size_t)(m0 + ldrow + 64) * K + k0 + ldseg * 8;
        size_t gb0 = (size_t)(n0 + ldrow) * K + k0 + ldseg * 8;
        size_t gb1 = (size_t)(n0 + ldrow + 64) * K + k0 + ldseg * 8;
        cp16(so + sm_off0, gA + ga0);
        cp16(so + sm_off1, gA + ga1);
        cp16(so + TG_MAT_B + sm_off0, gBh + gb0);
        cp16(so + TG_MAT_B + sm_off1, gBh + gb1);
        if (BLO) {
            cp16(so + 2 * TG_MAT_B + sm_off0, gBl + gb0);
            cp16(so + 2 * TG_MAT_B + sm_off1, gBl + gb1);
        }
        asm volatile("cp.async.commit_group;" ::: "memory");
    };

    issue(0, 0);
    issue(1, 1);

    const int a_row_in = (lane & 7) + (lane & 8);
    const int a_koff   = (lane >> 4) * 8;
    const int b_row_in = lane & 7;
    const int b_koff   = ((lane >> 3) & 1) * 8;

    for (int i = 0; i < NCHUNK; i++) {
        if (i + 1 < NCHUNK)
            asm volatile("cp.async.wait_group 1;" ::: "memory");
        else
            asm volatile("cp.async.wait_group 0;" ::: "memory");
        __syncthreads();
        if (i + 2 < NCHUNK) issue(i + 2, (i + 2) % 3);

        const uint32_t soA = sbase + (uint32_t)((i % 3) * STAGE);
        const uint32_t soB = soA + TG_MAT_B;
        #pragma unroll
        for (int ks = 0; ks < 2; ks++) {
            uint32_t bh[4][2], bl[4][2];
            #pragma unroll
            for (int nt = 0; nt < 4; nt++) {
                int nr = wn * 32 + nt * 8 + b_row_in;
                uint32_t bd = soB + (uint32_t)((nr * 40 + ks * 16 + b_koff) * 2);
                ldsm_x2(bh[nt], bd);
                if (BLO) ldsm_x2(bl[nt], bd + TG_MAT_B);
            }
            #pragma unroll
            for (int mt = 0; mt < 4; mt++) {
                uint32_t ah[4];
                int mr = wm * 64 + mt * 16 + a_row_in;
                uint32_t ad = soA + (uint32_t)((mr * 40 + ks * 16 + a_koff) * 2);
                ldsm_x4(ah, ad);
                #pragma unroll
                for (int nt = 0; nt < 4; nt++) {
                    mma_f16(acc[mt][nt], ah, bh[nt]);
                    if (BLO) mma_f16(acc[mt][nt], ah, bl[nt]);
                }
            }
        }
        // no trailing barrier: the barrier after wait_group orders stage reuse
    }

    // ---- epilogue ----
    const int g = lane >> 2, tq = lane & 3;
    #pragma unroll
    for (int mt = 0; mt < 4; mt++) {
        #pragma unroll
        for (int half = 0; half < 2; half++) {
            int m = m0 + wm * 64 + mt * 16 + g + half * 8;
            bool valid = (m < Mreal);
            int win = 0, tok = 0, yy = 0, xx = 0, bb = 0;
            if (MODE <= 1) {
                win = m / NTOK; tok = m - win * NTOK;
                if (MODE == 1) {
                    bb = win / NWIN; int rem = win - bb * NWIN;
                    yy = (rem / 5) * WS + tok / WS;
                    xx = (rem % 5) * WS + tok % WS;
                    valid = valid && (yy < 64) && (xx < 64);
                }
            }
            if (!valid) continue;
            #pragma unroll
            for (int nt = 0; nt < 4; nt++) {
                int n = n0 + wn * 32 + nt * 8 + 2 * tq;
                float v0 = acc[mt][nt][half * 2]     + bias[n];
                float v1 = acc[mt][nt][half * 2 + 1] + bias[n + 1];
                if (MODE == 0) {
                    int which = n / 768;
                    int dd = n - which * 768;
                    int head = dd >> 6, hd = dd & 63;
                    size_t o = ((size_t)(win * NHEAD + head) * NTOK + tok) * HDIM + hd;
                    if (which == 0) {
                        g_qh[o]     = __float2half_rn(v0 * 0.125f);
                        g_qh[o + 1] = __float2half_rn(v1 * 0.125f);
                    } else if (which == 1) {
                        g_kh[o]     = __float2half_rn(v0);
                        g_kh[o + 1] = __float2half_rn(v1);
                    } else {
                        g_vh[o]     = __float2half_rn(v0);
                        g_vh[o + 1] = __float2half_rn(v1);
                    }
                } else if (MODE == 1) {
                    size_t o = ((size_t)(bb * 64 + yy) * 64 + xx) * DIM + n;
                    g_x2[o]     = aux[o] + v0;
                    g_x2[o + 1] = aux[o + 1] + v1;
                } else if (MODE == 2) {
                    float gl0 = 0.5f * v0 * (1.f + erff(v0 * 0.70710678118f));
                    float gl1 = 0.5f * v1 * (1.f + erff(v1 * 0.70710678118f));
                    size_t o = (size_t)m * 3072 + n;
                    g_h1[o]     = __float2half_rn(gl0);
                    g_h1[o + 1] = __float2half_rn(gl1);
                } else {
                    size_t o = (size_t)m * DIM + n;
                    outp[o]     = v0 + g_x2[o];
                    outp[o + 1] = v1 + g_x2[o + 1];
                }
            }
        }
    }
}

// ---------------- tensor-core attention: one CTA (8 warps) per (window, head) ----------------
#define ATT_QS_H   0
#define ATT_KS_H   14976
#define ATT_VS_H   29376
#define ATT_F_OFF  88704
#define ATT_B_OFF  90528
#define SM_ATT_TOTAL 91328

__global__ __launch_bounds__(256) void attn_kernel(const float* __restrict__ rel_h,
                                                   const float* __restrict__ rel_w,
                                                   const int* __restrict__ q_idx,
                                                   const int* __restrict__ k_idx)
{
    extern __shared__ char smraw[];
    __half* qs  = (__half*)smraw;
    __half* ksm = qs + ATT_KS_H;
    __half* vsm = qs + ATT_VS_H;
    float* Shf  = (float*)(smraw + ATT_F_OFF);
    float* Swf  = Shf + 196;
    float* rshf = Swf + 196;
    float* rswf = rshf + 32;
    unsigned char* qr8 = (unsigned char*)(smraw + ATT_B_OFF);
    unsigned char* qc8 = qr8 + 196;
    unsigned char* kr8 = qc8 + 196;
    unsigned char* kc8 = kr8 + 196;

    const uint32_t sb = smem_u32(smraw);
    int bh = blockIdx.x;
    int win = bh / NHEAD, head = bh - win * NHEAD;
    int tid = threadIdx.x, warp = tid >> 5, lane = tid & 31;

    const __half* qg = g_qh + (size_t)bh * NTOK * HDIM;
    const __half* kg = g_kh + (size_t)bh * NTOK * HDIM;
    const __half* vg = g_vh + (size_t)bh * NTOK * HDIM;
    for (int i = tid; i < 196 * 8; i += 256) {
        int r = i >> 3, sg = i & 7;
        *(uint4*)(qs  + r * 72 + sg * 8) = *(const uint4*)(qg + r * 64 + sg * 8);
        *(uint4*)(ksm + r * 72 + sg * 8) = *(const uint4*)(kg + r * 64 + sg * 8);
        *(uint4*)(vsm + r * 72 + sg * 8) = *(const uint4*)(vg + r * 64 + sg * 8);
    }
    uint4 z = make_uint4(0, 0, 0, 0);
    for (int i = tid; i < 224; i += 256) {
        if (i < 96)       { int r = 196 + (i >> 3);        *(uint4*)(qs  + r * 72 + (i & 7) * 8) = z; }
        else if (i < 128) { int j = i - 96;  int r = 196 + (j >> 3); *(uint4*)(ksm + r * 72 + (j & 7) * 8) = z; }
        else              { int j = i - 128; int r = 196 + (j >> 3); *(uint4*)(vsm + r * 72 + (j & 7) * 8) = z; }
    }
    if (tid < 27) {
        const float* rp = rel_h + tid * HDIM;
        float s = 0;
        #pragma unroll 8
        for (int c = 0; c < HDIM; c++) s += rp[c];
        rshf[tid] = s;
    } else if (tid >= 32 && tid < 59) {
        const float* rp = rel_w + (tid - 32) * HDIM;
        float s = 0;
        #pragma unroll 8
        for (int c = 0; c < HDIM; c++) s += rp[c];
        rswf[tid - 32] = s;
    }
    if (tid < 196) {
        int qi = q_idx[(size_t)bh * NTOK + tid];
        int ki = k_idx[(size_t)bh * NTOK + tid];
        qr8[tid] = (unsigned char)(qi / WS);
        qc8[tid] = (unsigned char)(qi % WS);
        kr8[tid] = (unsigned char)(ki / WS);
        kc8[tid] = (unsigned char)(ki % WS);
    }
    __syncthreads();
    if (tid < 196) {
        int i = tid / WS, j = tid - i * WS;
        Shf[tid] = rshf[i - j + WS - 1];
        Swf[tid] = rswf[i - j + WS - 1];
    }
    __syncthreads();

    const int g = lane >> 2, tq = lane & 3;
    const int a_row_in = (lane & 7) + (lane & 8);
    const int a_koff   = (lane >> 4) * 8;
    const int b_row_in = lane & 7;
    const int b_koff   = ((lane >> 3) & 1) * 8;
    const uint32_t kbase = sb + ATT_KS_H * 2;
    const uint32_t vbase = sb + ATT_VS_H * 2;

    for (int mt = warp; mt < 13; mt += 8) {
        float sacc[25][4];
        #pragma unroll
        for (int nt = 0; nt < 25; nt++)
            #pragma unroll
            for (int c = 0; c < 4; c++) sacc[nt][c] = 0.f;

        #pragma unroll
        for (int kk = 0; kk < 4; kk++) {
            uint32_t af[4];
            uint32_t qa = sb + (uint32_t)(((mt * 16 + a_row_in) * 72 + kk * 16 + a_koff) * 2);
            ldsm_x4(af, qa);
            #pragma unroll
            for (int nt = 0; nt < 25; nt++) {
                uint32_t bf[2];
                uint32_t ka = kbase + (uint32_t)(((nt * 8 + b_row_in) * 72 + kk * 16 + b_koff) * 2);
                ldsm_x2(bf, ka);
                mma_f16(sacc[nt], af, bf);
            }
        }

        int row0 = mt * 16 + g;
        int row1 = row0 + 8;
        int qb0 = qr8[row0] * WS, qc0 = qc8[row0] * WS;
        int qb1 = qr8[row1] * WS, qc1 = qc8[row1] * WS;
        float mx0 = -1e30f, mx1 = -1e30f;
        #pragma unroll
        for (int nt = 0; nt < 25; nt++) {
            #pragma unroll
            for (int c = 0; c < 2; c++) {
                int col = nt * 8 + tq * 2 + c;
                float s0, s1;
                if (col < 196) {
                    int kr = kr8[col], kc = kc8[col];
                    s0 = sacc[nt][c]     + Shf[qb0 + kr] + Swf[qc0 + kc];
                    s1 = sacc[nt][2 + c] + Shf[qb1 + kr] + Swf[qc1 + kc];
                } else {
                    s0 = -1e30f; s1 = -1e30f;
                }
                sacc[nt][c] = s0; sacc[nt][2 + c] = s1;
                mx0 = fmaxf(mx0, s0); mx1 = fmaxf(mx1, s1);
            }
        }
        mx0 = fmaxf(mx0, __shfl_xor_sync(0xffffffffu, mx0, 1));
        mx0 = fmaxf(mx0, __shfl_xor_sync(0xffffffffu, mx0, 2));
        mx1 = fmaxf(mx1, __shfl_xor_sync(0xffffffffu, mx1, 1));
        mx1 = fmaxf(mx1, __shfl_xor_sync(0xffffffffu, mx1, 2));

        float sm0 = 0.f, sm1 = 0.f;
        uint32_t pf[13][4];
        #pragma unroll
        for (int nt = 0; nt < 25; nt++) {
            float e00 = expf(sacc[nt][0] - mx0);
            float e01 = expf(sacc[nt][1] - mx0);
            float e10 = expf(sacc[nt][2] - mx1);
            float e11 = expf(sacc[nt][3] - mx1);
            sm0 += e00 + e01;
            sm1 += e10 + e11;
            int kt = nt >> 1, hi = nt & 1;
            pf[kt][hi * 2 + 0] = packh2(e00, e01);
            pf[kt][hi * 2 + 1] = packh2(e10, e11);
        }
        pf[12][2] = 0u; pf[12][3] = 0u;
        sm0 += __shfl_xor_sync(0xffffffffu, sm0, 1);
        sm0 += __shfl_xor_sync(0xffffffffu, sm0, 2);
        sm1 += __shfl_xor_sync(0xffffffffu, sm1, 1);
        sm1 += __shfl_xor_sync(0xffffffffu, sm1, 2);
        float inv0 = 1.f / sm0, inv1 = 1.f / sm1;

        float oacc[8][4];
        #pragma unroll
        for (int dt = 0; dt < 8; dt++)
            #pragma unroll
            for (int c = 0; c < 4; c++) oacc[dt][c] = 0.f;
        #pragma unroll
        for (int kt = 0; kt < 13; kt++) {
            #pragma unroll
            for (int dt = 0; dt < 8; dt++) {
                uint32_t bf[2];
                uint32_t va = vbase + (uint32_t)(((kt * 16 + (lane & 15)) * 72 + dt * 8) * 2);
                ldsm_x2t(bf, va);
                mma_f16(oacc[dt], pf[kt], bf);
            }
        }

        bool ok0 = row0 < NTOK, ok1 = row1 < NTOK;
        size_t ob0 = ((size_t)(win * NTOK) + row0) * DIM + head * HDIM;
        #pragma unroll
        for (int dt = 0; dt < 8; dt++) {
            int d = dt * 8 + tq * 2;
            if (ok0) {
                __half2 hv = __floats2half2_rn(oacc[dt][0] * inv0, oacc[dt][1] * inv0);
                *(__half2*)(g_ao + ob0 + d) = hv;
            }
            if (ok1) {
                __half2 hv = __floats2half2_rn(oacc[dt][2] * inv1, oacc[dt][3] * inv1);
                *(__half2*)(g_ao + ob0 + (size_t)8 * DIM + d) = hv;
            }
        }
    }
}

// ---------------- launch ----------------
extern "C" void kernel_launch(void* const* d_in, const int* in_sizes, int n_in,
                              void* d_out, int out_size)
{
    const float* x     = (const float*)d_in[0];
    const int*   qidx  = (const int*)d_in[1];
    const int*   kidx  = (const int*)d_in[2];
    const float* ln1w  = (const float*)d_in[3];
    const float* ln1b  = (const float*)d_in[4];
    const float* ln2w  = (const float*)d_in[5];
    const float* ln2b  = (const float*)d_in[6];
    const float* qkvw  = (const float*)d_in[7];
    const float* qkvb  = (const float*)d_in[8];
    const float* projw = (const float*)d_in[9];
    const float* projb = (const float*)d_in[10];
    const float* relh  = (const float*)d_in[11];
    const float* relw  = (const float*)d_in[12];
    const float* w1    = (const float*)d_in[13];
    const float* b1    = (const float*)d_in[14];
    const float* w2    = (const float*)d_in[15];
    const float* b2    = (const float*)d_in[16];
    float* out = (float*)d_out;

    cudaFuncSetAttribute(attn_kernel, cudaFuncAttributeMaxDynamicSharedMemorySize, SM_ATT_TOTAL);
    cudaFuncSetAttribute(tgemm_kernel<0>, cudaFuncAttributeMaxDynamicSharedMemorySize, 3 * 3 * TG_MAT_B);
    cudaFuncSetAttribute(tgemm_kernel<1>, cudaFuncAttributeMaxDynamicSharedMemorySize, 3 * 3 * TG_MAT_B);
    cudaFuncSetAttribute(tgemm_kernel<2>, cudaFuncAttributeMaxDynamicSharedMemorySize, 3 * 2 * TG_MAT_B);
    cudaFuncSetAttribute(tgemm_kernel<3>, cudaFuncAttributeMaxDynamicSharedMemorySize, 3 * 2 * TG_MAT_B);

    __half *wqkv_h, *wqkv_l, *wproj_h, *wproj_l, *w1_h, *w2_h;
    cudaGetSymbolAddress((void**)&wqkv_h, g_wqkv_h);
    cudaGetSymbolAddress((void**)&wqkv_l, g_wqkv_l);
    cudaGetSymbolAddress((void**)&wproj_h, g_wproj_h);
    cudaGetSymbolAddress((void**)&wproj_l, g_wproj_l);
    cudaGetSymbolAddress((void**)&w1_h, g_w1_h);
    cudaGetSymbolAddress((void**)&w2_h, g_w2_h);

    // launch index 3 = tgemm<0> (ncu profiles it)
    wsplit_kernel<<<dim3(2304 / 32, 768 / 32), 256>>>(qkvw, wqkv_h, wqkv_l, 768, 2304);   // 0
    wsplit_kernel<<<dim3(3072 / 32, 768 / 32), 256>>>(w1, w1_h, nullptr, 768, 3072);       // 1
    ln1_kernel<<<TOKW, 256>>>(x, ln1w, ln1b);                                              // 2
    tgemm_kernel<0><<<dim3(2304 / 128, TOKW_PAD / 128), 256, 3 * 3 * TG_MAT_B>>>(qkvb, nullptr, nullptr); // 3
    attn_kernel<<<BH, 256, SM_ATT_TOTAL>>>(relh, relw, qidx, kidx);                        // 4
    wsplit_kernel<<<dim3(768 / 32, 768 / 32), 256>>>(projw, wproj_h, wproj_l, 768, 768);   // 5
    tgemm_kernel<1><<<dim3(768 / 128, TOKW_PAD / 128), 256, 3 * 3 * TG_MAT_B>>>(projb, x, nullptr); // 6
    ln2_kernel<<<TOKX, 256>>>(ln2w, ln2b);                                                 // 7
    wsplit_kernel<<<dim3(768 / 32, 3072 / 32), 256>>>(w2, w2_h, nullptr, 3072, 768);       // 8
    tgemm_kernel<2><<<dim3(3072 / 128, TOKX / 128), 256, 3 * 2 * TG_MAT_B>>>(b1, nullptr, nullptr); // 9
    tgemm_kernel<3><<<dim3(768 / 128, TOKX / 128), 256, 3 * 2 * TG_MAT_B>>>(b2, nullptr, out);      // 10
}

// round 12
// speedup vs baseline: 2.7570x; 1.1848x over previous
/*
 * R12: non-qkv GEMMs use K-chunk 64 + XOR-swizzled 128B smem rows (no pad,
 * 3-stage, halved barrier density); proj drops B-lo (1 MMA/step); B frags
 * loaded as paired ldmatrix.x4 everywhere. Attention unchanged.
 */
#include <cuda_runtime.h>
#include <cuda_fp16.h>
#include <math.h>
#include <stdint.h>

#define DIM   768
#define NHEAD 12
#define HDIM  64
#define WS    14
#define NTOK  196
#define NWIN  25
#define BATCH 8
#define NWB   200
#define TOKW  39200
#define TOKW_PAD 39296
#define TOKX  32768
#define BH    2400

// ---------------- device scratch ----------------
__device__ __half g_a[(size_t)TOKW_PAD * DIM];
__device__ __half g_ao[(size_t)TOKW_PAD * DIM];
__device__ __half g_b[(size_t)TOKX * DIM];
__device__ __half g_h1[(size_t)TOKX * 3072];
__device__ __half g_wqkv_h[(size_t)2304 * 768];
__device__ __half g_wqkv_l[(size_t)2304 * 768];
__device__ __half g_wproj_h[(size_t)768 * 768];
__device__ __half g_w1_h[(size_t)3072 * 768];
__device__ __half g_w2_h[(size_t)768 * 3072];
__device__ __half g_qh[(size_t)BH * NTOK * HDIM];
__device__ __half g_kh[(size_t)BH * NTOK * HDIM];
__device__ __half g_vh[(size_t)BH * NTOK * HDIM];
__device__ float g_x2[(size_t)TOKX * DIM];

// ---------------- PTX helpers ----------------
__device__ __forceinline__ uint32_t smem_u32(const void* p) {
    uint32_t a;
    asm("{ .reg .u64 t; cvta.to.shared.u64 t, %1; cvt.u32.u64 %0, t; }" : "=r"(a) : "l"(p));
    return a;
}
__device__ __forceinline__ void cp16(uint32_t dst, const void* src) {
    asm volatile("cp.async.cg.shared.global [%0], [%1], 16;" :: "r"(dst), "l"(src));
}
__device__ __forceinline__ void ldsm_x4(uint32_t* r, uint32_t addr) {
    asm volatile("ldmatrix.sync.aligned.m8n8.x4.shared.b16 {%0,%1,%2,%3}, [%4];"
        : "=r"(r[0]), "=r"(r[1]), "=r"(r[2]), "=r"(r[3]) : "r"(addr));
}
__device__ __forceinline__ void ldsm_x2(uint32_t* r, uint32_t addr) {
    asm volatile("ldmatrix.sync.aligned.m8n8.x2.shared.b16 {%0,%1}, [%2];"
        : "=r"(r[0]), "=r"(r[1]) : "r"(addr));
}
__device__ __forceinline__ void ldsm_x2t(uint32_t* r, uint32_t addr) {
    asm volatile("ldmatrix.sync.aligned.m8n8.x2.trans.shared.b16 {%0,%1}, [%2];"
        : "=r"(r[0]), "=r"(r[1]) : "r"(addr));
}
__device__ __forceinline__ void mma_f16(float* c, const uint32_t* a, const uint32_t* b) {
    asm volatile(
        "mma.sync.aligned.m16n8k16.row.col.f32.f16.f16.f32 "
        "{%0,%1,%2,%3}, {%4,%5,%6,%7}, {%8,%9}, {%0,%1,%2,%3};"
        : "+f"(c[0]), "+f"(c[1]), "+f"(c[2]), "+f"(c[3])
        : "r"(a[0]), "r"(a[1]), "r"(a[2]), "r"(a[3]), "r"(b[0]), "r"(b[1]));
}
__device__ __forceinline__ void f16split(float v, __half& h, __half& l) {
    h = __float2half_rn(v);
    l = __float2half_rn(v - __half2float(h));
}
__device__ __forceinline__ uint32_t packh2(float a, float b) {
    __half2 h = __floats2half2_rn(a, b);
    return *(uint32_t*)&h;
}

// ---------------- weight transpose + fp16 split: W[K,N] -> Wt_h(/l)[N,K] ----------------
__global__ __launch_bounds__(256) void wsplit_kernel(const float* __restrict__ W,
                                                     __half* __restrict__ Wh,
                                                     __half* __restrict__ Wl,
                                                     int K, int N)
{
    __shared__ float tile[32][33];
    int k0 = blockIdx.y * 32, n0 = blockIdx.x * 32;
    int tx = threadIdx.x & 31, ty = threadIdx.x >> 5;
    #pragma unroll
    for (int j = 0; j < 32; j += 8)
        tile[ty + j][tx] = W[(size_t)(k0 + ty + j) * N + n0 + tx];
    __syncthreads();
    #pragma unroll
    for (int j = 0; j < 32; j += 8) {
        float v = tile[tx][ty + j];
        __half h, l;
        f16split(v, h, l);
        size_t o = (size_t)(n0 + ty + j) * K + k0 + tx;
        Wh[o] = h;
        if (Wl) Wl[o] = l;
    }
}

// ---------------- LayerNorm 1 (window partition + pad, fp16 out) ----------------
__global__ __launch_bounds__(256) void ln1_kernel(const float* __restrict__ x,
                                                  const float* __restrict__ g,
                                                  const float* __restrict__ b)
{
    int widx = blockIdx.x;
    int win = widx / NTOK, tok = widx - win * NTOK;
    int bb = win / NWIN, rem = win - bb * NWIN;
    int y = (rem / 5) * WS + tok / WS;
    int xx = (rem % 5) * WS + tok % WS;
    size_t ob = (size_t)widx * DIM;
    int tid = threadIdx.x;
    if (y >= 64 || xx >= 64) {
        for (int i = tid; i < DIM; i += 256) g_a[ob + i] = __float2half(0.f);
        return;
    }
    const float* row = x + ((size_t)(bb * 64 + y) * 64 + xx) * DIM;
    float v0 = row[tid], v1 = row[tid + 256], v2 = row[tid + 512];
    float s = v0 + v1 + v2, sq = v0 * v0 + v1 * v1 + v2 * v2;
    #pragma unroll
    for (int off = 16; off; off >>= 1) {
        s  += __shfl_xor_sync(0xffffffffu, s, off);
        sq += __shfl_xor_sync(0xffffffffu, sq, off);
    }
    __shared__ float rs[8], rq[8], smu, srs;
    int wid = tid >> 5, lane = tid & 31;
    if (!lane) { rs[wid] = s; rq[wid] = sq; }
    __syncthreads();
    if (tid == 0) {
        float S = 0, Q = 0;
        #pragma unroll
        for (int i = 0; i < 8; i++) { S += rs[i]; Q += rq[i]; }
        float mu = S * (1.f / 768.f);
        float var = Q * (1.f / 768.f) - mu * mu;
        smu = mu; srs = rsqrtf(var + 1e-5f);
    }
    __syncthreads();
    float mu = smu, r = srs;
    #pragma unroll
    for (int p = 0; p < 3; p++) {
        int i = tid + p * 256;
        float vv = ((p == 0 ? v0 : p == 1 ? v1 : v2) - mu) * r * g[i] + b[i];
        g_a[ob + i] = __float2half_rn(vv);
    }
}

// ---------------- LayerNorm 2 (fp16 out) ----------------
__global__ __launch_bounds__(256) void ln2_kernel(const float* __restrict__ g,
                                                  const float* __restrict__ b)
{
    int tid = threadIdx.x;
    const float* row = g_x2 + (size_t)blockIdx.x * DIM;
    size_t ob = (size_t)blockIdx.x * DIM;
    float v0 = row[tid], v1 = row[tid + 256], v2 = row[tid + 512];
    float s = v0 + v1 + v2, sq = v0 * v0 + v1 * v1 + v2 * v2;
    #pragma unroll
    for (int off = 16; off; off >>= 1) {
        s  += __shfl_xor_sync(0xffffffffu, s, off);
        sq += __shfl_xor_sync(0xffffffffu, sq, off);
    }
    __shared__ float rs[8], rq[8], smu, srs;
    int wid = tid >> 5, lane = tid & 31;
    if (!lane) { rs[wid] = s; rq[wid] = sq; }
    __syncthreads();
    if (tid == 0) {
        float S = 0, Q = 0;
        #pragma unroll
        for (int i = 0; i < 8; i++) { S += rs[i]; Q += rq[i]; }
        float mu = S * (1.f / 768.f);
        float var = Q * (1.f / 768.f) - mu * mu;
        smu = mu; srs = rsqrtf(var + 1e-5f);
    }
    __syncthreads();
    float mu = smu, r = srs;
    #pragma unroll
    for (int p = 0; p < 3; p++) {
        int i = tid + p * 256;
        float vv = ((p == 0 ? v0 : p == 1 ? v1 : v2) - mu) * r * g[i] + b[i];
        g_b[ob + i] = __float2half_rn(vv);
    }
}

// ---------------- mma.sync GEMM: D[M,N] = A[M,K] x Wt[N,K]^T ----------------
// MODE 0 (qkv): B hi/lo, K-chunk 32, padded rows (80B), 3 stages.
// MODEs 1-3:    B hi only, K-chunk 64, swizzled 128B rows, 3 stages.
template <int MODE>
__global__ __launch_bounds__(256, 2) void tgemm_kernel(const float* __restrict__ bias,
                                                       const float* __restrict__ aux,
                                                       float* __restrict__ outp)
{
    constexpr int  K      = (MODE == 3) ? 3072 : 768;
    constexpr int  Mreal  = (MODE <= 1) ? TOKW : TOKX;
    constexpr bool BLO    = (MODE == 0);
    constexpr int  KCH    = BLO ? 32 : 64;
    constexpr int  KS     = KCH / 16;
    constexpr int  ROWB   = BLO ? 80 : 128;
    constexpr int  MATB   = 128 * ROWB;
    constexpr int  NMATS  = BLO ? 3 : 2;
    constexpr int  STAGE  = NMATS * MATB;
    constexpr int  NCHUNK = K / KCH;
    constexpr int  SEGS   = (KCH * 2) / 16;   // 16B segments per row: 4 or 8
    constexpr int  RPP    = 256 / SEGS;       // rows per cp pass: 64 or 32
    constexpr int  NPASS  = 128 / RPP;        // 2 or 4

    const __half* gA  = (MODE == 0) ? g_a : (MODE == 1) ? g_ao : (MODE == 2) ? g_b : g_h1;
    const __half* gBh = (MODE == 0) ? g_wqkv_h : (MODE == 1) ? g_wproj_h : (MODE == 2) ? g_w1_h : g_w2_h;
    const __half* gBl = g_wqkv_l;   // MODE 0 only

    extern __shared__ char smem_raw[];
    const uint32_t sbase = smem_u32(smem_raw);

    const int t = threadIdx.x;
    const int m0 = blockIdx.y * 128;
    const int n0 = blockIdx.x * 128;
    const int warp = t >> 5, lane = t & 31;
    const int wm = warp >> 2, wn = warp & 3;

    float acc[4][4][4];
    #pragma unroll
    for (int a = 0; a < 4; a++)
        #pragma unroll
        for (int b2 = 0; b2 < 4; b2++)
            #pragma unroll
            for (int c = 0; c < 4; c++) acc[a][b2][c] = 0.f;

    const int ldrow = t / SEGS, ldseg = t % SEGS;

    auto issue = [&](int chunk, int stg) {
        const int k0 = chunk * KCH;
        const uint32_t so = sbase + (uint32_t)(stg * STAGE);
        #pragma unroll
        for (int p = 0; p < NPASS; p++) {
            int r = ldrow + p * RPP;
            uint32_t off;
            if (BLO) off = (uint32_t)(r * ROWB + ldseg * 16);
            else     off = (uint32_t)(r * 128 + ((ldseg ^ (r & 7)) << 4));
            size_t gaA = (size_t)(m0 + r) * K + k0 + ldseg * 8;
            size_t gaB = (size_t)(n0 + r) * K + k0 + ldseg * 8;
            cp16(so + off, gA + gaA);
            cp16(so + MATB + off, gBh + gaB);
            if (BLO) cp16(so + 2 * MATB + off, gBl + gaB);
        }
        asm volatile("cp.async.commit_group;" ::: "memory");
    };

    issue(0, 0);
    issue(1, 1);

    const int a_row_in = (lane & 7) + (lane & 8);   // 0..15
    const int a_kg     = lane >> 4;                 // 0/1 (8-half granule)
    const int b_row16  = (lane & 7) + ((lane >> 4) << 3);  // 0..15
    const int b_kg     = (lane >> 3) & 1;

    for (int i = 0; i < NCHUNK; i++) {
        if (i + 1 < NCHUNK)
            asm volatile("cp.async.wait_group 1;" ::: "memory");
        else
            asm volatile("cp.async.wait_group 0;" ::: "memory");
        __syncthreads();
        if (i + 2 < NCHUNK) issue(i + 2, (i + 2) % 3);

        const uint32_t soA = sbase + (uint32_t)((i % 3) * STAGE);
        const uint32_t soB = soA + MATB;
        #pragma unroll
        for (int ks = 0; ks < KS; ks++) {
            uint32_t bh[4][2], bl[4][2];
            #pragma unroll
            for (int pr = 0; pr < 2; pr++) {
                int nr = wn * 32 + pr * 16 + b_row16;
                uint32_t bd;
                if (BLO) bd = soB + (uint32_t)(nr * ROWB + (ks * 16 + b_kg * 8) * 2);
                else     bd = soB + (uint32_t)(nr * 128 + (((ks * 2 + b_kg) ^ (nr & 7)) << 4));
                uint32_t r4[4];
                ldsm_x4(r4, bd);
                bh[2 * pr][0] = r4[0]; bh[2 * pr][1] = r4[1];
                bh[2 * pr + 1][0] = r4[2]; bh[2 * pr + 1][1] = r4[3];
                if (BLO) {
                    ldsm_x4(r4, bd + MATB);
                    bl[2 * pr][0] = r4[0]; bl[2 * pr][1] = r4[1];
                    bl[2 * pr + 1][0] = r4[2]; bl[2 * pr + 1][1] = r4[3];
                }
            }
            #pragma unroll
            for (int mt = 0; mt < 4; mt++) {
                uint32_t ah[4];
                int mr = wm * 64 + mt * 16 + a_row_in;
                uint32_t ad;
                if (BLO) ad = soA + (uint32_t)(mr * ROWB + (ks * 16 + a_kg * 8) * 2);
                else     ad = soA + (uint32_t)(mr * 128 + (((ks * 2 + a_kg) ^ (mr & 7)) << 4));
                ldsm_x4(ah, ad);
                #pragma unroll
                for (int nt = 0; nt < 4; nt++) {
                    mma_f16(acc[mt][nt], ah, bh[nt]);
                    if (BLO) mma_f16(acc[mt][nt], ah, bl[nt]);
                }
            }
        }
    }

    // ---- epilogue ----
    const int g = lane >> 2, tq = lane & 3;
    #pragma unroll
    for (int mt = 0; mt < 4; mt++) {
        #pragma unroll
        for (int half = 0; half < 2; half++) {
            int m = m0 + wm * 64 + mt * 16 + g + half * 8;
            bool valid = (m < Mreal);
            int win = 0, tok = 0, yy = 0, xx = 0, bb = 0;
            if (MODE <= 1) {
                win = m / NTOK; tok = m - win * NTOK;
                if (MODE == 1) {
                    bb = win / NWIN; int rem = win - bb * NWIN;
                    yy = (rem / 5) * WS + tok / WS;
                    xx = (rem % 5) * WS + tok % WS;
                    valid = valid && (yy < 64) && (xx < 64);
                }
            }
            if (!valid) continue;
            #pragma unroll
            for (int nt = 0; nt < 4; nt++) {
                int n = n0 + wn * 32 + nt * 8 + 2 * tq;
                float v0 = acc[mt][nt][half * 2]     + bias[n];
                float v1 = acc[mt][nt][half * 2 + 1] + bias[n + 1];
                if (MODE == 0) {
                    int which = n / 768;
                    int dd = n - which * 768;
                    int head = dd >> 6, hd = dd & 63;
                    size_t o = ((size_t)(win * NHEAD + head) * NTOK + tok) * HDIM + hd;
                    if (which == 0) {
                        g_qh[o]     = __float2half_rn(v0 * 0.125f);
                        g_qh[o + 1] = __float2half_rn(v1 * 0.125f);
                    } else if (which == 1) {
                        g_kh[o]     = __float2half_rn(v0);
                        g_kh[o + 1] = __float2half_rn(v1);
                    } else {
                        g_vh[o]     = __float2half_rn(v0);
                        g_vh[o + 1] = __float2half_rn(v1);
                    }
                } else if (MODE == 1) {
                    size_t o = ((size_t)(bb * 64 + yy) * 64 + xx) * DIM + n;
                    g_x2[o]     = aux[o] + v0;
                    g_x2[o + 1] = aux[o + 1] + v1;
                } else if (MODE == 2) {
                    float gl0 = 0.5f * v0 * (1.f + erff(v0 * 0.70710678118f));
                    float gl1 = 0.5f * v1 * (1.f + erff(v1 * 0.70710678118f));
                    size_t o = (size_t)m * 3072 + n;
                    g_h1[o]     = __float2half_rn(gl0);
                    g_h1[o + 1] = __float2half_rn(gl1);
                } else {
                    size_t o = (size_t)m * DIM + n;
                    outp[o]     = v0 + g_x2[o];
                    outp[o + 1] = v1 + g_x2[o + 1];
                }
            }
        }
    }
}

// ---------------- tensor-core attention: one CTA (8 warps) per (window, head) ----------------
#define ATT_QS_H   0
#define ATT_KS_H   14976
#define ATT_VS_H   29376
#define ATT_F_OFF  88704
#define ATT_B_OFF  90528
#define SM_ATT_TOTAL 91328

__global__ __launch_bounds__(256) void attn_kernel(const float* __restrict__ rel_h,
                                                   const float* __restrict__ rel_w,
                                                   const int* __restrict__ q_idx,
                                                   const int* __restrict__ k_idx)
{
    extern __shared__ char smraw[];
    __half* qs  = (__half*)smraw;
    __half* ksm = qs + ATT_KS_H;
    __half* vsm = qs + ATT_VS_H;
    float* Shf  = (float*)(smraw + ATT_F_OFF);
    float* Swf  = Shf + 196;
    float* rshf = Swf + 196;
    float* rswf = rshf + 32;
    unsigned char* qr8 = (unsigned char*)(smraw + ATT_B_OFF);
    unsigned char* qc8 = qr8 + 196;
    unsigned char* kr8 = qc8 + 196;
    unsigned char* kc8 = kr8 + 196;

    const uint32_t sb = smem_u32(smraw);
    int bh = blockIdx.x;
    int win = bh / NHEAD, head = bh - win * NHEAD;
    int tid = threadIdx.x, warp = tid >> 5, lane = tid & 31;

    const __half* qg = g_qh + (size_t)bh * NTOK * HDIM;
    const __half* kg = g_kh + (size_t)bh * NTOK * HDIM;
    const __half* vg = g_vh + (size_t)bh * NTOK * HDIM;
    for (int i = tid; i < 196 * 8; i += 256) {
        int r = i >> 3, sg = i & 7;
        *(uint4*)(qs  + r * 72 + sg * 8) = *(const uint4*)(qg + r * 64 + sg * 8);
        *(uint4*)(ksm + r * 72 + sg * 8) = *(const uint4*)(kg + r * 64 + sg * 8);
        *(uint4*)(vsm + r * 72 + sg * 8) = *(const uint4*)(vg + r * 64 + sg * 8);
    }
    uint4 z = make_uint4(0, 0, 0, 0);
    for (int i = tid; i < 224; i += 256) {
        if (i < 96)       { int r = 196 + (i >> 3);        *(uint4*)(qs  + r * 72 + (i & 7) * 8) = z; }
        else if (i < 128) { int j = i - 96;  int r = 196 + (j >> 3); *(uint4*)(ksm + r * 72 + (j & 7) * 8) = z; }
        else              { int j = i - 128; int r = 196 + (j >> 3); *(uint4*)(vsm + r * 72 + (j & 7) * 8) = z; }
    }
    if (tid < 27) {
        const float* rp = rel_h + tid * HDIM;
        float s = 0;
        #pragma unroll 8
        for (int c = 0; c < HDIM; c++) s += rp[c];
        rshf[tid] = s;
    } else if (tid >= 32 && tid < 59) {
        const float* rp = rel_w + (tid - 32) * HDIM;
        float s = 0;
        #pragma unroll 8
        for (int c = 0; c < HDIM; c++) s += rp[c];
        rswf[tid - 32] = s;
    }
    if (tid < 196) {
        int qi = q_idx[(size_t)bh * NTOK + tid];
        int ki = k_idx[(size_t)bh * NTOK + tid];
        qr8[tid] = (unsigned char)(qi / WS);
        qc8[tid] = (unsigned char)(qi % WS);
        kr8[tid] = (unsigned char)(ki / WS);
        kc8[tid] = (unsigned char)(ki % WS);
    }
    __syncthreads();
    if (tid < 196) {
        int i = tid / WS, j = tid - i * WS;
        Shf[tid] = rshf[i - j + WS - 1];
        Swf[tid] = rswf[i - j + WS - 1];
    }
    __syncthreads();

    const int g = lane >> 2, tq = lane & 3;
    const int a_row_in = (lane & 7) + (lane & 8);
    const int a_koff   = (lane >> 4) * 8;
    const int b_row_in = lane & 7;
    const int b_koff   = ((lane >> 3) & 1) * 8;
    const uint32_t kbase = sb + ATT_KS_H * 2;
    const uint32_t vbase = sb + ATT_VS_H * 2;

    for (int mt = warp; mt < 13; mt += 8) {
        float sacc[25][4];
        #pragma unroll
        for (int nt = 0; nt < 25; nt++)
            #pragma unroll
            for (int c = 0; c < 4; c++) sacc[nt][c] = 0.f;

        #pragma unroll
        for (int kk = 0; kk < 4; kk++) {
            uint32_t af[4];
            uint32_t qa = sb + (uint32_t)(((mt * 16 + a_row_in) * 72 + kk * 16 + a_koff) * 2);
            ldsm_x4(af, qa);
            #pragma unroll
            for (int nt = 0; nt < 25; nt++) {
                uint32_t bf[2];
                uint32_t ka = kbase + (uint32_t)(((nt * 8 + b_row_in) * 72 + kk * 16 + b_koff) * 2);
                ldsm_x2(bf, ka);
                mma_f16(sacc[nt], af, bf);
            }
        }

        int row0 = mt * 16 + g;
        int row1 = row0 + 8;
        int qb0 = qr8[row0] * WS, qc0 = qc8[row0] * WS;
        int qb1 = qr8[row1] * WS, qc1 = qc8[row1] * WS;
        float mx0 = -1e30f, mx1 = -1e30f;
        #pragma unroll
        for (int nt = 0; nt < 25; nt++) {
            #pragma unroll
            for (int c = 0; c < 2; c++) {
                int col = nt * 8 + tq * 2 + c;
                float s0, s1;
                if (col < 196) {
                    int kr = kr8[col], kc = kc8[col];
                    s0 = sacc[nt][c]     + Shf[qb0 + kr] + Swf[qc0 + kc];
                    s1 = sacc[nt][2 + c] + Shf[qb1 + kr] + Swf[qc1 + kc];
                } else {
                    s0 = -1e30f; s1 = -1e30f;
                }
                sacc[nt][c] = s0; sacc[nt][2 + c] = s1;
                mx0 = fmaxf(mx0, s0); mx1 = fmaxf(mx1, s1);
            }
        }
        mx0 = fmaxf(mx0, __shfl_xor_sync(0xffffffffu, mx0, 1));
        mx0 = fmaxf(mx0, __shfl_xor_sync(0xffffffffu, mx0, 2));
        mx1 = fmaxf(mx1, __shfl_xor_sync(0xffffffffu, mx1, 1));
        mx1 = fmaxf(mx1, __shfl_xor_sync(0xffffffffu, mx1, 2));

        float sm0 = 0.f, sm1 = 0.f;
        uint32_t pf[13][4];
        #pragma unroll
        for (int nt = 0; nt < 25; nt++) {
            float e00 = expf(sacc[nt][0] - mx0);
            float e01 = expf(sacc[nt][1] - mx0);
            float e10 = expf(sacc[nt][2] - mx1);
            float e11 = expf(sacc[nt][3] - mx1);
            sm0 += e00 + e01;
            sm1 += e10 + e11;
            int kt = nt >> 1, hi = nt & 1;
            pf[kt][hi * 2 + 0] = packh2(e00, e01);
            pf[kt][hi * 2 + 1] = packh2(e10, e11);
        }
        pf[12][2] = 0u; pf[12][3] = 0u;
        sm0 += __shfl_xor_sync(0xffffffffu, sm0, 1);
        sm0 += __shfl_xor_sync(0xffffffffu, sm0, 2);
        sm1 += __shfl_xor_sync(0xffffffffu, sm1, 1);
        sm1 += __shfl_xor_sync(0xffffffffu, sm1, 2);
        float inv0 = 1.f / sm0, inv1 = 1.f / sm1;

        float oacc[8][4];
        #pragma unroll
        for (int dt = 0; dt < 8; dt++)
            #pragma unroll
            for (int c = 0; c < 4; c++) oacc[dt][c] = 0.f;
        #pragma unroll
        for (int kt = 0; kt < 13; kt++) {
            #pragma unroll
            for (int dt = 0; dt < 8; dt++) {
                uint32_t bf[2];
                uint32_t va = vbase + (uint32_t)(((kt * 16 + (lane & 15)) * 72 + dt * 8) * 2);
                ldsm_x2t(bf, va);
                mma_f16(oacc[dt], pf[kt], bf);
            }
        }

        bool ok0 = row0 < NTOK, ok1 = row1 < NTOK;
        size_t ob0 = ((size_t)(win * NTOK) + row0) * DIM + head * HDIM;
        #pragma unroll
        for (int dt = 0; dt < 8; dt++) {
            int d = dt * 8 + tq * 2;
            if (ok0) {
                __half2 hv = __floats2half2_rn(oacc[dt][0] * inv0, oacc[dt][1] * inv0);
                *(__half2*)(g_ao + ob0 + d) = hv;
            }
            if (ok1) {
                __half2 hv = __floats2half2_rn(oacc[dt][2] * inv1, oacc[dt][3] * inv1);
                *(__half2*)(g_ao + ob0 + (size_t)8 * DIM + d) = hv;
            }
        }
    }
}

// ---------------- launch ----------------
#define SMEM_TG0 (3 * 3 * 10240)
#define SMEM_TGX (3 * 2 * 16384)

extern "C" void kernel_launch(void* const* d_in, const int* in_sizes, int n_in,
                              void* d_out, int out_size)
{
    const float* x     = (const float*)d_in[0];
    const int*   qidx  = (const int*)d_in[1];
    const int*   kidx  = (const int*)d_in[2];
    const float* ln1w  = (const float*)d_in[3];
    const float* ln1b  = (const float*)d_in[4];
    const float* ln2w  = (const float*)d_in[5];
    const float* ln2b  = (const float*)d_in[6];
    const float* qkvw  = (const float*)d_in[7];
    const float* qkvb  = (const float*)d_in[8];
    const float* projw = (const float*)d_in[9];
    const float* projb = (const float*)d_in[10];
    const float* relh  = (const float*)d_in[11];
    const float* relw  = (const float*)d_in[12];
    const float* w1    = (const float*)d_in[13];
    const float* b1    = (const float*)d_in[14];
    const float* w2    = (const float*)d_in[15];
    const float* b2    = (const float*)d_in[16];
    float* out = (float*)d_out;

    cudaFuncSetAttribute(attn_kernel, cudaFuncAttributeMaxDynamicSharedMemorySize, SM_ATT_TOTAL);
    cudaFuncSetAttribute(tgemm_kernel<0>, cudaFuncAttributeMaxDynamicSharedMemorySize, SMEM_TG0);
    cudaFuncSetAttribute(tgemm_kernel<1>, cudaFuncAttributeMaxDynamicSharedMemorySize, SMEM_TGX);
    cudaFuncSetAttribute(tgemm_kernel<2>, cudaFuncAttributeMaxDynamicSharedMemorySize, SMEM_TGX);
    cudaFuncSetAttribute(tgemm_kernel<3>, cudaFuncAttributeMaxDynamicSharedMemorySize, SMEM_TGX);

    __half *wqkv_h, *wqkv_l, *wproj_h, *w1_h, *w2_h;
    cudaGetSymbolAddress((void**)&wqkv_h, g_wqkv_h);
    cudaGetSymbolAddress((void**)&wqkv_l, g_wqkv_l);
    cudaGetSymbolAddress((void**)&wproj_h, g_wproj_h);
    cudaGetSymbolAddress((void**)&w1_h, g_w1_h);
    cudaGetSymbolAddress((void**)&w2_h, g_w2_h);

    // launch index 3 = tgemm<0> (ncu profiles it)
    wsplit_kernel<<<dim3(2304 / 32, 768 / 32), 256>>>(qkvw, wqkv_h, wqkv_l, 768, 2304);   // 0
    wsplit_kernel<<<dim3(3072 / 32, 768 / 32), 256>>>(w1, w1_h, nullptr, 768, 3072);       // 1
    ln1_kernel<<<TOKW, 256>>>(x, ln1w, ln1b);                                              // 2
    tgemm_kernel<0><<<dim3(2304 / 128, TOKW_PAD / 128), 256, SMEM_TG0>>>(qkvb, nullptr, nullptr); // 3
    attn_kernel<<<BH, 256, SM_ATT_TOTAL>>>(relh, relw, qidx, kidx);                        // 4
    wsplit_kernel<<<dim3(768 / 32, 768 / 32), 256>>>(projw, wproj_h, nullptr, 768, 768);   // 5
    tgemm_kernel<1><<<dim3(768 / 128, TOKW_PAD / 128), 256, SMEM_TGX>>>(projb, x, nullptr); // 6
    ln2_kernel<<<TOKX, 256>>>(ln2w, ln2b);                                                 // 7
    wsplit_kernel<<<dim3(768 / 32, 3072 / 32), 256>>>(w2, w2_h, nullptr, 3072, 768);       // 8
    tgemm_kernel<2><<<dim3(3072 / 128, TOKX / 128), 256, SMEM_TGX>>>(b1, nullptr, nullptr); // 9
    tgemm_kernel<3><<<dim3(768 / 128, TOKX / 128), 256, SMEM_TGX>>>(b2, nullptr, out);      // 10
}

// round 13
// speedup vs baseline: 3.2837x; 1.1911x over previous
/*
 * R13: ALL GEMMs uniform: A single fp16 x B hi fp16, 1 MMA/step, K-chunk 64,
 * XOR-swizzled 128B rows, 3-stage cp.async, 2 CTAs/SM. qkv B-lo dropped
 * (fp16 q/k/v storage rounding already dominates). Attention unchanged.
 */
#include <cuda_runtime.h>
#include <cuda_fp16.h>
#include <math.h>
#include <stdint.h>

#define DIM   768
#define NHEAD 12
#define HDIM  64
#define WS    14
#define NTOK  196
#define NWIN  25
#define BATCH 8
#define NWB   200
#define TOKW  39200
#define TOKW_PAD 39296
#define TOKX  32768
#define BH    2400

// ---------------- device scratch ----------------
__device__ __half g_a[(size_t)TOKW_PAD * DIM];
__device__ __half g_ao[(size_t)TOKW_PAD * DIM];
__device__ __half g_b[(size_t)TOKX * DIM];
__device__ __half g_h1[(size_t)TOKX * 3072];
__device__ __half g_wqkv_h[(size_t)2304 * 768];
__device__ __half g_wproj_h[(size_t)768 * 768];
__device__ __half g_w1_h[(size_t)3072 * 768];
__device__ __half g_w2_h[(size_t)768 * 3072];
__device__ __half g_qh[(size_t)BH * NTOK * HDIM];
__device__ __half g_kh[(size_t)BH * NTOK * HDIM];
__device__ __half g_vh[(size_t)BH * NTOK * HDIM];
__device__ float g_x2[(size_t)TOKX * DIM];

// ---------------- PTX helpers ----------------
__device__ __forceinline__ uint32_t smem_u32(const void* p) {
    uint32_t a;
    asm("{ .reg .u64 t; cvta.to.shared.u64 t, %1; cvt.u32.u64 %0, t; }" : "=r"(a) : "l"(p));
    return a;
}
__device__ __forceinline__ void cp16(uint32_t dst, const void* src) {
    asm volatile("cp.async.cg.shared.global [%0], [%1], 16;" :: "r"(dst), "l"(src));
}
__device__ __forceinline__ void ldsm_x4(uint32_t* r, uint32_t addr) {
    asm volatile("ldmatrix.sync.aligned.m8n8.x4.shared.b16 {%0,%1,%2,%3}, [%4];"
        : "=r"(r[0]), "=r"(r[1]), "=r"(r[2]), "=r"(r[3]) : "r"(addr));
}
__device__ __forceinline__ void ldsm_x2(uint32_t* r, uint32_t addr) {
    asm volatile("ldmatrix.sync.aligned.m8n8.x2.shared.b16 {%0,%1}, [%2];"
        : "=r"(r[0]), "=r"(r[1]) : "r"(addr));
}
__device__ __forceinline__ void ldsm_x2t(uint32_t* r, uint32_t addr) {
    asm volatile("ldmatrix.sync.aligned.m8n8.x2.trans.shared.b16 {%0,%1}, [%2];"
        : "=r"(r[0]), "=r"(r[1]) : "r"(addr));
}
__device__ __forceinline__ void mma_f16(float* c, const uint32_t* a, const uint32_t* b) {
    asm volatile(
        "mma.sync.aligned.m16n8k16.row.col.f32.f16.f16.f32 "
        "{%0,%1,%2,%3}, {%4,%5,%6,%7}, {%8,%9}, {%0,%1,%2,%3};"
        : "+f"(c[0]), "+f"(c[1]), "+f"(c[2]), "+f"(c[3])
        : "r"(a[0]), "r"(a[1]), "r"(a[2]), "r"(a[3]), "r"(b[0]), "r"(b[1]));
}
__device__ __forceinline__ uint32_t packh2(float a, float b) {
    __half2 h = __floats2half2_rn(a, b);
    return *(uint32_t*)&h;
}

// ---------------- weight transpose + fp16: W[K,N] -> Wt[N,K] ----------------
__global__ __launch_bounds__(256) void wsplit_kernel(const float* __restrict__ W,
                                                     __half* __restrict__ Wh,
                                                     int K, int N)
{
    __shared__ float tile[32][33];
    int k0 = blockIdx.y * 32, n0 = blockIdx.x * 32;
    int tx = threadIdx.x & 31, ty = threadIdx.x >> 5;
    #pragma unroll
    for (int j = 0; j < 32; j += 8)
        tile[ty + j][tx] = W[(size_t)(k0 + ty + j) * N + n0 + tx];
    __syncthreads();
    #pragma unroll
    for (int j = 0; j < 32; j += 8) {
        Wh[(size_t)(n0 + ty + j) * K + k0 + tx] = __float2half_rn(tile[tx][ty + j]);
    }
}

// ---------------- LayerNorm 1 (window partition + pad, fp16 out) ----------------
__global__ __launch_bounds__(256) void ln1_kernel(const float* __restrict__ x,
                                                  const float* __restrict__ g,
                                                  const float* __restrict__ b)
{
    int widx = blockIdx.x;
    int win = widx / NTOK, tok = widx - win * NTOK;
    int bb = win / NWIN, rem = win - bb * NWIN;
    int y = (rem / 5) * WS + tok / WS;
    int xx = (rem % 5) * WS + tok % WS;
    size_t ob = (size_t)widx * DIM;
    int tid = threadIdx.x;
    if (y >= 64 || xx >= 64) {
        for (int i = tid; i < DIM; i += 256) g_a[ob + i] = __float2half(0.f);
        return;
    }
    const float* row = x + ((size_t)(bb * 64 + y) * 64 + xx) * DIM;
    float v0 = row[tid], v1 = row[tid + 256], v2 = row[tid + 512];
    float s = v0 + v1 + v2, sq = v0 * v0 + v1 * v1 + v2 * v2;
    #pragma unroll
    for (int off = 16; off; off >>= 1) {
        s  += __shfl_xor_sync(0xffffffffu, s, off);
        sq += __shfl_xor_sync(0xffffffffu, sq, off);
    }
    __shared__ float rs[8], rq[8], smu, srs;
    int wid = tid >> 5, lane = tid & 31;
    if (!lane) { rs[wid] = s; rq[wid] = sq; }
    __syncthreads();
    if (tid == 0) {
        float S = 0, Q = 0;
        #pragma unroll
        for (int i = 0; i < 8; i++) { S += rs[i]; Q += rq[i]; }
        float mu = S * (1.f / 768.f);
        float var = Q * (1.f / 768.f) - mu * mu;
        smu = mu; srs = rsqrtf(var + 1e-5f);
    }
    __syncthreads();
    float mu = smu, r = srs;
    #pragma unroll
    for (int p = 0; p < 3; p++) {
        int i = tid + p * 256;
        float vv = ((p == 0 ? v0 : p == 1 ? v1 : v2) - mu) * r * g[i] + b[i];
        g_a[ob + i] = __float2half_rn(vv);
    }
}

// ---------------- LayerNorm 2 (fp16 out) ----------------
__global__ __launch_bounds__(256) void ln2_kernel(const float* __restrict__ g,
                                                  const float* __restrict__ b)
{
    int tid = threadIdx.x;
    const float* row = g_x2 + (size_t)blockIdx.x * DIM;
    size_t ob = (size_t)blockIdx.x * DIM;
    float v0 = row[tid], v1 = row[tid + 256], v2 = row[tid + 512];
    float s = v0 + v1 + v2, sq = v0 * v0 + v1 * v1 + v2 * v2;
    #pragma unroll
    for (int off = 16; off; off >>= 1) {
        s  += __shfl_xor_sync(0xffffffffu, s, off);
        sq += __shfl_xor_sync(0xffffffffu, sq, off);
    }
    __shared__ float rs[8], rq[8], smu, srs;
    int wid = tid >> 5, lane = tid & 31;
    if (!lane) { rs[wid] = s; rq[wid] = sq; }
    __syncthreads();
    if (tid == 0) {
        float S = 0, Q = 0;
        #pragma unroll
        for (int i = 0; i < 8; i++) { S += rs[i]; Q += rq[i]; }
        float mu = S * (1.f / 768.f);
        float var = Q * (1.f / 768.f) - mu * mu;
        smu = mu; srs = rsqrtf(var + 1e-5f);
    }
    __syncthreads();
    float mu = smu, r = srs;
    #pragma unroll
    for (int p = 0; p < 3; p++) {
        int i = tid + p * 256;
        float vv = ((p == 0 ? v0 : p == 1 ? v1 : v2) - mu) * r * g[i] + b[i];
        g_b[ob + i] = __float2half_rn(vv);
    }
}

// ---------------- mma.sync GEMM: D[M,N] = A[M,K] x Wt[N,K]^T (uniform) ----------------
// All modes: 1 MMA/step, K-chunk 64, swizzled 128B rows, 3 stages, 2 mats.
#define MATB   16384
#define STAGE  (2 * MATB)
#define SMEM_TG (3 * STAGE)

template <int MODE>
__global__ __launch_bounds__(256, 2) void tgemm_kernel(const float* __restrict__ bias,
                                                       const float* __restrict__ aux,
                                                       float* __restrict__ outp)
{
    constexpr int K      = (MODE == 3) ? 3072 : 768;
    constexpr int Mreal  = (MODE <= 1) ? TOKW : TOKX;
    constexpr int NCHUNK = K / 64;
    const __half* gA  = (MODE == 0) ? g_a : (MODE == 1) ? g_ao : (MODE == 2) ? g_b : g_h1;
    const __half* gBh = (MODE == 0) ? g_wqkv_h : (MODE == 1) ? g_wproj_h : (MODE == 2) ? g_w1_h : g_w2_h;

    extern __shared__ char smem_raw[];
    const uint32_t sbase = smem_u32(smem_raw);

    const int t = threadIdx.x;
    const int m0 = blockIdx.y * 128;
    const int n0 = blockIdx.x * 128;
    const int warp = t >> 5, lane = t & 31;
    const int wm = warp >> 2, wn = warp & 3;

    float acc[4][4][4];
    #pragma unroll
    for (int a = 0; a < 4; a++)
        #pragma unroll
        for (int b2 = 0; b2 < 4; b2++)
            #pragma unroll
            for (int c = 0; c < 4; c++) acc[a][b2][c] = 0.f;

    const int ldrow = t >> 3, ldseg = t & 7;    // 32 rows x 8 segs per pass

    auto issue = [&](int chunk, int stg) {
        const int k0 = chunk * 64;
        const uint32_t so = sbase + (uint32_t)(stg * STAGE);
        #pragma unroll
        for (int p = 0; p < 4; p++) {
            int r = ldrow + p * 32;
            uint32_t off = (uint32_t)(r * 128 + ((ldseg ^ (r & 7)) << 4));
            size_t gaA = (size_t)(m0 + r) * K + k0 + ldseg * 8;
            size_t gaB = (size_t)(n0 + r) * K + k0 + ldseg * 8;
            cp16(so + off, gA + gaA);
            cp16(so + MATB + off, gBh + gaB);
        }
        asm volatile("cp.async.commit_group;" ::: "memory");
    };

    issue(0, 0);
    issue(1, 1);

    const int a_row_in = (lane & 7) + (lane & 8);          // 0..15
    const int a_kg     = lane >> 4;                        // 0/1
    const int b_row16  = (lane & 7) + ((lane >> 4) << 3);  // 0..15
    const int b_kg     = (lane >> 3) & 1;

    for (int i = 0; i < NCHUNK; i++) {
        if (i + 1 < NCHUNK)
            asm volatile("cp.async.wait_group 1;" ::: "memory");
        else
            asm volatile("cp.async.wait_group 0;" ::: "memory");
        __syncthreads();
        if (i + 2 < NCHUNK) issue(i + 2, (i + 2) % 3);

        const uint32_t soA = sbase + (uint32_t)((i % 3) * STAGE);
        const uint32_t soB = soA + MATB;
        #pragma unroll
        for (int ks = 0; ks < 4; ks++) {
            uint32_t bh[4][2];
            #pragma unroll
            for (int pr = 0; pr < 2; pr++) {
                int nr = wn * 32 + pr * 16 + b_row16;
                uint32_t bd = soB + (uint32_t)(nr * 128 + (((ks * 2 + b_kg) ^ (nr & 7)) << 4));
                uint32_t r4[4];
                ldsm_x4(r4, bd);
                bh[2 * pr][0] = r4[0]; bh[2 * pr][1] = r4[1];
                bh[2 * pr + 1][0] = r4[2]; bh[2 * pr + 1][1] = r4[3];
            }
            #pragma unroll
            for (int mt = 0; mt < 4; mt++) {
                uint32_t ah[4];
                int mr = wm * 64 + mt * 16 + a_row_in;
                uint32_t ad = soA + (uint32_t)(mr * 128 + (((ks * 2 + a_kg) ^ (mr & 7)) << 4));
                ldsm_x4(ah, ad);
                #pragma unroll
                for (int nt = 0; nt < 4; nt++)
                    mma_f16(acc[mt][nt], ah, bh[nt]);
            }
        }
    }

    // ---- epilogue ----
    const int g = lane >> 2, tq = lane & 3;
    #pragma unroll
    for (int mt = 0; mt < 4; mt++) {
        #pragma unroll
        for (int half = 0; half < 2; half++) {
            int m = m0 + wm * 64 + mt * 16 + g + half * 8;
            bool valid = (m < Mreal);
            int win = 0, tok = 0, yy = 0, xx = 0, bb = 0;
            if (MODE <= 1) {
                win = m / NTOK; tok = m - win * NTOK;
                if (MODE == 1) {
                    bb = win / NWIN; int rem = win - bb * NWIN;
                    yy = (rem / 5) * WS + tok / WS;
                    xx = (rem % 5) * WS + tok % WS;
                    valid = valid && (yy < 64) && (xx < 64);
                }
            }
            if (!valid) continue;
            #pragma unroll
            for (int nt = 0; nt < 4; nt++) {
                int n = n0 + wn * 32 + nt * 8 + 2 * tq;
                float v0 = acc[mt][nt][half * 2]     + bias[n];
                float v1 = acc[mt][nt][half * 2 + 1] + bias[n + 1];
                if (MODE == 0) {
                    int which = n / 768;
                    int dd = n - which * 768;
                    int head = dd >> 6, hd = dd & 63;
                    size_t o = ((size_t)(win * NHEAD + head) * NTOK + tok) * HDIM + hd;
                    if (which == 0) {
                        g_qh[o]     = __float2half_rn(v0 * 0.125f);
                        g_qh[o + 1] = __float2half_rn(v1 * 0.125f);
                    } else if (which == 1) {
                        g_kh[o]     = __float2half_rn(v0);
                        g_kh[o + 1] = __float2half_rn(v1);
                    } else {
                        g_vh[o]     = __float2half_rn(v0);
                        g_vh[o + 1] = __float2half_rn(v1);
                    }
                } else if (MODE == 1) {
                    size_t o = ((size_t)(bb * 64 + yy) * 64 + xx) * DIM + n;
                    g_x2[o]     = aux[o] + v0;
                    g_x2[o + 1] = aux[o + 1] + v1;
                } else if (MODE == 2) {
                    float gl0 = 0.5f * v0 * (1.f + erff(v0 * 0.70710678118f));
                    float gl1 = 0.5f * v1 * (1.f + erff(v1 * 0.70710678118f));
                    size_t o = (size_t)m * 3072 + n;
                    g_h1[o]     = __float2half_rn(gl0);
                    g_h1[o + 1] = __float2half_rn(gl1);
                } else {
                    size_t o = (size_t)m * DIM + n;
                    outp[o]     = v0 + g_x2[o];
                    outp[o + 1] = v1 + g_x2[o + 1];
                }
            }
        }
    }
}

// ---------------- tensor-core attention: one CTA (8 warps) per (window, head) ----------------
#define ATT_QS_H   0
#define ATT_KS_H   14976
#define ATT_VS_H   29376
#define ATT_F_OFF  88704
#define ATT_B_OFF  90528
#define SM_ATT_TOTAL 91328

__global__ __launch_bounds__(256) void attn_kernel(const float* __restrict__ rel_h,
                                                   const float* __restrict__ rel_w,
                                                   const int* __restrict__ q_idx,
                                                   const int* __restrict__ k_idx)
{
    extern __shared__ char smraw[];
    __half* qs  = (__half*)smraw;
    __half* ksm = qs + ATT_KS_H;
    __half* vsm = qs + ATT_VS_H;
    float* Shf  = (float*)(smraw + ATT_F_OFF);
    float* Swf  = Shf + 196;
    float* rshf = Swf + 196;
    float* rswf = rshf + 32;
    unsigned char* qr8 = (unsigned char*)(smraw + ATT_B_OFF);
    unsigned char* qc8 = qr8 + 196;
    unsigned char* kr8 = qc8 + 196;
    unsigned char* kc8 = kr8 + 196;

    const uint32_t sb = smem_u32(smraw);
    int bh = blockIdx.x;
    int win = bh / NHEAD, head = bh - win * NHEAD;
    int tid = threadIdx.x, warp = tid >> 5, lane = tid & 31;

    const __half* qg = g_qh + (size_t)bh * NTOK * HDIM;
    const __half* kg = g_kh + (size_t)bh * NTOK * HDIM;
    const __half* vg = g_vh + (size_t)bh * NTOK * HDIM;
    for (int i = tid; i < 196 * 8; i += 256) {
        int r = i >> 3, sg = i & 7;
        *(uint4*)(qs  + r * 72 + sg * 8) = *(const uint4*)(qg + r * 64 + sg * 8);
        *(uint4*)(ksm + r * 72 + sg * 8) = *(const uint4*)(kg + r * 64 + sg * 8);
        *(uint4*)(vsm + r * 72 + sg * 8) = *(const uint4*)(vg + r * 64 + sg * 8);
    }
    uint4 z = make_uint4(0, 0, 0, 0);
    for (int i = tid; i < 224; i += 256) {
        if (i < 96)       { int r = 196 + (i >> 3);        *(uint4*)(qs  + r * 72 + (i & 7) * 8) = z; }
        else if (i < 128) { int j = i - 96;  int r = 196 + (j >> 3); *(uint4*)(ksm + r * 72 + (j & 7) * 8) = z; }
        else              { int j = i - 128; int r = 196 + (j >> 3); *(uint4*)(vsm + r * 72 + (j & 7) * 8) = z; }
    }
    if (tid < 27) {
        const float* rp = rel_h + tid * HDIM;
        float s = 0;
        #pragma unroll 8
        for (int c = 0; c < HDIM; c++) s += rp[c];
        rshf[tid] = s;
    } else if (tid >= 32 && tid < 59) {
        const float* rp = rel_w + (tid - 32) * HDIM;
        float s = 0;
        #pragma unroll 8
        for (int c = 0; c < HDIM; c++) s += rp[c];
        rswf[tid - 32] = s;
    }
    if (tid < 196) {
        int qi = q_idx[(size_t)bh * NTOK + tid];
        int ki = k_idx[(size_t)bh * NTOK + tid];
        qr8[tid] = (unsigned char)(qi / WS);
        qc8[tid] = (unsigned char)(qi % WS);
        kr8[tid] = (unsigned char)(ki / WS);
        kc8[tid] = (unsigned char)(ki % WS);
    }
    __syncthreads();
    if (tid < 196) {
        int i = tid / WS, j = tid - i * WS;
        Shf[tid] = rshf[i - j + WS - 1];
        Swf[tid] = rswf[i - j + WS - 1];
    }
    __syncthreads();

    const int g = lane >> 2, tq = lane & 3;
    const int a_row_in = (lane & 7) + (lane & 8);
    const int a_koff   = (lane >> 4) * 8;
    const int b_row_in = lane & 7;
    const int b_koff   = ((lane >> 3) & 1) * 8;
    const uint32_t kbase = sb + ATT_KS_H * 2;
    const uint32_t vbase = sb + ATT_VS_H * 2;

    for (int mt = warp; mt < 13; mt += 8) {
        float sacc[25][4];
        #pragma unroll
        for (int nt = 0; nt < 25; nt++)
            #pragma unroll
            for (int c = 0; c < 4; c++) sacc[nt][c] = 0.f;

        #pragma unroll
        for (int kk = 0; kk < 4; kk++) {
            uint32_t af[4];
            uint32_t qa = sb + (uint32_t)(((mt * 16 + a_row_in) * 72 + kk * 16 + a_koff) * 2);
            ldsm_x4(af, qa);
            #pragma unroll
            for (int nt = 0; nt < 25; nt++) {
                uint32_t bf[2];
                uint32_t ka = kbase + (uint32_t)(((nt * 8 + b_row_in) * 72 + kk * 16 + b_koff) * 2);
                ldsm_x2(bf, ka);
                mma_f16(sacc[nt], af, bf);
            }
        }

        int row0 = mt * 16 + g;
        int row1 = row0 + 8;
        int qb0 = qr8[row0] * WS, qc0 = qc8[row0] * WS;
        int qb1 = qr8[row1] * WS, qc1 = qc8[row1] * WS;
        float mx0 = -1e30f, mx1 = -1e30f;
        #pragma unroll
        for (int nt = 0; nt < 25; nt++) {
            #pragma unroll
            for (int c = 0; c < 2; c++) {
                int col = nt * 8 + tq * 2 + c;
                float s0, s1;
                if (col < 196) {
                    int kr = kr8[col], kc = kc8[col];
                    s0 = sacc[nt][c]     + Shf[qb0 + kr] + Swf[qc0 + kc];
                    s1 = sacc[nt][2 + c] + Shf[qb1 + kr] + Swf[qc1 + kc];
                } else {
                    s0 = -1e30f; s1 = -1e30f;
                }
                sacc[nt][c] = s0; sacc[nt][2 + c] = s1;
                mx0 = fmaxf(mx0, s0); mx1 = fmaxf(mx1, s1);
            }
        }
        mx0 = fmaxf(mx0, __shfl_xor_sync(0xffffffffu, mx0, 1));
        mx0 = fmaxf(mx0, __shfl_xor_sync(0xffffffffu, mx0, 2));
        mx1 = fmaxf(mx1, __shfl_xor_sync(0xffffffffu, mx1, 1));
        mx1 = fmaxf(mx1, __shfl_xor_sync(0xffffffffu, mx1, 2));

        float sm0 = 0.f, sm1 = 0.f;
        uint32_t pf[13][4];
        #pragma unroll
        for (int nt = 0; nt < 25; nt++) {
            float e00 = expf(sacc[nt][0] - mx0);
            float e01 = expf(sacc[nt][1] - mx0);
            float e10 = expf(sacc[nt][2] - mx1);
            float e11 = expf(sacc[nt][3] - mx1);
            sm0 += e00 + e01;
            sm1 += e10 + e11;
            int kt = nt >> 1, hi = nt & 1;
            pf[kt][hi * 2 + 0] = packh2(e00, e01);
            pf[kt][hi * 2 + 1] = packh2(e10, e11);
        }
        pf[12][2] = 0u; pf[12][3] = 0u;
        sm0 += __shfl_xor_sync(0xffffffffu, sm0, 1);
        sm0 += __shfl_xor_sync(0xffffffffu, sm0, 2);
        sm1 += __shfl_xor_sync(0xffffffffu, sm1, 1);
        sm1 += __shfl_xor_sync(0xffffffffu, sm1, 2);
        float inv0 = 1.f / sm0, inv1 = 1.f / sm1;

        float oacc[8][4];
        #pragma unroll
        for (int dt = 0; dt < 8; dt++)
            #pragma unroll
            for (int c = 0; c < 4; c++) oacc[dt][c] = 0.f;
        #pragma unroll
        for (int kt = 0; kt < 13; kt++) {
            #pragma unroll
            for (int dt = 0; dt < 8; dt++) {
                uint32_t bf[2];
                uint32_t va = vbase + (uint32_t)(((kt * 16 + (lane & 15)) * 72 + dt * 8) * 2);
                ldsm_x2t(bf, va);
                mma_f16(oacc[dt], pf[kt], bf);
            }
        }

        bool ok0 = row0 < NTOK, ok1 = row1 < NTOK;
        size_t ob0 = ((size_t)(win * NTOK) + row0) * DIM + head * HDIM;
        #pragma unroll
        for (int dt = 0; dt < 8; dt++) {
            int d = dt * 8 + tq * 2;
            if (ok0) {
                __half2 hv = __floats2half2_rn(oacc[dt][0] * inv0, oacc[dt][1] * inv0);
                *(__half2*)(g_ao + ob0 + d) = hv;
            }
            if (ok1) {
                __half2 hv = __floats2half2_rn(oacc[dt][2] * inv1, oacc[dt][3] * inv1);
                *(__half2*)(g_ao + ob0 + (size_t)8 * DIM + d) = hv;
            }
        }
    }
}

// ---------------- launch ----------------
extern "C" void kernel_launch(void* const* d_in, const int* in_sizes, int n_in,
                              void* d_out, int out_size)
{
    const float* x     = (const float*)d_in[0];
    const int*   qidx  = (const int*)d_in[1];
    const int*   kidx  = (const int*)d_in[2];
    const float* ln1w  = (const float*)d_in[3];
    const float* ln1b  = (const float*)d_in[4];
    const float* ln2w  = (const float*)d_in[5];
    const float* ln2b  = (const float*)d_in[6];
    const float* qkvw  = (const float*)d_in[7];
    const float* qkvb  = (const float*)d_in[8];
    const float* projw = (const float*)d_in[9];
    const float* projb = (const float*)d_in[10];
    const float* relh  = (const float*)d_in[11];
    const float* relw  = (const float*)d_in[12];
    const float* w1    = (const float*)d_in[13];
    const float* b1    = (const float*)d_in[14];
    const float* w2    = (const float*)d_in[15];
    const float* b2    = (const float*)d_in[16];
    float* out = (float*)d_out;

    cudaFuncSetAttribute(attn_kernel, cudaFuncAttributeMaxDynamicSharedMemorySize, SM_ATT_TOTAL);
    cudaFuncSetAttribute(tgemm_kernel<0>, cudaFuncAttributeMaxDynamicSharedMemorySize, SMEM_TG);
    cudaFuncSetAttribute(tgemm_kernel<1>, cudaFuncAttributeMaxDynamicSharedMemorySize, SMEM_TG);
    cudaFuncSetAttribute(tgemm_kernel<2>, cudaFuncAttributeMaxDynamicSharedMemorySize, SMEM_TG);
    cudaFuncSetAttribute(tgemm_kernel<3>, cudaFuncAttributeMaxDynamicSharedMemorySize, SMEM_TG);

    __half *wqkv_h, *wproj_h, *w1_h, *w2_h;
    cudaGetSymbolAddress((void**)&wqkv_h, g_wqkv_h);
    cudaGetSymbolAddress((void**)&wproj_h, g_wproj_h);
    cudaGetSymbolAddress((void**)&w1_h, g_w1_h);
    cudaGetSymbolAddress((void**)&w2_h, g_w2_h);

    // launch index 3 = tgemm<0> (ncu profiles it)
    wsplit_kernel<<<dim3(2304 / 32, 768 / 32), 256>>>(qkvw, wqkv_h, 768, 2304);           // 0
    wsplit_kernel<<<dim3(3072 / 32, 768 / 32), 256>>>(w1, w1_h, 768, 3072);                // 1
    ln1_kernel<<<TOKW, 256>>>(x, ln1w, ln1b);                                              // 2
    tgemm_kernel<0><<<dim3(2304 / 128, TOKW_PAD / 128), 256, SMEM_TG>>>(qkvb, nullptr, nullptr); // 3
    attn_kernel<<<BH, 256, SM_ATT_TOTAL>>>(relh, relw, qidx, kidx);                        // 4
    wsplit_kernel<<<dim3(768 / 32, 768 / 32), 256>>>(projw, wproj_h, 768, 768);            // 5
    tgemm_kernel<1><<<dim3(768 / 128, TOKW_PAD / 128), 256, SMEM_TG>>>(projb, x, nullptr); // 6
    ln2_kernel<<<TOKX, 256>>>(ln2w, ln2b);                                                 // 7
    wsplit_kernel<<<dim3(768 / 32, 3072 / 32), 256>>>(w2, w2_h, 3072, 768);                // 8
    tgemm_kernel<2><<<dim3(3072 / 128, TOKX / 128), 256, SMEM_TG>>>(b1, nullptr, nullptr); // 9
    tgemm_kernel<3><<<dim3(768 / 128, TOKX / 128), 256, SMEM_TG>>>(b2, nullptr, out);      // 10
}

// round 14
// speedup vs baseline: 3.4988x; 1.0655x over previous
/*
 * R14: R13 + (a) intra-chunk B-fragment double buffering in tgemm (overlap
 * ldsm with MMA), (b) attention __launch_bounds__(256,2) for 2 CTAs/SM.
 * Numerics identical to R13.
 */
#include <cuda_runtime.h>
#include <cuda_fp16.h>
#include <math.h>
#include <stdint.h>

#define DIM   768
#define NHEAD 12
#define HDIM  64
#define WS    14
#define NTOK  196
#define NWIN  25
#define BATCH 8
#define NWB   200
#define TOKW  39200
#define TOKW_PAD 39296
#define TOKX  32768
#define BH    2400

// ---------------- device scratch ----------------
__device__ __half g_a[(size_t)TOKW_PAD * DIM];
__device__ __half g_ao[(size_t)TOKW_PAD * DIM];
__device__ __half g_b[(size_t)TOKX * DIM];
__device__ __half g_h1[(size_t)TOKX * 3072];
__device__ __half g_wqkv_h[(size_t)2304 * 768];
__device__ __half g_wproj_h[(size_t)768 * 768];
__device__ __half g_w1_h[(size_t)3072 * 768];
__device__ __half g_w2_h[(size_t)768 * 3072];
__device__ __half g_qh[(size_t)BH * NTOK * HDIM];
__device__ __half g_kh[(size_t)BH * NTOK * HDIM];
__device__ __half g_vh[(size_t)BH * NTOK * HDIM];
__device__ float g_x2[(size_t)TOKX * DIM];

// ---------------- PTX helpers ----------------
__device__ __forceinline__ uint32_t smem_u32(const void* p) {
    uint32_t a;
    asm("{ .reg .u64 t; cvta.to.shared.u64 t, %1; cvt.u32.u64 %0, t; }" : "=r"(a) : "l"(p));
    return a;
}
__device__ __forceinline__ void cp16(uint32_t dst, const void* src) {
    asm volatile("cp.async.cg.shared.global [%0], [%1], 16;" :: "r"(dst), "l"(src));
}
__device__ __forceinline__ void ldsm_x4(uint32_t* r, uint32_t addr) {
    asm volatile("ldmatrix.sync.aligned.m8n8.x4.shared.b16 {%0,%1,%2,%3}, [%4];"
        : "=r"(r[0]), "=r"(r[1]), "=r"(r[2]), "=r"(r[3]) : "r"(addr));
}
__device__ __forceinline__ void ldsm_x2(uint32_t* r, uint32_t addr) {
    asm volatile("ldmatrix.sync.aligned.m8n8.x2.shared.b16 {%0,%1}, [%2];"
        : "=r"(r[0]), "=r"(r[1]) : "r"(addr));
}
__device__ __forceinline__ void ldsm_x2t(uint32_t* r, uint32_t addr) {
    asm volatile("ldmatrix.sync.aligned.m8n8.x2.trans.shared.b16 {%0,%1}, [%2];"
        : "=r"(r[0]), "=r"(r[1]) : "r"(addr));
}
__device__ __forceinline__ void mma_f16(float* c, const uint32_t* a, const uint32_t* b) {
    asm volatile(
        "mma.sync.aligned.m16n8k16.row.col.f32.f16.f16.f32 "
        "{%0,%1,%2,%3}, {%4,%5,%6,%7}, {%8,%9}, {%0,%1,%2,%3};"
        : "+f"(c[0]), "+f"(c[1]), "+f"(c[2]), "+f"(c[3])
        : "r"(a[0]), "r"(a[1]), "r"(a[2]), "r"(a[3]), "r"(b[0]), "r"(b[1]));
}
__device__ __forceinline__ uint32_t packh2(float a, float b) {
    __half2 h = __floats2half2_rn(a, b);
    return *(uint32_t*)&h;
}

// ---------------- weight transpose + fp16: W[K,N] -> Wt[N,K] ----------------
__global__ __launch_bounds__(256) void wsplit_kernel(const float* __restrict__ W,
                                                     __half* __restrict__ Wh,
                                                     int K, int N)
{
    __shared__ float tile[32][33];
    int k0 = blockIdx.y * 32, n0 = blockIdx.x * 32;
    int tx = threadIdx.x & 31, ty = threadIdx.x >> 5;
    #pragma unroll
    for (int j = 0; j < 32; j += 8)
        tile[ty + j][tx] = W[(size_t)(k0 + ty + j) * N + n0 + tx];
    __syncthreads();
    #pragma unroll
    for (int j = 0; j < 32; j += 8) {
        Wh[(size_t)(n0 + ty + j) * K + k0 + tx] = __float2half_rn(tile[tx][ty + j]);
    }
}

// ---------------- LayerNorm 1 (window partition + pad, fp16 out) ----------------
__global__ __launch_bounds__(256) void ln1_kernel(const float* __restrict__ x,
                                                  const float* __restrict__ g,
                                                  const float* __restrict__ b)
{
    int widx = blockIdx.x;
    int win = widx / NTOK, tok = widx - win * NTOK;
    int bb = win / NWIN, rem = win - bb * NWIN;
    int y = (rem / 5) * WS + tok / WS;
    int xx = (rem % 5) * WS + tok % WS;
    size_t ob = (size_t)widx * DIM;
    int tid = threadIdx.x;
    if (y >= 64 || xx >= 64) {
        for (int i = tid; i < DIM; i += 256) g_a[ob + i] = __float2half(0.f);
        return;
    }
    const float* row = x + ((size_t)(bb * 64 + y) * 64 + xx) * DIM;
    float v0 = row[tid], v1 = row[tid + 256], v2 = row[tid + 512];
    float s = v0 + v1 + v2, sq = v0 * v0 + v1 * v1 + v2 * v2;
    #pragma unroll
    for (int off = 16; off; off >>= 1) {
        s  += __shfl_xor_sync(0xffffffffu, s, off);
        sq += __shfl_xor_sync(0xffffffffu, sq, off);
    }
    __shared__ float rs[8], rq[8], smu, srs;
    int wid = tid >> 5, lane = tid & 31;
    if (!lane) { rs[wid] = s; rq[wid] = sq; }
    __syncthreads();
    if (tid == 0) {
        float S = 0, Q = 0;
        #pragma unroll
        for (int i = 0; i < 8; i++) { S += rs[i]; Q += rq[i]; }
        float mu = S * (1.f / 768.f);
        float var = Q * (1.f / 768.f) - mu * mu;
        smu = mu; srs = rsqrtf(var + 1e-5f);
    }
    __syncthreads();
    float mu = smu, r = srs;
    #pragma unroll
    for (int p = 0; p < 3; p++) {
        int i = tid + p * 256;
        float vv = ((p == 0 ? v0 : p == 1 ? v1 : v2) - mu) * r * g[i] + b[i];
        g_a[ob + i] = __float2half_rn(vv);
    }
}

// ---------------- LayerNorm 2 (fp16 out) ----------------
__global__ __launch_bounds__(256) void ln2_kernel(const float* __restrict__ g,
                                                  const float* __restrict__ b)
{
    int tid = threadIdx.x;
    const float* row = g_x2 + (size_t)blockIdx.x * DIM;
    size_t ob = (size_t)blockIdx.x * DIM;
    float v0 = row[tid], v1 = row[tid + 256], v2 = row[tid + 512];
    float s = v0 + v1 + v2, sq = v0 * v0 + v1 * v1 + v2 * v2;
    #pragma unroll
    for (int off = 16; off; off >>= 1) {
        s  += __shfl_xor_sync(0xffffffffu, s, off);
        sq += __shfl_xor_sync(0xffffffffu, sq, off);
    }
    __shared__ float rs[8], rq[8], smu, srs;
    int wid = tid >> 5, lane = tid & 31;
    if (!lane) { rs[wid] = s; rq[wid] = sq; }
    __syncthreads();
    if (tid == 0) {
        float S = 0, Q = 0;
        #pragma unroll
        for (int i = 0; i < 8; i++) { S += rs[i]; Q += rq[i]; }
        float mu = S * (1.f / 768.f);
        float var = Q * (1.f / 768.f) - mu * mu;
        smu = mu; srs = rsqrtf(var + 1e-5f);
    }
    __syncthreads();
    float mu = smu, r = srs;
    #pragma unroll
    for (int p = 0; p < 3; p++) {
        int i = tid + p * 256;
        float vv = ((p == 0 ? v0 : p == 1 ? v1 : v2) - mu) * r * g[i] + b[i];
        g_b[ob + i] = __float2half_rn(vv);
    }
}

// ---------------- mma.sync GEMM: D[M,N] = A[M,K] x Wt[N,K]^T (uniform) ----------------
#define MATB   16384
#define STAGE  (2 * MATB)
#define SMEM_TG (3 * STAGE)

template <int MODE>
__global__ __launch_bounds__(256, 2) void tgemm_kernel(const float* __restrict__ bias,
                                                       const float* __restrict__ aux,
                                                       float* __restrict__ outp)
{
    constexpr int K      = (MODE == 3) ? 3072 : 768;
    constexpr int Mreal  = (MODE <= 1) ? TOKW : TOKX;
    constexpr int NCHUNK = K / 64;
    const __half* gA  = (MODE == 0) ? g_a : (MODE == 1) ? g_ao : (MODE == 2) ? g_b : g_h1;
    const __half* gBh = (MODE == 0) ? g_wqkv_h : (MODE == 1) ? g_wproj_h : (MODE == 2) ? g_w1_h : g_w2_h;

    extern __shared__ char smem_raw[];
    const uint32_t sbase = smem_u32(smem_raw);

    const int t = threadIdx.x;
    const int m0 = blockIdx.y * 128;
    const int n0 = blockIdx.x * 128;
    const int warp = t >> 5, lane = t & 31;
    const int wm = warp >> 2, wn = warp & 3;

    float acc[4][4][4];
    #pragma unroll
    for (int a = 0; a < 4; a++)
        #pragma unroll
        for (int b2 = 0; b2 < 4; b2++)
            #pragma unroll
            for (int c = 0; c < 4; c++) acc[a][b2][c] = 0.f;

    const int ldrow = t >> 3, ldseg = t & 7;

    auto issue = [&](int chunk, int stg) {
        const int k0 = chunk * 64;
        const uint32_t so = sbase + (uint32_t)(stg * STAGE);
        #pragma unroll
        for (int p = 0; p < 4; p++) {
            int r = ldrow + p * 32;
            uint32_t off = (uint32_t)(r * 128 + ((ldseg ^ (r & 7)) << 4));
            size_t gaA = (size_t)(m0 + r) * K + k0 + ldseg * 8;
            size_t gaB = (size_t)(n0 + r) * K + k0 + ldseg * 8;
            cp16(so + off, gA + gaA);
            cp16(so + MATB + off, gBh + gaB);
        }
        asm volatile("cp.async.commit_group;" ::: "memory");
    };

    issue(0, 0);
    issue(1, 1);

    const int a_row_in = (lane & 7) + (lane & 8);
    const int a_kg     = lane >> 4;
    const int b_row16  = (lane & 7) + ((lane >> 4) << 3);
    const int b_kg     = (lane >> 3) & 1;

    for (int i = 0; i < NCHUNK; i++) {
        if (i + 1 < NCHUNK)
            asm volatile("cp.async.wait_group 1;" ::: "memory");
        else
            asm volatile("cp.async.wait_group 0;" ::: "memory");
        __syncthreads();
        if (i + 2 < NCHUNK) issue(i + 2, (i + 2) % 3);

        const uint32_t soA = sbase + (uint32_t)((i % 3) * STAGE);
        const uint32_t soB = soA + MATB;

        auto loadB = [&](int ks, uint32_t bh[4][2]) {
            #pragma unroll
            for (int pr = 0; pr < 2; pr++) {
                int nr = wn * 32 + pr * 16 + b_row16;
                uint32_t bd = soB + (uint32_t)(nr * 128 + (((ks * 2 + b_kg) ^ (nr & 7)) << 4));
                uint32_t r4[4];
                ldsm_x4(r4, bd);
                bh[2 * pr][0] = r4[0]; bh[2 * pr][1] = r4[1];
                bh[2 * pr + 1][0] = r4[2]; bh[2 * pr + 1][1] = r4[3];
            }
        };

        uint32_t bcur[4][2], bnxt[4][2];
        loadB(0, bcur);
        #pragma unroll
        for (int ks = 0; ks < 4; ks++) {
            if (ks < 3) loadB(ks + 1, bnxt);
            #pragma unroll
            for (int mt = 0; mt < 4; mt++) {
                uint32_t ah[4];
                int mr = wm * 64 + mt * 16 + a_row_in;
                uint32_t ad = soA + (uint32_t)(mr * 128 + (((ks * 2 + a_kg) ^ (mr & 7)) << 4));
                ldsm_x4(ah, ad);
                #pragma unroll
                for (int nt = 0; nt < 4; nt++)
                    mma_f16(acc[mt][nt], ah, bcur[nt]);
            }
            if (ks < 3) {
                #pragma unroll
                for (int nt = 0; nt < 4; nt++) {
                    bcur[nt][0] = bnxt[nt][0];
                    bcur[nt][1] = bnxt[nt][1];
                }
            }
        }
    }

    // ---- epilogue ----
    const int g = lane >> 2, tq = lane & 3;
    #pragma unroll
    for (int mt = 0; mt < 4; mt++) {
        #pragma unroll
        for (int half = 0; half < 2; half++) {
            int m = m0 + wm * 64 + mt * 16 + g + half * 8;
            bool valid = (m < Mreal);
            int win = 0, tok = 0, yy = 0, xx = 0, bb = 0;
            if (MODE <= 1) {
                win = m / NTOK; tok = m - win * NTOK;
                if (MODE == 1) {
                    bb = win / NWIN; int rem = win - bb * NWIN;
                    yy = (rem / 5) * WS + tok / WS;
                    xx = (rem % 5) * WS + tok % WS;
                    valid = valid && (yy < 64) && (xx < 64);
                }
            }
            if (!valid) continue;
            #pragma unroll
            for (int nt = 0; nt < 4; nt++) {
                int n = n0 + wn * 32 + nt * 8 + 2 * tq;
                float v0 = acc[mt][nt][half * 2]     + bias[n];
                float v1 = acc[mt][nt][half * 2 + 1] + bias[n + 1];
                if (MODE == 0) {
                    int which = n / 768;
                    int dd = n - which * 768;
                    int head = dd >> 6, hd = dd & 63;
                    size_t o = ((size_t)(win * NHEAD + head) * NTOK + tok) * HDIM + hd;
                    if (which == 0) {
                        g_qh[o]     = __float2half_rn(v0 * 0.125f);
                        g_qh[o + 1] = __float2half_rn(v1 * 0.125f);
                    } else if (which == 1) {
                        g_kh[o]     = __float2half_rn(v0);
                        g_kh[o + 1] = __float2half_rn(v1);
                    } else {
                        g_vh[o]     = __float2half_rn(v0);
                        g_vh[o + 1] = __float2half_rn(v1);
                    }
                } else if (MODE == 1) {
                    size_t o = ((size_t)(bb * 64 + yy) * 64 + xx) * DIM + n;
                    g_x2[o]     = aux[o] + v0;
                    g_x2[o + 1] = aux[o + 1] + v1;
                } else if (MODE == 2) {
                    float gl0 = 0.5f * v0 * (1.f + erff(v0 * 0.70710678118f));
                    float gl1 = 0.5f * v1 * (1.f + erff(v1 * 0.70710678118f));
                    size_t o = (size_t)m * 3072 + n;
                    g_h1[o]     = __float2half_rn(gl0);
                    g_h1[o + 1] = __float2half_rn(gl1);
                } else {
                    size_t o = (size_t)m * DIM + n;
                    outp[o]     = v0 + g_x2[o];
                    outp[o + 1] = v1 + g_x2[o + 1];
                }
            }
        }
    }
}

// ---------------- tensor-core attention: one CTA (8 warps) per (window, head) ----------------
#define ATT_QS_H   0
#define ATT_KS_H   14976
#define ATT_VS_H   29376
#define ATT_F_OFF  88704
#define ATT_B_OFF  90528
#define SM_ATT_TOTAL 91328

__global__ __launch_bounds__(256, 2) void attn_kernel(const float* __restrict__ rel_h,
                                                      const float* __restrict__ rel_w,
                                                      const int* __restrict__ q_idx,
                                                      const int* __restrict__ k_idx)
{
    extern __shared__ char smraw[];
    __half* qs  = (__half*)smraw;
    __half* ksm = qs + ATT_KS_H;
    __half* vsm = qs + ATT_VS_H;
    float* Shf  = (float*)(smraw + ATT_F_OFF);
    float* Swf  = Shf + 196;
    float* rshf = Swf + 196;
    float* rswf = rshf + 32;
    unsigned char* qr8 = (unsigned char*)(smraw + ATT_B_OFF);
    unsigned char* qc8 = qr8 + 196;
    unsigned char* kr8 = qc8 + 196;
    unsigned char* kc8 = kr8 + 196;

    const uint32_t sb = smem_u32(smraw);
    int bh = blockIdx.x;
    int win = bh / NHEAD, head = bh - win * NHEAD;
    int tid = threadIdx.x, warp = tid >> 5, lane = tid & 31;

    const __half* qg = g_qh + (size_t)bh * NTOK * HDIM;
    const __half* kg = g_kh + (size_t)bh * NTOK * HDIM;
    const __half* vg = g_vh + (size_t)bh * NTOK * HDIM;
    for (int i = tid; i < 196 * 8; i += 256) {
        int r = i >> 3, sg = i & 7;
        *(uint4*)(qs  + r * 72 + sg * 8) = *(const uint4*)(qg + r * 64 + sg * 8);
        *(uint4*)(ksm + r * 72 + sg * 8) = *(const uint4*)(kg + r * 64 + sg * 8);
        *(uint4*)(vsm + r * 72 + sg * 8) = *(const uint4*)(vg + r * 64 + sg * 8);
    }
    uint4 z = make_uint4(0, 0, 0, 0);
    for (int i = tid; i < 224; i += 256) {
        if (i < 96)       { int r = 196 + (i >> 3);        *(uint4*)(qs  + r * 72 + (i & 7) * 8) = z; }
        else if (i < 128) { int j = i - 96;  int r = 196 + (j >> 3); *(uint4*)(ksm + r * 72 + (j & 7) * 8) = z; }
        else              { int j = i - 128; int r = 196 + (j >> 3); *(uint4*)(vsm + r * 72 + (j & 7) * 8) = z; }
    }
    if (tid < 27) {
        const float* rp = rel_h + tid * HDIM;
        float s = 0;
        #pragma unroll 8
        for (int c = 0; c < HDIM; c++) s += rp[c];
        rshf[tid] = s;
    } else if (tid >= 32 && tid < 59) {
        const float* rp = rel_w + (tid - 32) * HDIM;
        float s = 0;
        #pragma unroll 8
        for (int c = 0; c < HDIM; c++) s += rp[c];
        rswf[tid - 32] = s;
    }
    if (tid < 196) {
        int qi = q_idx[(size_t)bh * NTOK + tid];
        int ki = k_idx[(size_t)bh * NTOK + tid];
        qr8[tid] = (unsigned char)(qi / WS);
        qc8[tid] = (unsigned char)(qi % WS);
        kr8[tid] = (unsigned char)(ki / WS);
        kc8[tid] = (unsigned char)(ki % WS);
    }
    __syncthreads();
    if (tid < 196) {
        int i = tid / WS, j = tid - i * WS;
        Shf[tid] = rshf[i - j + WS - 1];
        Swf[tid] = rswf[i - j + WS - 1];
    }
    __syncthreads();

    const int g = lane >> 2, tq = lane & 3;
    const int a_row_in = (lane & 7) + (lane & 8);
    const int a_koff   = (lane >> 4) * 8;
    const int b_row_in = lane & 7;
    const int b_koff   = ((lane >> 3) & 1) * 8;
    const uint32_t kbase = sb + ATT_KS_H * 2;
    const uint32_t vbase = sb + ATT_VS_H * 2;

    for (int mt = warp; mt < 13; mt += 8) {
        float sacc[25][4];
        #pragma unroll
        for (int nt = 0; nt < 25; nt++)
            #pragma unroll
            for (int c = 0; c < 4; c++) sacc[nt][c] = 0.f;

        #pragma unroll
        for (int kk = 0; kk < 4; kk++) {
            uint32_t af[4];
            uint32_t qa = sb + (uint32_t)(((mt * 16 + a_row_in) * 72 + kk * 16 + a_koff) * 2);
            ldsm_x4(af, qa);
            #pragma unroll
            for (int nt = 0; nt < 25; nt++) {
                uint32_t bf[2];
                uint32_t ka = kbase + (uint32_t)(((nt * 8 + b_row_in) * 72 + kk * 16 + b_koff) * 2);
                ldsm_x2(bf, ka);
                mma_f16(sacc[nt], af, bf);
            }
        }

        int row0 = mt * 16 + g;
        int row1 = row0 + 8;
        int qb0 = qr8[row0] * WS, qc0 = qc8[row0] * WS;
        int qb1 = qr8[row1] * WS, qc1 = qc8[row1] * WS;
        float mx0 = -1e30f, mx1 = -1e30f;
        #pragma unroll
        for (int nt = 0; nt < 25; nt++) {
            #pragma unroll
            for (int c = 0; c < 2; c++) {
                int col = nt * 8 + tq * 2 + c;
                float s0, s1;
                if (col < 196) {
                    int kr = kr8[col], kc = kc8[col];
                    s0 = sacc[nt][c]     + Shf[qb0 + kr] + Swf[qc0 + kc];
                    s1 = sacc[nt][2 + c] + Shf[qb1 + kr] + Swf[qc1 + kc];
                } else {
                    s0 = -1e30f; s1 = -1e30f;
                }
                sacc[nt][c] = s0; sacc[nt][2 + c] = s1;
                mx0 = fmaxf(mx0, s0); mx1 = fmaxf(mx1, s1);
            }
        }
        mx0 = fmaxf(mx0, __shfl_xor_sync(0xffffffffu, mx0, 1));
        mx0 = fmaxf(mx0, __shfl_xor_sync(0xffffffffu, mx0, 2));
        mx1 = fmaxf(mx1, __shfl_xor_sync(0xffffffffu, mx1, 1));
        mx1 = fmaxf(mx1, __shfl_xor_sync(0xffffffffu, mx1, 2));

        float sm0 = 0.f, sm1 = 0.f;
        uint32_t pf[13][4];
        #pragma unroll
        for (int nt = 0; nt < 25; nt++) {
            float e00 = expf(sacc[nt][0] - mx0);
            float e01 = expf(sacc[nt][1] - mx0);
            float e10 = expf(sacc[nt][2] - mx1);
            float e11 = expf(sacc[nt][3] - mx1);
            sm0 += e00 + e01;
            sm1 += e10 + e11;
            int kt = nt >> 1, hi = nt & 1;
            pf[kt][hi * 2 + 0] = packh2(e00, e01);
            pf[kt][hi * 2 + 1] = packh2(e10, e11);
        }
        pf[12][2] = 0u; pf[12][3] = 0u;
        sm0 += __shfl_xor_sync(0xffffffffu, sm0, 1);
        sm0 += __shfl_xor_sync(0xffffffffu, sm0, 2);
        sm1 += __shfl_xor_sync(0xffffffffu, sm1, 1);
        sm1 += __shfl_xor_sync(0xffffffffu, sm1, 2);
        float inv0 = 1.f / sm0, inv1 = 1.f / sm1;

        float oacc[8][4];
        #pragma unroll
        for (int dt = 0; dt < 8; dt++)
            #pragma unroll
            for (int c = 0; c < 4; c++) oacc[dt][c] = 0.f;
        #pragma unroll
        for (int kt = 0; kt < 13; kt++) {
            #pragma unroll
            for (int dt = 0; dt < 8; dt++) {
                uint32_t bf[2];
                uint32_t va = vbase + (uint32_t)(((kt * 16 + (lane & 15)) * 72 + dt * 8) * 2);
                ldsm_x2t(bf, va);
                mma_f16(oacc[dt], pf[kt], bf);
            }
        }

        bool ok0 = row0 < NTOK, ok1 = row1 < NTOK;
        size_t ob0 = ((size_t)(win * NTOK) + row0) * DIM + head * HDIM;
        #pragma unroll
        for (int dt = 0; dt < 8; dt++) {
            int d = dt * 8 + tq * 2;
            if (ok0) {
                __half2 hv = __floats2half2_rn(oacc[dt][0] * inv0, oacc[dt][1] * inv0);
                *(__half2*)(g_ao + ob0 + d) = hv;
            }
            if (ok1) {
                __half2 hv = __floats2half2_rn(oacc[dt][2] * inv1, oacc[dt][3] * inv1);
                *(__half2*)(g_ao + ob0 + (size_t)8 * DIM + d) = hv;
            }
        }
    }
}

// ---------------- launch ----------------
extern "C" void kernel_launch(void* const* d_in, const int* in_sizes, int n_in,
                              void* d_out, int out_size)
{
    const float* x     = (const float*)d_in[0];
    const int*   qidx  = (const int*)d_in[1];
    const int*   kidx  = (const int*)d_in[2];
    const float* ln1w  = (const float*)d_in[3];
    const float* ln1b  = (const float*)d_in[4];
    const float* ln2w  = (const float*)d_in[5];
    const float* ln2b  = (const float*)d_in[6];
    const float* qkvw  = (const float*)d_in[7];
    const float* qkvb  = (const float*)d_in[8];
    const float* projw = (const float*)d_in[9];
    const float* projb = (const float*)d_in[10];
    const float* relh  = (const float*)d_in[11];
    const float* relw  = (const float*)d_in[12];
    const float* w1    = (const float*)d_in[13];
    const float* b1    = (const float*)d_in[14];
    const float* w2    = (const float*)d_in[15];
    const float* b2    = (const float*)d_in[16];
    float* out = (float*)d_out;

    cudaFuncSetAttribute(attn_kernel, cudaFuncAttributeMaxDynamicSharedMemorySize, SM_ATT_TOTAL);
    cudaFuncSetAttribute(tgemm_kernel<0>, cudaFuncAttributeMaxDynamicSharedMemorySize, SMEM_TG);
    cudaFuncSetAttribute(tgemm_kernel<1>, cudaFuncAttributeMaxDynamicSharedMemorySize, SMEM_TG);
    cudaFuncSetAttribute(tgemm_kernel<2>, cudaFuncAttributeMaxDynamicSharedMemorySize, SMEM_TG);
    cudaFuncSetAttribute(tgemm_kernel<3>, cudaFuncAttributeMaxDynamicSharedMemorySize, SMEM_TG);

    __half *wqkv_h, *wproj_h, *w1_h, *w2_h;
    cudaGetSymbolAddress((void**)&wqkv_h, g_wqkv_h);
    cudaGetSymbolAddress((void**)&wproj_h, g_wproj_h);
    cudaGetSymbolAddress((void**)&w1_h, g_w1_h);
    cudaGetSymbolAddress((void**)&w2_h, g_w2_h);

    // launch index 3 = tgemm<0> (ncu profiles it)
    wsplit_kernel<<<dim3(2304 / 32, 768 / 32), 256>>>(qkvw, wqkv_h, 768, 2304);           // 0
    wsplit_kernel<<<dim3(3072 / 32, 768 / 32), 256>>>(w1, w1_h, 768, 3072);                // 1
    ln1_kernel<<<TOKW, 256>>>(x, ln1w, ln1b);                                              // 2
    tgemm_kernel<0><<<dim3(2304 / 128, TOKW_PAD / 128), 256, SMEM_TG>>>(qkvb, nullptr, nullptr); // 3
    attn_kernel<<<BH, 256, SM_ATT_TOTAL>>>(relh, relw, qidx, kidx);                        // 4
    wsplit_kernel<<<dim3(768 / 32, 768 / 32), 256>>>(projw, wproj_h, 768, 768);            // 5
    tgemm_kernel<1><<<dim3(768 / 128, TOKW_PAD / 128), 256, SMEM_TG>>>(projb, x, nullptr); // 6
    ln2_kernel<<<TOKX, 256>>>(ln2w, ln2b);                                                 // 7
    wsplit_kernel<<<dim3(768 / 32, 3072 / 32), 256>>>(w2, w2_h, 3072, 768);                // 8
    tgemm_kernel<2><<<dim3(3072 / 128, TOKX / 128), 256, SMEM_TG>>>(b1, nullptr, nullptr); // 9
    tgemm_kernel<3><<<dim3(768 / 128, TOKX / 128), 256, SMEM_TG>>>(b2, nullptr, out);      // 10
}

// round 15
// speedup vs baseline: 3.5905x; 1.0262x over previous
/*
 * R15: GEMMs rebuilt as 4 warps/CTA (128 threads), warp tile 64x64 —
 * halves LDSM traffic per MMA (measured L1=68% bottleneck). 2 CTAs/SM.
 * Numerics identical to R14 (rel_err should stay 1.44e-4).
 */
#include <cuda_runtime.h>
#include <cuda_fp16.h>
#include <math.h>
#include <stdint.h>

#define DIM   768
#define NHEAD 12
#define HDIM  64
#define WS    14
#define NTOK  196
#define NWIN  25
#define BATCH 8
#define NWB   200
#define TOKW  39200
#define TOKW_PAD 39296
#define TOKX  32768
#define BH    2400

// ---------------- device scratch ----------------
__device__ __half g_a[(size_t)TOKW_PAD * DIM];
__device__ __half g_ao[(size_t)TOKW_PAD * DIM];
__device__ __half g_b[(size_t)TOKX * DIM];
__device__ __half g_h1[(size_t)TOKX * 3072];
__device__ __half g_wqkv_h[(size_t)2304 * 768];
__device__ __half g_wproj_h[(size_t)768 * 768];
__device__ __half g_w1_h[(size_t)3072 * 768];
__device__ __half g_w2_h[(size_t)768 * 3072];
__device__ __half g_qh[(size_t)BH * NTOK * HDIM];
__device__ __half g_kh[(size_t)BH * NTOK * HDIM];
__device__ __half g_vh[(size_t)BH * NTOK * HDIM];
__device__ float g_x2[(size_t)TOKX * DIM];

// ---------------- PTX helpers ----------------
__device__ __forceinline__ uint32_t smem_u32(const void* p) {
    uint32_t a;
    asm("{ .reg .u64 t; cvta.to.shared.u64 t, %1; cvt.u32.u64 %0, t; }" : "=r"(a) : "l"(p));
    return a;
}
__device__ __forceinline__ void cp16(uint32_t dst, const void* src) {
    asm volatile("cp.async.cg.shared.global [%0], [%1], 16;" :: "r"(dst), "l"(src));
}
__device__ __forceinline__ void ldsm_x4(uint32_t* r, uint32_t addr) {
    asm volatile("ldmatrix.sync.aligned.m8n8.x4.shared.b16 {%0,%1,%2,%3}, [%4];"
        : "=r"(r[0]), "=r"(r[1]), "=r"(r[2]), "=r"(r[3]) : "r"(addr));
}
__device__ __forceinline__ void ldsm_x2(uint32_t* r, uint32_t addr) {
    asm volatile("ldmatrix.sync.aligned.m8n8.x2.shared.b16 {%0,%1}, [%2];"
        : "=r"(r[0]), "=r"(r[1]) : "r"(addr));
}
__device__ __forceinline__ void ldsm_x2t(uint32_t* r, uint32_t addr) {
    asm volatile("ldmatrix.sync.aligned.m8n8.x2.trans.shared.b16 {%0,%1}, [%2];"
        : "=r"(r[0]), "=r"(r[1]) : "r"(addr));
}
__device__ __forceinline__ void mma_f16(float* c, const uint32_t* a, const uint32_t* b) {
    asm volatile(
        "mma.sync.aligned.m16n8k16.row.col.f32.f16.f16.f32 "
        "{%0,%1,%2,%3}, {%4,%5,%6,%7}, {%8,%9}, {%0,%1,%2,%3};"
        : "+f"(c[0]), "+f"(c[1]), "+f"(c[2]), "+f"(c[3])
        : "r"(a[0]), "r"(a[1]), "r"(a[2]), "r"(a[3]), "r"(b[0]), "r"(b[1]));
}
__device__ __forceinline__ uint32_t packh2(float a, float b) {
    __half2 h = __floats2half2_rn(a, b);
    return *(uint32_t*)&h;
}

// ---------------- weight transpose + fp16: W[K,N] -> Wt[N,K] ----------------
__global__ __launch_bounds__(256) void wsplit_kernel(const float* __restrict__ W,
                                                     __half* __restrict__ Wh,
                                                     int K, int N)
{
    __shared__ float tile[32][33];
    int k0 = blockIdx.y * 32, n0 = blockIdx.x * 32;
    int tx = threadIdx.x & 31, ty = threadIdx.x >> 5;
    #pragma unroll
    for (int j = 0; j < 32; j += 8)
        tile[ty + j][tx] = W[(size_t)(k0 + ty + j) * N + n0 + tx];
    __syncthreads();
    #pragma unroll
    for (int j = 0; j < 32; j += 8) {
        Wh[(size_t)(n0 + ty + j) * K + k0 + tx] = __float2half_rn(tile[tx][ty + j]);
    }
}

// ---------------- LayerNorm 1 ----------------
__global__ __launch_bounds__(256) void ln1_kernel(const float* __restrict__ x,
                                                  const float* __restrict__ g,
                                                  const float* __restrict__ b)
{
    int widx = blockIdx.x;
    int win = widx / NTOK, tok = widx - win * NTOK;
    int bb = win / NWIN, rem = win - bb * NWIN;
    int y = (rem / 5) * WS + tok / WS;
    int xx = (rem % 5) * WS + tok % WS;
    size_t ob = (size_t)widx * DIM;
    int tid = threadIdx.x;
    if (y >= 64 || xx >= 64) {
        for (int i = tid; i < DIM; i += 256) g_a[ob + i] = __float2half(0.f);
        return;
    }
    const float* row = x + ((size_t)(bb * 64 + y) * 64 + xx) * DIM;
    float v0 = row[tid], v1 = row[tid + 256], v2 = row[tid + 512];
    float s = v0 + v1 + v2, sq = v0 * v0 + v1 * v1 + v2 * v2;
    #pragma unroll
    for (int off = 16; off; off >>= 1) {
        s  += __shfl_xor_sync(0xffffffffu, s, off);
        sq += __shfl_xor_sync(0xffffffffu, sq, off);
    }
    __shared__ float rs[8], rq[8], smu, srs;
    int wid = tid >> 5, lane = tid & 31;
    if (!lane) { rs[wid] = s; rq[wid] = sq; }
    __syncthreads();
    if (tid == 0) {
        float S = 0, Q = 0;
        #pragma unroll
        for (int i = 0; i < 8; i++) { S += rs[i]; Q += rq[i]; }
        float mu = S * (1.f / 768.f);
        float var = Q * (1.f / 768.f) - mu * mu;
        smu = mu; srs = rsqrtf(var + 1e-5f);
    }
    __syncthreads();
    float mu = smu, r = srs;
    #pragma unroll
    for (int p = 0; p < 3; p++) {
        int i = tid + p * 256;
        float vv = ((p == 0 ? v0 : p == 1 ? v1 : v2) - mu) * r * g[i] + b[i];
        g_a[ob + i] = __float2half_rn(vv);
    }
}

// ---------------- LayerNorm 2 ----------------
__global__ __launch_bounds__(256) void ln2_kernel(const float* __restrict__ g,
                                                  const float* __restrict__ b)
{
    int tid = threadIdx.x;
    const float* row = g_x2 + (size_t)blockIdx.x * DIM;
    size_t ob = (size_t)blockIdx.x * DIM;
    float v0 = row[tid], v1 = row[tid + 256], v2 = row[tid + 512];
    float s = v0 + v1 + v2, sq = v0 * v0 + v1 * v1 + v2 * v2;
    #pragma unroll
    for (int off = 16; off; off >>= 1) {
        s  += __shfl_xor_sync(0xffffffffu, s, off);
        sq += __shfl_xor_sync(0xffffffffu, sq, off);
    }
    __shared__ float rs[8], rq[8], smu, srs;
    int wid = tid >> 5, lane = tid & 31;
    if (!lane) { rs[wid] = s; rq[wid] = sq; }
    __syncthreads();
    if (tid == 0) {
        float S = 0, Q = 0;
        #pragma unroll
        for (int i = 0; i < 8; i++) { S += rs[i]; Q += rq[i]; }
        float mu = S * (1.f / 768.f);
        float var = Q * (1.f / 768.f) - mu * mu;
        smu = mu; srs = rsqrtf(var + 1e-5f);
    }
    __syncthreads();
    float mu = smu, r = srs;
    #pragma unroll
    for (int p = 0; p < 3; p++) {
        int i = tid + p * 256;
        float vv = ((p == 0 ? v0 : p == 1 ? v1 : v2) - mu) * r * g[i] + b[i];
        g_b[ob + i] = __float2half_rn(vv);
    }
}

// ---------------- mma.sync GEMM: 128 threads, 4 warps, warp tile 64x64 ----------------
#define MATB   16384
#define STAGE  (2 * MATB)
#define SMEM_TG (3 * STAGE)

template <int MODE>
__global__ __launch_bounds__(128, 2) void tgemm_kernel(const float* __restrict__ bias,
                                                       const float* __restrict__ aux,
                                                       float* __restrict__ outp)
{
    constexpr int K      = (MODE == 3) ? 3072 : 768;
    constexpr int Mreal  = (MODE <= 1) ? TOKW : TOKX;
    constexpr int NCHUNK = K / 64;
    const __half* gA  = (MODE == 0) ? g_a : (MODE == 1) ? g_ao : (MODE == 2) ? g_b : g_h1;
    const __half* gBh = (MODE == 0) ? g_wqkv_h : (MODE == 1) ? g_wproj_h : (MODE == 2) ? g_w1_h : g_w2_h;

    extern __shared__ char smem_raw[];
    const uint32_t sbase = smem_u32(smem_raw);

    const int t = threadIdx.x;
    const int m0 = blockIdx.y * 128;
    const int n0 = blockIdx.x * 128;
    const int warp = t >> 5, lane = t & 31;
    const int wm = warp >> 1, wn = warp & 1;   // 2x2 warps, tile 64x64

    float acc[4][8][4];
    #pragma unroll
    for (int a = 0; a < 4; a++)
        #pragma unroll
        for (int b2 = 0; b2 < 8; b2++)
            #pragma unroll
            for (int c = 0; c < 4; c++) acc[a][b2][c] = 0.f;

    const int ldrow = t >> 3, ldseg = t & 7;   // 16 rows x 8 segs per pass

    auto issue = [&](int chunk, int stg) {
        const int k0 = chunk * 64;
        const uint32_t so = sbase + (uint32_t)(stg * STAGE);
        #pragma unroll
        for (int p = 0; p < 8; p++) {
            int r = ldrow + p * 16;
            uint32_t off = (uint32_t)(r * 128 + ((ldseg ^ (r & 7)) << 4));
            size_t gaA = (size_t)(m0 + r) * K + k0 + ldseg * 8;
            size_t gaB = (size_t)(n0 + r) * K + k0 + ldseg * 8;
            cp16(so + off, gA + gaA);
            cp16(so + MATB + off, gBh + gaB);
        }
        asm volatile("cp.async.commit_group;" ::: "memory");
    };

    issue(0, 0);
    issue(1, 1);

    const int a_row_in = (lane & 7) + (lane & 8);
    const int a_kg     = lane >> 4;
    const int b_row16  = (lane & 7) + ((lane >> 4) << 3);
    const int b_kg     = (lane >> 3) & 1;

    for (int i = 0; i < NCHUNK; i++) {
        if (i + 1 < NCHUNK)
            asm volatile("cp.async.wait_group 1;" ::: "memory");
        else
            asm volatile("cp.async.wait_group 0;" ::: "memory");
        __syncthreads();
        if (i + 2 < NCHUNK) issue(i + 2, (i + 2) % 3);

        const uint32_t soA = sbase + (uint32_t)((i % 3) * STAGE);
        const uint32_t soB = soA + MATB;
        #pragma unroll
        for (int ks = 0; ks < 4; ks++) {
            uint32_t bh[8][2];
            #pragma unroll
            for (int pr = 0; pr < 4; pr++) {
                int nr = wn * 64 + pr * 16 + b_row16;
                uint32_t bd = soB + (uint32_t)(nr * 128 + (((ks * 2 + b_kg) ^ (nr & 7)) << 4));
                uint32_t r4[4];
                ldsm_x4(r4, bd);
                bh[2 * pr][0] = r4[0]; bh[2 * pr][1] = r4[1];
                bh[2 * pr + 1][0] = r4[2]; bh[2 * pr + 1][1] = r4[3];
            }
            #pragma unroll
            for (int mt = 0; mt < 4; mt++) {
                uint32_t ah[4];
                int mr = wm * 64 + mt * 16 + a_row_in;
                uint32_t ad = soA + (uint32_t)(mr * 128 + (((ks * 2 + a_kg) ^ (mr & 7)) << 4));
                ldsm_x4(ah, ad);
                #pragma unroll
                for (int nt = 0; nt < 8; nt++)
                    mma_f16(acc[mt][nt], ah, bh[nt]);
            }
        }
    }

    // ---- epilogue ----
    const int g = lane >> 2, tq = lane & 3;
    #pragma unroll
    for (int mt = 0; mt < 4; mt++) {
        #pragma unroll
        for (int half = 0; half < 2; half++) {
            int m = m0 + wm * 64 + mt * 16 + g + half * 8;
            bool valid = (m < Mreal);
            int win = 0, tok = 0, yy = 0, xx = 0, bb = 0;
            if (MODE <= 1) {
                win = m / NTOK; tok = m - win * NTOK;
                if (MODE == 1) {
                    bb = win / NWIN; int rem = win - bb * NWIN;
                    yy = (rem / 5) * WS + tok / WS;
                    xx = (rem % 5) * WS + tok % WS;
                    valid = valid && (yy < 64) && (xx < 64);
                }
            }
            if (!valid) continue;
            #pragma unroll
            for (int nt = 0; nt < 8; nt++) {
                int n = n0 + wn * 64 + nt * 8 + 2 * tq;
                float v0 = acc[mt][nt][half * 2]     + bias[n];
                float v1 = acc[mt][nt][half * 2 + 1] + bias[n + 1];
                if (MODE == 0) {
                    int which = n / 768;
                    int dd = n - which * 768;
                    int head = dd >> 6, hd = dd & 63;
                    size_t o = ((size_t)(win * NHEAD + head) * NTOK + tok) * HDIM + hd;
                    if (which == 0) {
                        g_qh[o]     = __float2half_rn(v0 * 0.125f);
                        g_qh[o + 1] = __float2half_rn(v1 * 0.125f);
                    } else if (which == 1) {
                        g_kh[o]     = __float2half_rn(v0);
                        g_kh[o + 1] = __float2half_rn(v1);
                    } else {
                        g_vh[o]     = __float2half_rn(v0);
                        g_vh[o + 1] = __float2half_rn(v1);
                    }
                } else if (MODE == 1) {
                    size_t o = ((size_t)(bb * 64 + yy) * 64 + xx) * DIM + n;
                    g_x2[o]     = aux[o] + v0;
                    g_x2[o + 1] = aux[o + 1] + v1;
                } else if (MODE == 2) {
                    float gl0 = 0.5f * v0 * (1.f + erff(v0 * 0.70710678118f));
                    float gl1 = 0.5f * v1 * (1.f + erff(v1 * 0.70710678118f));
                    size_t o = (size_t)m * 3072 + n;
                    g_h1[o]     = __float2half_rn(gl0);
                    g_h1[o + 1] = __float2half_rn(gl1);
                } else {
                    size_t o = (size_t)m * DIM + n;
                    outp[o]     = v0 + g_x2[o];
                    outp[o + 1] = v1 + g_x2[o + 1];
                }
            }
        }
    }
}

// ---------------- tensor-core attention (unchanged from R14) ----------------
#define ATT_QS_H   0
#define ATT_KS_H   14976
#define ATT_VS_H   29376
#define ATT_F_OFF  88704
#define ATT_B_OFF  90528
#define SM_ATT_TOTAL 91328

__global__ __launch_bounds__(256, 2) void attn_kernel(const float* __restrict__ rel_h,
                                                      const float* __restrict__ rel_w,
                                                      const int* __restrict__ q_idx,
                                                      const int* __restrict__ k_idx)
{
    extern __shared__ char smraw[];
    __half* qs  = (__half*)smraw;
    __half* ksm = qs + ATT_KS_H;
    __half* vsm = qs + ATT_VS_H;
    float* Shf  = (float*)(smraw + ATT_F_OFF);
    float* Swf  = Shf + 196;
    float* rshf = Swf + 196;
    float* rswf = rshf + 32;
    unsigned char* qr8 = (unsigned char*)(smraw + ATT_B_OFF);
    unsigned char* qc8 = qr8 + 196;
    unsigned char* kr8 = qc8 + 196;
    unsigned char* kc8 = kr8 + 196;

    const uint32_t sb = smem_u32(smraw);
    int bh = blockIdx.x;
    int win = bh / NHEAD, head = bh - win * NHEAD;
    int tid = threadIdx.x, warp = tid >> 5, lane = tid & 31;

    const __half* qg = g_qh + (size_t)bh * NTOK * HDIM;
    const __half* kg = g_kh + (size_t)bh * NTOK * HDIM;
    const __half* vg = g_vh + (size_t)bh * NTOK * HDIM;
    for (int i = tid; i < 196 * 8; i += 256) {
        int r = i >> 3, sg = i & 7;
        *(uint4*)(qs  + r * 72 + sg * 8) = *(const uint4*)(qg + r * 64 + sg * 8);
        *(uint4*)(ksm + r * 72 + sg * 8) = *(const uint4*)(kg + r * 64 + sg * 8);
        *(uint4*)(vsm + r * 72 + sg * 8) = *(const uint4*)(vg + r * 64 + sg * 8);
    }
    uint4 z = make_uint4(0, 0, 0, 0);
    for (int i = tid; i < 224; i += 256) {
        if (i < 96)       { int r = 196 + (i >> 3);        *(uint4*)(qs  + r * 72 + (i & 7) * 8) = z; }
        else if (i < 128) { int j = i - 96;  int r = 196 + (j >> 3); *(uint4*)(ksm + r * 72 + (j & 7) * 8) = z; }
        else              { int j = i - 128; int r = 196 + (j >> 3); *(uint4*)(vsm + r * 72 + (j & 7) * 8) = z; }
    }
    if (tid < 27) {
        const float* rp = rel_h + tid * HDIM;
        float s = 0;
        #pragma unroll 8
        for (int c = 0; c < HDIM; c++) s += rp[c];
        rshf[tid] = s;
    } else if (tid >= 32 && tid < 59) {
        const float* rp = rel_w + (tid - 32) * HDIM;
        float s = 0;
        #pragma unroll 8
        for (int c = 0; c < HDIM; c++) s += rp[c];
        rswf[tid - 32] = s;
    }
    if (tid < 196) {
        int qi = q_idx[(size_t)bh * NTOK + tid];
        int ki = k_idx[(size_t)bh * NTOK + tid];
        qr8[tid] = (unsigned char)(qi / WS);
        qc8[tid] = (unsigned char)(qi % WS);
        kr8[tid] = (unsigned char)(ki / WS);
        kc8[tid] = (unsigned char)(ki % WS);
    }
    __syncthreads();
    if (tid < 196) {
        int i = tid / WS, j = tid - i * WS;
        Shf[tid] = rshf[i - j + WS - 1];
        Swf[tid] = rswf[i - j + WS - 1];
    }
    __syncthreads();

    const int g = lane >> 2, tq = lane & 3;
    const int a_row_in = (lane & 7) + (lane & 8);
    const int a_koff   = (lane >> 4) * 8;
    const int b_row_in = lane & 7;
    const int b_koff   = ((lane >> 3) & 1) * 8;
    const uint32_t kbase = sb + ATT_KS_H * 2;
    const uint32_t vbase = sb + ATT_VS_H * 2;

    for (int mt = warp; mt < 13; mt += 8) {
        float sacc[25][4];
        #pragma unroll
        for (int nt = 0; nt < 25; nt++)
            #pragma unroll
            for (int c = 0; c < 4; c++) sacc[nt][c] = 0.f;

        #pragma unroll
        for (int kk = 0; kk < 4; kk++) {
            uint32_t af[4];
            uint32_t qa = sb + (uint32_t)(((mt * 16 + a_row_in) * 72 + kk * 16 + a_koff) * 2);
            ldsm_x4(af, qa);
            #pragma unroll
            for (int nt = 0; nt < 25; nt++) {
                uint32_t bf[2];
                uint32_t ka = kbase + (uint32_t)(((nt * 8 + b_row_in) * 72 + kk * 16 + b_koff) * 2);
                ldsm_x2(bf, ka);
                mma_f16(sacc[nt], af, bf);
            }
        }

        int row0 = mt * 16 + g;
        int row1 = row0 + 8;
        int qb0 = qr8[row0] * WS, qc0 = qc8[row0] * WS;
        int qb1 = qr8[row1] * WS, qc1 = qc8[row1] * WS;
        float mx0 = -1e30f, mx1 = -1e30f;
        #pragma unroll
        for (int nt = 0; nt < 25; nt++) {
            #pragma unroll
            for (int c = 0; c < 2; c++) {
                int col = nt * 8 + tq * 2 + c;
                float s0, s1;
                if (col < 196) {
                    int kr = kr8[col], kc = kc8[col];
                    s0 = sacc[nt][c]     + Shf[qb0 + kr] + Swf[qc0 + kc];
                    s1 = sacc[nt][2 + c] + Shf[qb1 + kr] + Swf[qc1 + kc];
                } else {
                    s0 = -1e30f; s1 = -1e30f;
                }
                sacc[nt][c] = s0; sacc[nt][2 + c] = s1;
                mx0 = fmaxf(mx0, s0); mx1 = fmaxf(mx1, s1);
            }
        }
        mx0 = fmaxf(mx0, __shfl_xor_sync(0xffffffffu, mx0, 1));
        mx0 = fmaxf(mx0, __shfl_xor_sync(0xffffffffu, mx0, 2));
        mx1 = fmaxf(mx1, __shfl_xor_sync(0xffffffffu, mx1, 1));
        mx1 = fmaxf(mx1, __shfl_xor_sync(0xffffffffu, mx1, 2));

        float sm0 = 0.f, sm1 = 0.f;
        uint32_t pf[13][4];
        #pragma unroll
        for (int nt = 0; nt < 25; nt++) {
            float e00 = expf(sacc[nt][0] - mx0);
            float e01 = expf(sacc[nt][1] - mx0);
            float e10 = expf(sacc[nt][2] - mx1);
            float e11 = expf(sacc[nt][3] - mx1);
            sm0 += e00 + e01;
            sm1 += e10 + e11;
            int kt = nt >> 1, hi = nt & 1;
            pf[kt][hi * 2 + 0] = packh2(e00, e01);
            pf[kt][hi * 2 + 1] = packh2(e10, e11);
        }
        pf[12][2] = 0u; pf[12][3] = 0u;
        sm0 += __shfl_xor_sync(0xffffffffu, sm0, 1);
        sm0 += __shfl_xor_sync(0xffffffffu, sm0, 2);
        sm1 += __shfl_xor_sync(0xffffffffu, sm1, 1);
        sm1 += __shfl_xor_sync(0xffffffffu, sm1, 2);
        float inv0 = 1.f / sm0, inv1 = 1.f / sm1;

        float oacc[8][4];
        #pragma unroll
        for (int dt = 0; dt < 8; dt++)
            #pragma unroll
            for (int c = 0; c < 4; c++) oacc[dt][c] = 0.f;
        #pragma unroll
        for (int kt = 0; kt < 13; kt++) {
            #pragma unroll
            for (int dt = 0; dt < 8; dt++) {
                uint32_t bf[2];
                uint32_t va = vbase + (uint32_t)(((kt * 16 + (lane & 15)) * 72 + dt * 8) * 2);
                ldsm_x2t(bf, va);
                mma_f16(oacc[dt], pf[kt], bf);
            }
        }

        bool ok0 = row0 < NTOK, ok1 = row1 < NTOK;
        size_t ob0 = ((size_t)(win * NTOK) + row0) * DIM + head * HDIM;
        #pragma unroll
        for (int dt = 0; dt < 8; dt++) {
            int d = dt * 8 + tq * 2;
            if (ok0) {
                __half2 hv = __floats2half2_rn(oacc[dt][0] * inv0, oacc[dt][1] * inv0);
                *(__half2*)(g_ao + ob0 + d) = hv;
            }
            if (ok1) {
                __half2 hv = __floats2half2_rn(oacc[dt][2] * inv1, oacc[dt][3] * inv1);
                *(__half2*)(g_ao + ob0 + (size_t)8 * DIM + d) = hv;
            }
        }
    }
}

// ---------------- launch ----------------
extern "C" void kernel_launch(void* const* d_in, const int* in_sizes, int n_in,
                              void* d_out, int out_size)
{
    const float* x     = (const float*)d_in[0];
    const int*   qidx  = (const int*)d_in[1];
    const int*   kidx  = (const int*)d_in[2];
    const float* ln1w  = (const float*)d_in[3];
    const float* ln1b  = (const float*)d_in[4];
    const float* ln2w  = (const float*)d_in[5];
    const float* ln2b  = (const float*)d_in[6];
    const float* qkvw  = (const float*)d_in[7];
    const float* qkvb  = (const float*)d_in[8];
    const float* projw = (const float*)d_in[9];
    const float* projb = (const float*)d_in[10];
    const float* relh  = (const float*)d_in[11];
    const float* relw  = (const float*)d_in[12];
    const float* w1    = (const float*)d_in[13];
    const float* b1    = (const float*)d_in[14];
    const float* w2    = (const float*)d_in[15];
    const float* b2    = (const float*)d_in[16];
    float* out = (float*)d_out;

    cudaFuncSetAttribute(attn_kernel, cudaFuncAttributeMaxDynamicSharedMemorySize, SM_ATT_TOTAL);
    cudaFuncSetAttribute(tgemm_kernel<0>, cudaFuncAttributeMaxDynamicSharedMemorySize, SMEM_TG);
    cudaFuncSetAttribute(tgemm_kernel<1>, cudaFuncAttributeMaxDynamicSharedMemorySize, SMEM_TG);
    cudaFuncSetAttribute(tgemm_kernel<2>, cudaFuncAttributeMaxDynamicSharedMemorySize, SMEM_TG);
    cudaFuncSetAttribute(tgemm_kernel<3>, cudaFuncAttributeMaxDynamicSharedMemorySize, SMEM_TG);

    __half *wqkv_h, *wproj_h, *w1_h, *w2_h;
    cudaGetSymbolAddress((void**)&wqkv_h, g_wqkv_h);
    cudaGetSymbolAddress((void**)&wproj_h, g_wproj_h);
    cudaGetSymbolAddress((void**)&w1_h, g_w1_h);
    cudaGetSymbolAddress((void**)&w2_h, g_w2_h);

    // launch index 3 = tgemm<0> (ncu profiles it)
    wsplit_kernel<<<dim3(2304 / 32, 768 / 32), 256>>>(qkvw, wqkv_h, 768, 2304);           // 0
    wsplit_kernel<<<dim3(3072 / 32, 768 / 32), 256>>>(w1, w1_h, 768, 3072);                // 1
    ln1_kernel<<<TOKW, 256>>>(x, ln1w, ln1b);                                              // 2
    tgemm_kernel<0><<<dim3(2304 / 128, TOKW_PAD / 128), 128, SMEM_TG>>>(qkvb, nullptr, nullptr); // 3
    attn_kernel<<<BH, 256, SM_ATT_TOTAL>>>(relh, relw, qidx, kidx);                        // 4
    wsplit_kernel<<<dim3(768 / 32, 768 / 32), 256>>>(projw, wproj_h, 768, 768);            // 5
    tgemm_kernel<1><<<dim3(768 / 128, TOKW_PAD / 128), 128, SMEM_TG>>>(projb, x, nullptr); // 6
    ln2_kernel<<<TOKX, 256>>>(ln2w, ln2b);                                                 // 7
    wsplit_kernel<<<dim3(768 / 32, 3072 / 32), 256>>>(w2, w2_h, 3072, 768);                // 8
    tgemm_kernel<2><<<dim3(3072 / 128, TOKX / 128), 128, SMEM_TG>>>(b1, nullptr, nullptr); // 9
    tgemm_kernel<3><<<dim3(768 / 128, TOKX / 128), 128, SMEM_TG>>>(b2, nullptr, out);      // 10
}

// round 16
// speedup vs baseline: 4.0632x; 1.1317x over previous
/*
 * R16: R15 + merged single wsplit kernel (was 4 launches) + vectorized
 * (half2/float2) GEMM epilogue stores + hoisted qkv region decode.
 * Numerics identical (rel_err expected 1.4429e-4).
 */
#include <cuda_runtime.h>
#include <cuda_fp16.h>
#include <math.h>
#include <stdint.h>

#define DIM   768
#define NHEAD 12
#define HDIM  64
#define WS    14
#define NTOK  196
#define NWIN  25
#define BATCH 8
#define NWB   200
#define TOKW  39200
#define TOKW_PAD 39296
#define TOKX  32768
#define BH    2400

// ---------------- device scratch ----------------
__device__ __half g_a[(size_t)TOKW_PAD * DIM];
__device__ __half g_ao[(size_t)TOKW_PAD * DIM];
__device__ __half g_b[(size_t)TOKX * DIM];
__device__ __half g_h1[(size_t)TOKX * 3072];
__device__ __half g_wqkv_h[(size_t)2304 * 768];
__device__ __half g_wproj_h[(size_t)768 * 768];
__device__ __half g_w1_h[(size_t)3072 * 768];
__device__ __half g_w2_h[(size_t)768 * 3072];
__device__ __half g_qh[(size_t)BH * NTOK * HDIM];
__device__ __half g_kh[(size_t)BH * NTOK * HDIM];
__device__ __half g_vh[(size_t)BH * NTOK * HDIM];
__device__ float g_x2[(size_t)TOKX * DIM];

// ---------------- PTX helpers ----------------
__device__ __forceinline__ uint32_t smem_u32(const void* p) {
    uint32_t a;
    asm("{ .reg .u64 t; cvta.to.shared.u64 t, %1; cvt.u32.u64 %0, t; }" : "=r"(a) : "l"(p));
    return a;
}
__device__ __forceinline__ void cp16(uint32_t dst, const void* src) {
    asm volatile("cp.async.cg.shared.global [%0], [%1], 16;" :: "r"(dst), "l"(src));
}
__device__ __forceinline__ void ldsm_x4(uint32_t* r, uint32_t addr) {
    asm volatile("ldmatrix.sync.aligned.m8n8.x4.shared.b16 {%0,%1,%2,%3}, [%4];"
        : "=r"(r[0]), "=r"(r[1]), "=r"(r[2]), "=r"(r[3]) : "r"(addr));
}
__device__ __forceinline__ void ldsm_x2(uint32_t* r, uint32_t addr) {
    asm volatile("ldmatrix.sync.aligned.m8n8.x2.shared.b16 {%0,%1}, [%2];"
        : "=r"(r[0]), "=r"(r[1]) : "r"(addr));
}
__device__ __forceinline__ void ldsm_x2t(uint32_t* r, uint32_t addr) {
    asm volatile("ldmatrix.sync.aligned.m8n8.x2.trans.shared.b16 {%0,%1}, [%2];"
        : "=r"(r[0]), "=r"(r[1]) : "r"(addr));
}
__device__ __forceinline__ void mma_f16(float* c, const uint32_t* a, const uint32_t* b) {
    asm volatile(
        "mma.sync.aligned.m16n8k16.row.col.f32.f16.f16.f32 "
        "{%0,%1,%2,%3}, {%4,%5,%6,%7}, {%8,%9}, {%0,%1,%2,%3};"
        : "+f"(c[0]), "+f"(c[1]), "+f"(c[2]), "+f"(c[3])
        : "r"(a[0]), "r"(a[1]), "r"(a[2]), "r"(a[3]), "r"(b[0]), "r"(b[1]));
}
__device__ __forceinline__ uint32_t packh2(float a, float b) {
    __half2 h = __floats2half2_rn(a, b);
    return *(uint32_t*)&h;
}

// ---------------- merged weight transpose (all 4 weights, one launch) ----------------
// tiles: qkv 72x24=1728, proj 24x24=576, w1 96x24=2304, w2 24x96=2304 -> 6912
__global__ __launch_bounds__(256) void wsplit_all(const float* __restrict__ Wqkv,
                                                  const float* __restrict__ Wproj,
                                                  const float* __restrict__ W1,
                                                  const float* __restrict__ W2)
{
    __shared__ float tile[32][33];
    int bid = blockIdx.x;
    const float* W; __half* Dst; int K, N, tilesX, tloc;
    if (bid < 1728)      { W = Wqkv;  Dst = g_wqkv_h;  K = 768;  N = 2304; tilesX = 72; tloc = bid; }
    else if (bid < 2304) { W = Wproj; Dst = g_wproj_h; K = 768;  N = 768;  tilesX = 24; tloc = bid - 1728; }
    else if (bid < 4608) { W = W1;    Dst = g_w1_h;    K = 768;  N = 3072; tilesX = 96; tloc = bid - 2304; }
    else                 { W = W2;    Dst = g_w2_h;    K = 3072; N = 768;  tilesX = 24; tloc = bid - 4608; }
    int tix = tloc % tilesX, tiy = tloc / tilesX;
    int k0 = tiy * 32, n0 = tix * 32;
    int tx = threadIdx.x & 31, ty = threadIdx.x >> 5;
    #pragma unroll
    for (int j = 0; j < 32; j += 8)
        tile[ty + j][tx] = W[(size_t)(k0 + ty + j) * N + n0 + tx];
    __syncthreads();
    #pragma unroll
    for (int j = 0; j < 32; j += 8)
        Dst[(size_t)(n0 + ty + j) * K + k0 + tx] = __float2half_rn(tile[tx][ty + j]);
}

// ---------------- LayerNorm 1 ----------------
__global__ __launch_bounds__(256) void ln1_kernel(const float* __restrict__ x,
                                                  const float* __restrict__ g,
                                                  const float* __restrict__ b)
{
    int widx = blockIdx.x;
    int win = widx / NTOK, tok = widx - win * NTOK;
    int bb = win / NWIN, rem = win - bb * NWIN;
    int y = (rem / 5) * WS + tok / WS;
    int xx = (rem % 5) * WS + tok % WS;
    size_t ob = (size_t)widx * DIM;
    int tid = threadIdx.x;
    if (y >= 64 || xx >= 64) {
        for (int i = tid; i < DIM; i += 256) g_a[ob + i] = __float2half(0.f);
        return;
    }
    const float* row = x + ((size_t)(bb * 64 + y) * 64 + xx) * DIM;
    float v0 = row[tid], v1 = row[tid + 256], v2 = row[tid + 512];
    float s = v0 + v1 + v2, sq = v0 * v0 + v1 * v1 + v2 * v2;
    #pragma unroll
    for (int off = 16; off; off >>= 1) {
        s  += __shfl_xor_sync(0xffffffffu, s, off);
        sq += __shfl_xor_sync(0xffffffffu, sq, off);
    }
    __shared__ float rs[8], rq[8], smu, srs;
    int wid = tid >> 5, lane = tid & 31;
    if (!lane) { rs[wid] = s; rq[wid] = sq; }
    __syncthreads();
    if (tid == 0) {
        float S = 0, Q = 0;
        #pragma unroll
        for (int i = 0; i < 8; i++) { S += rs[i]; Q += rq[i]; }
        float mu = S * (1.f / 768.f);
        float var = Q * (1.f / 768.f) - mu * mu;
        smu = mu; srs = rsqrtf(var + 1e-5f);
    }
    __syncthreads();
    float mu = smu, r = srs;
    #pragma unroll
    for (int p = 0; p < 3; p++) {
        int i = tid + p * 256;
        float vv = ((p == 0 ? v0 : p == 1 ? v1 : v2) - mu) * r * g[i] + b[i];
        g_a[ob + i] = __float2half_rn(vv);
    }
}

// ---------------- LayerNorm 2 ----------------
__global__ __launch_bounds__(256) void ln2_kernel(const float* __restrict__ g,
                                                  const float* __restrict__ b)
{
    int tid = threadIdx.x;
    const float* row = g_x2 + (size_t)blockIdx.x * DIM;
    size_t ob = (size_t)blockIdx.x * DIM;
    float v0 = row[tid], v1 = row[tid + 256], v2 = row[tid + 512];
    float s = v0 + v1 + v2, sq = v0 * v0 + v1 * v1 + v2 * v2;
    #pragma unroll
    for (int off = 16; off; off >>= 1) {
        s  += __shfl_xor_sync(0xffffffffu, s, off);
        sq += __shfl_xor_sync(0xffffffffu, sq, off);
    }
    __shared__ float rs[8], rq[8], smu, srs;
    int wid = tid >> 5, lane = tid & 31;
    if (!lane) { rs[wid] = s; rq[wid] = sq; }
    __syncthreads();
    if (tid == 0) {
        float S = 0, Q = 0;
        #pragma unroll
        for (int i = 0; i < 8; i++) { S += rs[i]; Q += rq[i]; }
        float mu = S * (1.f / 768.f);
        float var = Q * (1.f / 768.f) - mu * mu;
        smu = mu; srs = rsqrtf(var + 1e-5f);
    }
    __syncthreads();
    float mu = smu, r = srs;
    #pragma unroll
    for (int p = 0; p < 3; p++) {
        int i = tid + p * 256;
        float vv = ((p == 0 ? v0 : p == 1 ? v1 : v2) - mu) * r * g[i] + b[i];
        g_b[ob + i] = __float2half_rn(vv);
    }
}

// ---------------- mma.sync GEMM: 128 threads, 4 warps, warp tile 64x64 ----------------
#define MATB   16384
#define STAGE  (2 * MATB)
#define SMEM_TG (3 * STAGE)

template <int MODE>
__global__ __launch_bounds__(128, 2) void tgemm_kernel(const float* __restrict__ bias,
                                                       const float* __restrict__ aux,
                                                       float* __restrict__ outp)
{
    constexpr int K      = (MODE == 3) ? 3072 : 768;
    constexpr int Mreal  = (MODE <= 1) ? TOKW : TOKX;
    constexpr int NCHUNK = K / 64;
    const __half* gA  = (MODE == 0) ? g_a : (MODE == 1) ? g_ao : (MODE == 2) ? g_b : g_h1;
    const __half* gBh = (MODE == 0) ? g_wqkv_h : (MODE == 1) ? g_wproj_h : (MODE == 2) ? g_w1_h : g_w2_h;

    extern __shared__ char smem_raw[];
    const uint32_t sbase = smem_u32(smem_raw);

    const int t = threadIdx.x;
    const int m0 = blockIdx.y * 128;
    const int n0 = blockIdx.x * 128;
    const int warp = t >> 5, lane = t & 31;
    const int wm = warp >> 1, wn = warp & 1;

    float acc[4][8][4];
    #pragma unroll
    for (int a = 0; a < 4; a++)
        #pragma unroll
        for (int b2 = 0; b2 < 8; b2++)
            #pragma unroll
            for (int c = 0; c < 4; c++) acc[a][b2][c] = 0.f;

    const int ldrow = t >> 3, ldseg = t & 7;

    auto issue = [&](int chunk, int stg) {
        const int k0 = chunk * 64;
        const uint32_t so = sbase + (uint32_t)(stg * STAGE);
        #pragma unroll
        for (int p = 0; p < 8; p++) {
            int r = ldrow + p * 16;
            uint32_t off = (uint32_t)(r * 128 + ((ldseg ^ (r & 7)) << 4));
            size_t gaA = (size_t)(m0 + r) * K + k0 + ldseg * 8;
            size_t gaB = (size_t)(n0 + r) * K + k0 + ldseg * 8;
            cp16(so + off, gA + gaA);
            cp16(so + MATB + off, gBh + gaB);
        }
        asm volatile("cp.async.commit_group;" ::: "memory");
    };

    issue(0, 0);
    issue(1, 1);

    const int a_row_in = (lane & 7) + (lane & 8);
    const int a_kg     = lane >> 4;
    const int b_row16  = (lane & 7) + ((lane >> 4) << 3);
    const int b_kg     = (lane >> 3) & 1;

    for (int i = 0; i < NCHUNK; i++) {
        if (i + 1 < NCHUNK)
            asm volatile("cp.async.wait_group 1;" ::: "memory");
        else
            asm volatile("cp.async.wait_group 0;" ::: "memory");
        __syncthreads();
        if (i + 2 < NCHUNK) issue(i + 2, (i + 2) % 3);

        const uint32_t soA = sbase + (uint32_t)((i % 3) * STAGE);
        const uint32_t soB = soA + MATB;
        #pragma unroll
        for (int ks = 0; ks < 4; ks++) {
            uint32_t bh[8][2];
            #pragma unroll
            for (int pr = 0; pr < 4; pr++) {
                int nr = wn * 64 + pr * 16 + b_row16;
                uint32_t bd = soB + (uint32_t)(nr * 128 + (((ks * 2 + b_kg) ^ (nr & 7)) << 4));
                uint32_t r4[4];
                ldsm_x4(r4, bd);
                bh[2 * pr][0] = r4[0]; bh[2 * pr][1] = r4[1];
                bh[2 * pr + 1][0] = r4[2]; bh[2 * pr + 1][1] = r4[3];
            }
            #pragma unroll
            for (int mt = 0; mt < 4; mt++) {
                uint32_t ah[4];
                int mr = wm * 64 + mt * 16 + a_row_in;
                uint32_t ad = soA + (uint32_t)(mr * 128 + (((ks * 2 + a_kg) ^ (mr & 7)) << 4));
                ldsm_x4(ah, ad);
                #pragma unroll
                for (int nt = 0; nt < 8; nt++)
                    mma_f16(acc[mt][nt], ah, bh[nt]);
            }
        }
    }

    // ---- epilogue (vectorized stores) ----
    const int g = lane >> 2, tq = lane & 3;
    // MODE 0: which-region constant per CTA (768 % 128 == 0)
    const int which0 = (MODE == 0) ? (n0 / 768) : 0;
    #pragma unroll
    for (int mt = 0; mt < 4; mt++) {
        #pragma unroll
        for (int half = 0; half < 2; half++) {
            int m = m0 + wm * 64 + mt * 16 + g + half * 8;
            bool valid = (m < Mreal);
            int win = 0, tok = 0, yy = 0, xx = 0, bb = 0;
            if (MODE <= 1) {
                win = m / NTOK; tok = m - win * NTOK;
                if (MODE == 1) {
                    bb = win / NWIN; int rem = win - bb * NWIN;
                    yy = (rem / 5) * WS + tok / WS;
                    xx = (rem % 5) * WS + tok % WS;
                    valid = valid && (yy < 64) && (xx < 64);
                }
            }
            if (!valid) continue;
            #pragma unroll
            for (int nt = 0; nt < 8; nt++) {
                int n = n0 + wn * 64 + nt * 8 + 2 * tq;
                float v0 = acc[mt][nt][half * 2]     + bias[n];
                float v1 = acc[mt][nt][half * 2 + 1] + bias[n + 1];
                if (MODE == 0) {
                    int dd = n - which0 * 768;
                    int head = dd >> 6, hd = dd & 63;
                    size_t o = ((size_t)(win * NHEAD + head) * NTOK + tok) * HDIM + hd;
                    if (which0 == 0)
                        *(__half2*)(g_qh + o) = __floats2half2_rn(v0 * 0.125f, v1 * 0.125f);
                    else if (which0 == 1)
                        *(__half2*)(g_kh + o) = __floats2half2_rn(v0, v1);
                    else
                        *(__half2*)(g_vh + o) = __floats2half2_rn(v0, v1);
                } else if (MODE == 1) {
                    size_t o = ((size_t)(bb * 64 + yy) * 64 + xx) * DIM + n;
                    float2 ax = *(const float2*)(aux + o);
                    float2 r2 = make_float2(ax.x + v0, ax.y + v1);
                    *(float2*)(g_x2 + o) = r2;
                } else if (MODE == 2) {
                    float gl0 = 0.5f * v0 * (1.f + erff(v0 * 0.70710678118f));
                    float gl1 = 0.5f * v1 * (1.f + erff(v1 * 0.70710678118f));
                    size_t o = (size_t)m * 3072 + n;
                    *(__half2*)(g_h1 + o) = __floats2half2_rn(gl0, gl1);
                } else {
                    size_t o = (size_t)m * DIM + n;
                    float2 x2 = *(const float2*)(g_x2 + o);
                    *(float2*)(outp + o) = make_float2(v0 + x2.x, v1 + x2.y);
                }
            }
        }
    }
}

// ---------------- tensor-core attention (unchanged) ----------------
#define ATT_QS_H   0
#define ATT_KS_H   14976
#define ATT_VS_H   29376
#define ATT_F_OFF  88704
#define ATT_B_OFF  90528
#define SM_ATT_TOTAL 91328

__global__ __launch_bounds__(256, 2) void attn_kernel(const float* __restrict__ rel_h,
                                                      const float* __restrict__ rel_w,
                                                      const int* __restrict__ q_idx,
                                                      const int* __restrict__ k_idx)
{
    extern __shared__ char smraw[];
    __half* qs  = (__half*)smraw;
    __half* ksm = qs + ATT_KS_H;
    __half* vsm = qs + ATT_VS_H;
    float* Shf  = (float*)(smraw + ATT_F_OFF);
    float* Swf  = Shf + 196;
    float* rshf = Swf + 196;
    float* rswf = rshf + 32;
    unsigned char* qr8 = (unsigned char*)(smraw + ATT_B_OFF);
    unsigned char* qc8 = qr8 + 196;
    unsigned char* kr8 = qc8 + 196;
    unsigned char* kc8 = kr8 + 196;

    const uint32_t sb = smem_u32(smraw);
    int bh = blockIdx.x;
    int win = bh / NHEAD, head = bh - win * NHEAD;
    int tid = threadIdx.x, warp = tid >> 5, lane = tid & 31;

    const __half* qg = g_qh + (size_t)bh * NTOK * HDIM;
    const __half* kg = g_kh + (size_t)bh * NTOK * HDIM;
    const __half* vg = g_vh + (size_t)bh * NTOK * HDIM;
    for (int i = tid; i < 196 * 8; i += 256) {
        int r = i >> 3, sg = i & 7;
        *(uint4*)(qs  + r * 72 + sg * 8) = *(const uint4*)(qg + r * 64 + sg * 8);
        *(uint4*)(ksm + r * 72 + sg * 8) = *(const uint4*)(kg + r * 64 + sg * 8);
        *(uint4*)(vsm + r * 72 + sg * 8) = *(const uint4*)(vg + r * 64 + sg * 8);
    }
    uint4 z = make_uint4(0, 0, 0, 0);
    for (int i = tid; i < 224; i += 256) {
        if (i < 96)       { int r = 196 + (i >> 3);        *(uint4*)(qs  + r * 72 + (i & 7) * 8) = z; }
        else if (i < 128) { int j = i - 96;  int r = 196 + (j >> 3); *(uint4*)(ksm + r * 72 + (j & 7) * 8) = z; }
        else              { int j = i - 128; int r = 196 + (j >> 3); *(uint4*)(vsm + r * 72 + (j & 7) * 8) = z; }
    }
    if (tid < 27) {
        const float* rp = rel_h + tid * HDIM;
        float s = 0;
        #pragma unroll 8
        for (int c = 0; c < HDIM; c++) s += rp[c];
        rshf[tid] = s;
    } else if (tid >= 32 && tid < 59) {
        const float* rp = rel_w + (tid - 32) * HDIM;
        float s = 0;
        #pragma unroll 8
        for (int c = 0; c < HDIM; c++) s += rp[c];
        rswf[tid - 32] = s;
    }
    if (tid < 196) {
        int qi = q_idx[(size_t)bh * NTOK + tid];
        int ki = k_idx[(size_t)bh * NTOK + tid];
        qr8[tid] = (unsigned char)(qi / WS);
        qc8[tid] = (unsigned char)(qi % WS);
        kr8[tid] = (unsigned char)(ki / WS);
        kc8[tid] = (unsigned char)(ki % WS);
    }
    __syncthreads();
    if (tid < 196) {
        int i = tid / WS, j = tid - i * WS;
        Shf[tid] = rshf[i - j + WS - 1];
        Swf[tid] = rswf[i - j + WS - 1];
    }
    __syncthreads();

    const int g = lane >> 2, tq = lane & 3;
    const int a_row_in = (lane & 7) + (lane & 8);
    const int a_koff   = (lane >> 4) * 8;
    const int b_row_in = lane & 7;
    const int b_koff   = ((lane >> 3) & 1) * 8;
    const uint32_t kbase = sb + ATT_KS_H * 2;
    const uint32_t vbase = sb + ATT_VS_H * 2;

    for (int mt = warp; mt < 13; mt += 8) {
        float sacc[25][4];
        #pragma unroll
        for (int nt = 0; nt < 25; nt++)
            #pragma unroll
            for (int c = 0; c < 4; c++) sacc[nt][c] = 0.f;

        #pragma unroll
        for (int kk = 0; kk < 4; kk++) {
            uint32_t af[4];
            uint32_t qa = sb + (uint32_t)(((mt * 16 + a_row_in) * 72 + kk * 16 + a_koff) * 2);
            ldsm_x4(af, qa);
            #pragma unroll
            for (int nt = 0; nt < 25; nt++) {
                uint32_t bf[2];
                uint32_t ka = kbase + (uint32_t)(((nt * 8 + b_row_in) * 72 + kk * 16 + b_koff) * 2);
                ldsm_x2(bf, ka);
                mma_f16(sacc[nt], af, bf);
            }
        }

        int row0 = mt * 16 + g;
        int row1 = row0 + 8;
        int qb0 = qr8[row0] * WS, qc0 = qc8[row0] * WS;
        int qb1 = qr8[row1] * WS, qc1 = qc8[row1] * WS;
        float mx0 = -1e30f, mx1 = -1e30f;
        #pragma unroll
        for (int nt = 0; nt < 25; nt++) {
            #pragma unroll
            for (int c = 0; c < 2; c++) {
                int col = nt * 8 + tq * 2 + c;
                float s0, s1;
                if (col < 196) {
                    int kr = kr8[col], kc = kc8[col];
                    s0 = sacc[nt][c]     + Shf[qb0 + kr] + Swf[qc0 + kc];
                    s1 = sacc[nt][2 + c] + Shf[qb1 + kr] + Swf[qc1 + kc];
                } else {
                    s0 = -1e30f; s1 = -1e30f;
                }
                sacc[nt][c] = s0; sacc[nt][2 + c] = s1;
                mx0 = fmaxf(mx0, s0); mx1 = fmaxf(mx1, s1);
            }
        }
        mx0 = fmaxf(mx0, __shfl_xor_sync(0xffffffffu, mx0, 1));
        mx0 = fmaxf(mx0, __shfl_xor_sync(0xffffffffu, mx0, 2));
        mx1 = fmaxf(mx1, __shfl_xor_sync(0xffffffffu, mx1, 1));
        mx1 = fmaxf(mx1, __shfl_xor_sync(0xffffffffu, mx1, 2));

        float sm0 = 0.f, sm1 = 0.f;
        uint32_t pf[13][4];
        #pragma unroll
        for (int nt = 0; nt < 25; nt++) {
            float e00 = expf(sacc[nt][0] - mx0);
            float e01 = expf(sacc[nt][1] - mx0);
            float e10 = expf(sacc[nt][2] - mx1);
            float e11 = expf(sacc[nt][3] - mx1);
            sm0 += e00 + e01;
            sm1 += e10 + e11;
            int kt = nt >> 1, hi = nt & 1;
            pf[kt][hi * 2 + 0] = packh2(e00, e01);
            pf[kt][hi * 2 + 1] = packh2(e10, e11);
        }
        pf[12][2] = 0u; pf[12][3] = 0u;
        sm0 += __shfl_xor_sync(0xffffffffu, sm0, 1);
        sm0 += __shfl_xor_sync(0xffffffffu, sm0, 2);
        sm1 += __shfl_xor_sync(0xffffffffu, sm1, 1);
        sm1 += __shfl_xor_sync(0xffffffffu, sm1, 2);
        float inv0 = 1.f / sm0, inv1 = 1.f / sm1;

        float oacc[8][4];
        #pragma unroll
        for (int dt = 0; dt < 8; dt++)
            #pragma unroll
            for (int c = 0; c < 4; c++) oacc[dt][c] = 0.f;
        #pragma unroll
        for (int kt = 0; kt < 13; kt++) {
            #pragma unroll
            for (int dt = 0; dt < 8; dt++) {
                uint32_t bf[2];
                uint32_t va = vbase + (uint32_t)(((kt * 16 + (lane & 15)) * 72 + dt * 8) * 2);
                ldsm_x2t(bf, va);
                mma_f16(oacc[dt], pf[kt], bf);
            }
        }

        bool ok0 = row0 < NTOK, ok1 = row1 < NTOK;
        size_t ob0 = ((size_t)(win * NTOK) + row0) * DIM + head * HDIM;
        #pragma unroll
        for (int dt = 0; dt < 8; dt++) {
            int d = dt * 8 + tq * 2;
            if (ok0) {
                *(__half2*)(g_ao + ob0 + d) = __floats2half2_rn(oacc[dt][0] * inv0, oacc[dt][1] * inv0);
            }
            if (ok1) {
                *(__half2*)(g_ao + ob0 + (size_t)8 * DIM + d) = __floats2half2_rn(oacc[dt][2] * inv1, oacc[dt][3] * inv1);
            }
        }
    }
}

// ---------------- launch ----------------
extern "C" void kernel_launch(void* const* d_in, const int* in_sizes, int n_in,
                              void* d_out, int out_size)
{
    const float* x     = (const float*)d_in[0];
    const int*   qidx  = (const int*)d_in[1];
    const int*   kidx  = (const int*)d_in[2];
    const float* ln1w  = (const float*)d_in[3];
    const float* ln1b  = (const float*)d_in[4];
    const float* ln2w  = (const float*)d_in[5];
    const float* ln2b  = (const float*)d_in[6];
    const float* qkvw  = (const float*)d_in[7];
    const float* qkvb  = (const float*)d_in[8];
    const float* projw = (const float*)d_in[9];
    const float* projb = (const float*)d_in[10];
    const float* relh  = (const float*)d_in[11];
    const float* relw  = (const float*)d_in[12];
    const float* w1    = (const float*)d_in[13];
    const float* b1    = (const float*)d_in[14];
    const float* w2    = (const float*)d_in[15];
    const float* b2    = (const float*)d_in[16];
    float* out = (float*)d_out;

    cudaFuncSetAttribute(attn_kernel, cudaFuncAttributeMaxDynamicSharedMemorySize, SM_ATT_TOTAL);
    cudaFuncSetAttribute(tgemm_kernel<0>, cudaFuncAttributeMaxDynamicSharedMemorySize, SMEM_TG);
    cudaFuncSetAttribute(tgemm_kernel<1>, cudaFuncAttributeMaxDynamicSharedMemorySize, SMEM_TG);
    cudaFuncSetAttribute(tgemm_kernel<2>, cudaFuncAttributeMaxDynamicSharedMemorySize, SMEM_TG);
    cudaFuncSetAttribute(tgemm_kernel<3>, cudaFuncAttributeMaxDynamicSharedMemorySize, SMEM_TG);

    // launch index 3 = tgemm<0> (ncu profiles it)
    wsplit_all<<<6912, 256>>>(qkvw, projw, w1, w2);                                        // 0
    ln1_kernel<<<TOKW, 256>>>(x, ln1w, ln1b);                                              // 1
    tgemm_kernel<0><<<dim3(2304 / 128, TOKW_PAD / 128), 128, SMEM_TG>>>(qkvb, nullptr, nullptr); // 2
    attn_kernel<<<BH, 256, SM_ATT_TOTAL>>>(relh, relw, qidx, kidx);                        // 3
    tgemm_kernel<1><<<dim3(768 / 128, TOKW_PAD / 128), 128, SMEM_TG>>>(projb, x, nullptr); // 4
    ln2_kernel<<<TOKX, 256>>>(ln2w, ln2b);                                                 // 5
    tgemm_kernel<2><<<dim3(3072 / 128, TOKX / 128), 128, SMEM_TG>>>(b1, nullptr, nullptr); // 6
    tgemm_kernel<3><<<dim3(768 / 128, TOKX / 128), 128, SMEM_TG>>>(b2, nullptr, out);      // 7
}

// round 17
// speedup vs baseline: 4.0694x; 1.0015x over previous
/*
 * R17: attention LDSM halved — K fragments via paired ldsm.x4 (two n-tiles
 * per instr) and V fragments via ldsm.x4.trans (two d-tiles per instr).
 * Everything else identical to R16; rel_err must stay 1.4429e-4.
 */
#include <cuda_runtime.h>
#include <cuda_fp16.h>
#include <math.h>
#include <stdint.h>

#define DIM   768
#define NHEAD 12
#define HDIM  64
#define WS    14
#define NTOK  196
#define NWIN  25
#define BATCH 8
#define NWB   200
#define TOKW  39200
#define TOKW_PAD 39296
#define TOKX  32768
#define BH    2400

// ---------------- device scratch ----------------
__device__ __half g_a[(size_t)TOKW_PAD * DIM];
__device__ __half g_ao[(size_t)TOKW_PAD * DIM];
__device__ __half g_b[(size_t)TOKX * DIM];
__device__ __half g_h1[(size_t)TOKX * 3072];
__device__ __half g_wqkv_h[(size_t)2304 * 768];
__device__ __half g_wproj_h[(size_t)768 * 768];
__device__ __half g_w1_h[(size_t)3072 * 768];
__device__ __half g_w2_h[(size_t)768 * 3072];
__device__ __half g_qh[(size_t)BH * NTOK * HDIM];
__device__ __half g_kh[(size_t)BH * NTOK * HDIM];
__device__ __half g_vh[(size_t)BH * NTOK * HDIM];
__device__ float g_x2[(size_t)TOKX * DIM];

// ---------------- PTX helpers ----------------
__device__ __forceinline__ uint32_t smem_u32(const void* p) {
    uint32_t a;
    asm("{ .reg .u64 t; cvta.to.shared.u64 t, %1; cvt.u32.u64 %0, t; }" : "=r"(a) : "l"(p));
    return a;
}
__device__ __forceinline__ void cp16(uint32_t dst, const void* src) {
    asm volatile("cp.async.cg.shared.global [%0], [%1], 16;" :: "r"(dst), "l"(src));
}
__device__ __forceinline__ void ldsm_x4(uint32_t* r, uint32_t addr) {
    asm volatile("ldmatrix.sync.aligned.m8n8.x4.shared.b16 {%0,%1,%2,%3}, [%4];"
        : "=r"(r[0]), "=r"(r[1]), "=r"(r[2]), "=r"(r[3]) : "r"(addr));
}
__device__ __forceinline__ void ldsm_x2(uint32_t* r, uint32_t addr) {
    asm volatile("ldmatrix.sync.aligned.m8n8.x2.shared.b16 {%0,%1}, [%2];"
        : "=r"(r[0]), "=r"(r[1]) : "r"(addr));
}
__device__ __forceinline__ void ldsm_x4t(uint32_t* r, uint32_t addr) {
    asm volatile("ldmatrix.sync.aligned.m8n8.x4.trans.shared.b16 {%0,%1,%2,%3}, [%4];"
        : "=r"(r[0]), "=r"(r[1]), "=r"(r[2]), "=r"(r[3]) : "r"(addr));
}
__device__ __forceinline__ void mma_f16(float* c, const uint32_t* a, const uint32_t* b) {
    asm volatile(
        "mma.sync.aligned.m16n8k16.row.col.f32.f16.f16.f32 "
        "{%0,%1,%2,%3}, {%4,%5,%6,%7}, {%8,%9}, {%0,%1,%2,%3};"
        : "+f"(c[0]), "+f"(c[1]), "+f"(c[2]), "+f"(c[3])
        : "r"(a[0]), "r"(a[1]), "r"(a[2]), "r"(a[3]), "r"(b[0]), "r"(b[1]));
}
__device__ __forceinline__ uint32_t packh2(float a, float b) {
    __half2 h = __floats2half2_rn(a, b);
    return *(uint32_t*)&h;
}

// ---------------- merged weight transpose (all 4 weights, one launch) ----------------
__global__ __launch_bounds__(256) void wsplit_all(const float* __restrict__ Wqkv,
                                                  const float* __restrict__ Wproj,
                                                  const float* __restrict__ W1,
                                                  const float* __restrict__ W2)
{
    __shared__ float tile[32][33];
    int bid = blockIdx.x;
    const float* W; __half* Dst; int K, N, tilesX, tloc;
    if (bid < 1728)      { W = Wqkv;  Dst = g_wqkv_h;  K = 768;  N = 2304; tilesX = 72; tloc = bid; }
    else if (bid < 2304) { W = Wproj; Dst = g_wproj_h; K = 768;  N = 768;  tilesX = 24; tloc = bid - 1728; }
    else if (bid < 4608) { W = W1;    Dst = g_w1_h;    K = 768;  N = 3072; tilesX = 96; tloc = bid - 2304; }
    else                 { W = W2;    Dst = g_w2_h;    K = 3072; N = 768;  tilesX = 24; tloc = bid - 4608; }
    int tix = tloc % tilesX, tiy = tloc / tilesX;
    int k0 = tiy * 32, n0 = tix * 32;
    int tx = threadIdx.x & 31, ty = threadIdx.x >> 5;
    #pragma unroll
    for (int j = 0; j < 32; j += 8)
        tile[ty + j][tx] = W[(size_t)(k0 + ty + j) * N + n0 + tx];
    __syncthreads();
    #pragma unroll
    for (int j = 0; j < 32; j += 8)
        Dst[(size_t)(n0 + ty + j) * K + k0 + tx] = __float2half_rn(tile[tx][ty + j]);
}

// ---------------- LayerNorm 1 ----------------
__global__ __launch_bounds__(256) void ln1_kernel(const float* __restrict__ x,
                                                  const float* __restrict__ g,
                                                  const float* __restrict__ b)
{
    int widx = blockIdx.x;
    int win = widx / NTOK, tok = widx - win * NTOK;
    int bb = win / NWIN, rem = win - bb * NWIN;
    int y = (rem / 5) * WS + tok / WS;
    int xx = (rem % 5) * WS + tok % WS;
    size_t ob = (size_t)widx * DIM;
    int tid = threadIdx.x;
    if (y >= 64 || xx >= 64) {
        for (int i = tid; i < DIM; i += 256) g_a[ob + i] = __float2half(0.f);
        return;
    }
    const float* row = x + ((size_t)(bb * 64 + y) * 64 + xx) * DIM;
    float v0 = row[tid], v1 = row[tid + 256], v2 = row[tid + 512];
    float s = v0 + v1 + v2, sq = v0 * v0 + v1 * v1 + v2 * v2;
    #pragma unroll
    for (int off = 16; off; off >>= 1) {
        s  += __shfl_xor_sync(0xffffffffu, s, off);
        sq += __shfl_xor_sync(0xffffffffu, sq, off);
    }
    __shared__ float rs[8], rq[8], smu, srs;
    int wid = tid >> 5, lane = tid & 31;
    if (!lane) { rs[wid] = s; rq[wid] = sq; }
    __syncthreads();
    if (tid == 0) {
        float S = 0, Q = 0;
        #pragma unroll
        for (int i = 0; i < 8; i++) { S += rs[i]; Q += rq[i]; }
        float mu = S * (1.f / 768.f);
        float var = Q * (1.f / 768.f) - mu * mu;
        smu = mu; srs = rsqrtf(var + 1e-5f);
    }
    __syncthreads();
    float mu = smu, r = srs;
    #pragma unroll
    for (int p = 0; p < 3; p++) {
        int i = tid + p * 256;
        float vv = ((p == 0 ? v0 : p == 1 ? v1 : v2) - mu) * r * g[i] + b[i];
        g_a[ob + i] = __float2half_rn(vv);
    }
}

// ---------------- LayerNorm 2 ----------------
__global__ __launch_bounds__(256) void ln2_kernel(const float* __restrict__ g,
                                                  const float* __restrict__ b)
{
    int tid = threadIdx.x;
    const float* row = g_x2 + (size_t)blockIdx.x * DIM;
    size_t ob = (size_t)blockIdx.x * DIM;
    float v0 = row[tid], v1 = row[tid + 256], v2 = row[tid + 512];
    float s = v0 + v1 + v2, sq = v0 * v0 + v1 * v1 + v2 * v2;
    #pragma unroll
    for (int off = 16; off; off >>= 1) {
        s  += __shfl_xor_sync(0xffffffffu, s, off);
        sq += __shfl_xor_sync(0xffffffffu, sq, off);
    }
    __shared__ float rs[8], rq[8], smu, srs;
    int wid = tid >> 5, lane = tid & 31;
    if (!lane) { rs[wid] = s; rq[wid] = sq; }
    __syncthreads();
    if (tid == 0) {
        float S = 0, Q = 0;
        #pragma unroll
        for (int i = 0; i < 8; i++) { S += rs[i]; Q += rq[i]; }
        float mu = S * (1.f / 768.f);
        float var = Q * (1.f / 768.f) - mu * mu;
        smu = mu; srs = rsqrtf(var + 1e-5f);
    }
    __syncthreads();
    float mu = smu, r = srs;
    #pragma unroll
    for (int p = 0; p < 3; p++) {
        int i = tid + p * 256;
        float vv = ((p == 0 ? v0 : p == 1 ? v1 : v2) - mu) * r * g[i] + b[i];
        g_b[ob + i] = __float2half_rn(vv);
    }
}

// ---------------- mma.sync GEMM: 128 threads, 4 warps, warp tile 64x64 ----------------
#define MATB   16384
#define STAGE  (2 * MATB)
#define SMEM_TG (3 * STAGE)

template <int MODE>
__global__ __launch_bounds__(128, 2) void tgemm_kernel(const float* __restrict__ bias,
                                                       const float* __restrict__ aux,
                                                       float* __restrict__ outp)
{
    constexpr int K      = (MODE == 3) ? 3072 : 768;
    constexpr int Mreal  = (MODE <= 1) ? TOKW : TOKX;
    constexpr int NCHUNK = K / 64;
    const __half* gA  = (MODE == 0) ? g_a : (MODE == 1) ? g_ao : (MODE == 2) ? g_b : g_h1;
    const __half* gBh = (MODE == 0) ? g_wqkv_h : (MODE == 1) ? g_wproj_h : (MODE == 2) ? g_w1_h : g_w2_h;

    extern __shared__ char smem_raw[];
    const uint32_t sbase = smem_u32(smem_raw);

    const int t = threadIdx.x;
    const int m0 = blockIdx.y * 128;
    const int n0 = blockIdx.x * 128;
    const int warp = t >> 5, lane = t & 31;
    const int wm = warp >> 1, wn = warp & 1;

    float acc[4][8][4];
    #pragma unroll
    for (int a = 0; a < 4; a++)
        #pragma unroll
        for (int b2 = 0; b2 < 8; b2++)
            #pragma unroll
            for (int c = 0; c < 4; c++) acc[a][b2][c] = 0.f;

    const int ldrow = t >> 3, ldseg = t & 7;

    auto issue = [&](int chunk, int stg) {
        const int k0 = chunk * 64;
        const uint32_t so = sbase + (uint32_t)(stg * STAGE);
        #pragma unroll
        for (int p = 0; p < 8; p++) {
            int r = ldrow + p * 16;
            uint32_t off = (uint32_t)(r * 128 + ((ldseg ^ (r & 7)) << 4));
            size_t gaA = (size_t)(m0 + r) * K + k0 + ldseg * 8;
            size_t gaB = (size_t)(n0 + r) * K + k0 + ldseg * 8;
            cp16(so + off, gA + gaA);
            cp16(so + MATB + off, gBh + gaB);
        }
        asm volatile("cp.async.commit_group;" ::: "memory");
    };

    issue(0, 0);
    issue(1, 1);

    const int a_row_in = (lane & 7) + (lane & 8);
    const int a_kg     = lane >> 4;
    const int b_row16  = (lane & 7) + ((lane >> 4) << 3);
    const int b_kg     = (lane >> 3) & 1;

    for (int i = 0; i < NCHUNK; i++) {
        if (i + 1 < NCHUNK)
            asm volatile("cp.async.wait_group 1;" ::: "memory");
        else
            asm volatile("cp.async.wait_group 0;" ::: "memory");
        __syncthreads();
        if (i + 2 < NCHUNK) issue(i + 2, (i + 2) % 3);

        const uint32_t soA = sbase + (uint32_t)((i % 3) * STAGE);
        const uint32_t soB = soA + MATB;
        #pragma unroll
        for (int ks = 0; ks < 4; ks++) {
            uint32_t bh[8][2];
            #pragma unroll
            for (int pr = 0; pr < 4; pr++) {
                int nr = wn * 64 + pr * 16 + b_row16;
                uint32_t bd = soB + (uint32_t)(nr * 128 + (((ks * 2 + b_kg) ^ (nr & 7)) << 4));
                uint32_t r4[4];
                ldsm_x4(r4, bd);
                bh[2 * pr][0] = r4[0]; bh[2 * pr][1] = r4[1];
                bh[2 * pr + 1][0] = r4[2]; bh[2 * pr + 1][1] = r4[3];
            }
            #pragma unroll
            for (int mt = 0; mt < 4; mt++) {
                uint32_t ah[4];
                int mr = wm * 64 + mt * 16 + a_row_in;
                uint32_t ad = soA + (uint32_t)(mr * 128 + (((ks * 2 + a_kg) ^ (mr & 7)) << 4));
                ldsm_x4(ah, ad);
                #pragma unroll
                for (int nt = 0; nt < 8; nt++)
                    mma_f16(acc[mt][nt], ah, bh[nt]);
            }
        }
    }

    // ---- epilogue (vectorized stores) ----
    const int g = lane >> 2, tq = lane & 3;
    const int which0 = (MODE == 0) ? (n0 / 768) : 0;
    #pragma unroll
    for (int mt = 0; mt < 4; mt++) {
        #pragma unroll
        for (int half = 0; half < 2; half++) {
            int m = m0 + wm * 64 + mt * 16 + g + half * 8;
            bool valid = (m < Mreal);
            int win = 0, tok = 0, yy = 0, xx = 0, bb = 0;
            if (MODE <= 1) {
                win = m / NTOK; tok = m - win * NTOK;
                if (MODE == 1) {
                    bb = win / NWIN; int rem = win - bb * NWIN;
                    yy = (rem / 5) * WS + tok / WS;
                    xx = (rem % 5) * WS + tok % WS;
                    valid = valid && (yy < 64) && (xx < 64);
                }
            }
            if (!valid) continue;
            #pragma unroll
            for (int nt = 0; nt < 8; nt++) {
                int n = n0 + wn * 64 + nt * 8 + 2 * tq;
                float v0 = acc[mt][nt][half * 2]     + bias[n];
                float v1 = acc[mt][nt][half * 2 + 1] + bias[n + 1];
                if (MODE == 0) {
                    int dd = n - which0 * 768;
                    int head = dd >> 6, hd = dd & 63;
                    size_t o = ((size_t)(win * NHEAD + head) * NTOK + tok) * HDIM + hd;
                    if (which0 == 0)
                        *(__half2*)(g_qh + o) = __floats2half2_rn(v0 * 0.125f, v1 * 0.125f);
                    else if (which0 == 1)
                        *(__half2*)(g_kh + o) = __floats2half2_rn(v0, v1);
                    else
                        *(__half2*)(g_vh + o) = __floats2half2_rn(v0, v1);
                } else if (MODE == 1) {
                    size_t o = ((size_t)(bb * 64 + yy) * 64 + xx) * DIM + n;
                    float2 ax = *(const float2*)(aux + o);
                    *(float2*)(g_x2 + o) = make_float2(ax.x + v0, ax.y + v1);
                } else if (MODE == 2) {
                    float gl0 = 0.5f * v0 * (1.f + erff(v0 * 0.70710678118f));
                    float gl1 = 0.5f * v1 * (1.f + erff(v1 * 0.70710678118f));
                    size_t o = (size_t)m * 3072 + n;
                    *(__half2*)(g_h1 + o) = __floats2half2_rn(gl0, gl1);
                } else {
                    size_t o = (size_t)m * DIM + n;
                    float2 x2 = *(const float2*)(g_x2 + o);
                    *(float2*)(outp + o) = make_float2(v0 + x2.x, v1 + x2.y);
                }
            }
        }
    }
}

// ---------------- tensor-core attention: x4 fragment loads ----------------
#define ATT_QS_H   0
#define ATT_KS_H   14976
#define ATT_VS_H   29376
#define ATT_F_OFF  88704
#define ATT_B_OFF  90528
#define SM_ATT_TOTAL 91328

__global__ __launch_bounds__(256, 2) void attn_kernel(const float* __restrict__ rel_h,
                                                      const float* __restrict__ rel_w,
                                                      const int* __restrict__ q_idx,
                                                      const int* __restrict__ k_idx)
{
    extern __shared__ char smraw[];
    __half* qs  = (__half*)smraw;
    __half* ksm = qs + ATT_KS_H;
    __half* vsm = qs + ATT_VS_H;
    float* Shf  = (float*)(smraw + ATT_F_OFF);
    float* Swf  = Shf + 196;
    float* rshf = Swf + 196;
    float* rswf = rshf + 32;
    unsigned char* qr8 = (unsigned char*)(smraw + ATT_B_OFF);
    unsigned char* qc8 = qr8 + 196;
    unsigned char* kr8 = qc8 + 196;
    unsigned char* kc8 = kr8 + 196;

    const uint32_t sb = smem_u32(smraw);
    int bh = blockIdx.x;
    int win = bh / NHEAD, head = bh - win * NHEAD;
    int tid = threadIdx.x, warp = tid >> 5, lane = tid & 31;

    const __half* qg = g_qh + (size_t)bh * NTOK * HDIM;
    const __half* kg = g_kh + (size_t)bh * NTOK * HDIM;
    const __half* vg = g_vh + (size_t)bh * NTOK * HDIM;
    for (int i = tid; i < 196 * 8; i += 256) {
        int r = i >> 3, sg = i & 7;
        *(uint4*)(qs  + r * 72 + sg * 8) = *(const uint4*)(qg + r * 64 + sg * 8);
        *(uint4*)(ksm + r * 72 + sg * 8) = *(const uint4*)(kg + r * 64 + sg * 8);
        *(uint4*)(vsm + r * 72 + sg * 8) = *(const uint4*)(vg + r * 64 + sg * 8);
    }
    uint4 z = make_uint4(0, 0, 0, 0);
    for (int i = tid; i < 224; i += 256) {
        if (i < 96)       { int r = 196 + (i >> 3);        *(uint4*)(qs  + r * 72 + (i & 7) * 8) = z; }
        else if (i < 128) { int j = i - 96;  int r = 196 + (j >> 3); *(uint4*)(ksm + r * 72 + (j & 7) * 8) = z; }
        else              { int j = i - 128; int r = 196 + (j >> 3); *(uint4*)(vsm + r * 72 + (j & 7) * 8) = z; }
    }
    if (tid < 27) {
        const float* rp = rel_h + tid * HDIM;
        float s = 0;
        #pragma unroll 8
        for (int c = 0; c < HDIM; c++) s += rp[c];
        rshf[tid] = s;
    } else if (tid >= 32 && tid < 59) {
        const float* rp = rel_w + (tid - 32) * HDIM;
        float s = 0;
        #pragma unroll 8
        for (int c = 0; c < HDIM; c++) s += rp[c];
        rswf[tid - 32] = s;
    }
    if (tid < 196) {
        int qi = q_idx[(size_t)bh * NTOK + tid];
        int ki = k_idx[(size_t)bh * NTOK + tid];
        qr8[tid] = (unsigned char)(qi / WS);
        qc8[tid] = (unsigned char)(qi % WS);
        kr8[tid] = (unsigned char)(ki / WS);
        kc8[tid] = (unsigned char)(ki % WS);
    }
    __syncthreads();
    if (tid < 196) {
        int i = tid / WS, j = tid - i * WS;
        Shf[tid] = rshf[i - j + WS - 1];
        Swf[tid] = rswf[i - j + WS - 1];
    }
    __syncthreads();

    const int g = lane >> 2, tq = lane & 3;
    const int a_row_in = (lane & 7) + (lane & 8);
    const int a_koff   = (lane >> 4) * 8;
    // paired-x4 K-fragment addressing (two n-tiles per ldsm)
    const int kb_row16 = (lane & 7) + ((lane >> 4) << 3);   // 0..15 (pair row)
    const int kb_kg    = (lane >> 3) & 1;                   // k half
    // x4.trans V addressing (two d-tiles per ldsm)
    const int v_row16  = lane & 15;
    const int v_dhalf  = lane >> 4;                         // 0/1 -> dt, dt+1
    const uint32_t kbase = sb + ATT_KS_H * 2;
    const uint32_t vbase = sb + ATT_VS_H * 2;

    for (int mt = warp; mt < 13; mt += 8) {
        float sacc[25][4];
        #pragma unroll
        for (int nt = 0; nt < 25; nt++)
            #pragma unroll
            for (int c = 0; c < 4; c++) sacc[nt][c] = 0.f;

        #pragma unroll
        for (int kk = 0; kk < 4; kk++) {
            uint32_t af[4];
            uint32_t qa = sb + (uint32_t)(((mt * 16 + a_row_in) * 72 + kk * 16 + a_koff) * 2);
            ldsm_x4(af, qa);
            // 12 paired x4 loads cover n-tiles 0..23; tile 24 via x2-equivalent x4 reuse
            #pragma unroll
            for (int np = 0; np < 12; np++) {
                uint32_t r4[4];
                uint32_t ka = kbase + (uint32_t)(((np * 16 + kb_row16) * 72 + kk * 16 + kb_kg * 8) * 2);
                ldsm_x4(r4, ka);
                mma_f16(sacc[2 * np],     af, r4);
                mma_f16(sacc[2 * np + 1], af, r4 + 2);
            }
            {
                // last tile (nt=24): rows 192..199 (200 rows staged, zero-padded)
                uint32_t bf[2];
                uint32_t ka = kbase + (uint32_t)(((24 * 8 + (lane & 7)) * 72 + kk * 16 + ((lane >> 3) & 1) * 8) * 2);
                ldsm_x2(bf, ka);
                mma_f16(sacc[24], af, bf);
            }
        }

        int row0 = mt * 16 + g;
        int row1 = row0 + 8;
        int qb0 = qr8[row0] * WS, qc0 = qc8[row0] * WS;
        int qb1 = qr8[row1] * WS, qc1 = qc8[row1] * WS;
        float mx0 = -1e30f, mx1 = -1e30f;
        #pragma unroll
        for (int nt = 0; nt < 25; nt++) {
            #pragma unroll
            for (int c = 0; c < 2; c++) {
                int col = nt * 8 + tq * 2 + c;
                float s0, s1;
                if (col < 196) {
                    int kr = kr8[col], kc = kc8[col];
                    s0 = sacc[nt][c]     + Shf[qb0 + kr] + Swf[qc0 + kc];
                    s1 = sacc[nt][2 + c] + Shf[qb1 + kr] + Swf[qc1 + kc];
                } else {
                    s0 = -1e30f; s1 = -1e30f;
                }
                sacc[nt][c] = s0; sacc[nt][2 + c] = s1;
                mx0 = fmaxf(mx0, s0); mx1 = fmaxf(mx1, s1);
            }
        }
        mx0 = fmaxf(mx0, __shfl_xor_sync(0xffffffffu, mx0, 1));
        mx0 = fmaxf(mx0, __shfl_xor_sync(0xffffffffu, mx0, 2));
        mx1 = fmaxf(mx1, __shfl_xor_sync(0xffffffffu, mx1, 1));
        mx1 = fmaxf(mx1, __shfl_xor_sync(0xffffffffu, mx1, 2));

        float sm0 = 0.f, sm1 = 0.f;
        uint32_t pf[13][4];
        #pragma unroll
        for (int nt = 0; nt < 25; nt++) {
            float e00 = expf(sacc[nt][0] - mx0);
            float e01 = expf(sacc[nt][1] - mx0);
            float e10 = expf(sacc[nt][2] - mx1);
            float e11 = expf(sacc[nt][3] - mx1);
            sm0 += e00 + e01;
            sm1 += e10 + e11;
            int kt = nt >> 1, hi = nt & 1;
            pf[kt][hi * 2 + 0] = packh2(e00, e01);
            pf[kt][hi * 2 + 1] = packh2(e10, e11);
        }
        pf[12][2] = 0u; pf[12][3] = 0u;
        sm0 += __shfl_xor_sync(0xffffffffu, sm0, 1);
        sm0 += __shfl_xor_sync(0xffffffffu, sm0, 2);
        sm1 += __shfl_xor_sync(0xffffffffu, sm1, 1);
        sm1 += __shfl_xor_sync(0xffffffffu, sm1, 2);
        float inv0 = 1.f / sm0, inv1 = 1.f / sm1;

        float oacc[8][4];
        #pragma unroll
        for (int dt = 0; dt < 8; dt++)
            #pragma unroll
            for (int c = 0; c < 4; c++) oacc[dt][c] = 0.f;
        #pragma unroll
        for (int kt = 0; kt < 13; kt++) {
            #pragma unroll
            for (int dp = 0; dp < 4; dp++) {
                uint32_t r4[4];
                uint32_t va = vbase + (uint32_t)(((kt * 16 + v_row16) * 72 + (dp * 2 + v_dhalf) * 8) * 2);
                ldsm_x4t(r4, va);
                mma_f16(oacc[2 * dp],     pf[kt], r4);
                mma_f16(oacc[2 * dp + 1], pf[kt], r4 + 2);
            }
        }

        bool ok0 = row0 < NTOK, ok1 = row1 < NTOK;
        size_t ob0 = ((size_t)(win * NTOK) + row0) * DIM + head * HDIM;
        #pragma unroll
        for (int dt = 0; dt < 8; dt++) {
            int d = dt * 8 + tq * 2;
            if (ok0) {
                *(__half2*)(g_ao + ob0 + d) = __floats2half2_rn(oacc[dt][0] * inv0, oacc[dt][1] * inv0);
            }
            if (ok1) {
                *(__half2*)(g_ao + ob0 + (size_t)8 * DIM + d) = __floats2half2_rn(oacc[dt][2] * inv1, oacc[dt][3] * inv1);
            }
        }
    }
}

// ---------------- launch ----------------
extern "C" void kernel_launch(void* const* d_in, const int* in_sizes, int n_in,
                              void* d_out, int out_size)
{
    const float* x     = (const float*)d_in[0];
    const int*   qidx  = (const int*)d_in[1];
    const int*   kidx  = (const int*)d_in[2];
    const float* ln1w  = (const float*)d_in[3];
    const float* ln1b  = (const float*)d_in[4];
    const float* ln2w  = (const float*)d_in[5];
    const float* ln2b  = (const float*)d_in[6];
    const float* qkvw  = (const float*)d_in[7];
    const float* qkvb  = (const float*)d_in[8];
    const float* projw = (const float*)d_in[9];
    const float* projb = (const float*)d_in[10];
    const float* relh  = (const float*)d_in[11];
    const float* relw  = (const float*)d_in[12];
    const float* w1    = (const float*)d_in[13];
    const float* b1    = (const float*)d_in[14];
    const float* w2    = (const float*)d_in[15];
    const float* b2    = (const float*)d_in[16];
    float* out = (float*)d_out;

    cudaFuncSetAttribute(attn_kernel, cudaFuncAttributeMaxDynamicSharedMemorySize, SM_ATT_TOTAL);
    cudaFuncSetAttribute(tgemm_kernel<0>, cudaFuncAttributeMaxDynamicSharedMemorySize, SMEM_TG);
    cudaFuncSetAttribute(tgemm_kernel<1>, cudaFuncAttributeMaxDynamicSharedMemorySize, SMEM_TG);
    cudaFuncSetAttribute(tgemm_kernel<2>, cudaFuncAttributeMaxDynamicSharedMemorySize, SMEM_TG);
    cudaFuncSetAttribute(tgemm_kernel<3>, cudaFuncAttributeMaxDynamicSharedMemorySize, SMEM_TG);

    // launch index 3 = attn_kernel (ncu profiles it)
    wsplit_all<<<6912, 256>>>(qkvw, projw, w1, w2);                                        // 0
    ln1_kernel<<<TOKW, 256>>>(x, ln1w, ln1b);                                              // 1
    tgemm_kernel<0><<<dim3(2304 / 128, TOKW_PAD / 128), 128, SMEM_TG>>>(qkvb, nullptr, nullptr); // 2
    attn_kernel<<<BH, 256, SM_ATT_TOTAL>>>(relh, relw, qidx, kidx);                        // 3
    tgemm_kernel<1><<<dim3(768 / 128, TOKW_PAD / 128), 128, SMEM_TG>>>(projb, x, nullptr); // 4
    ln2_kernel<<<TOKX, 256>>>(ln2w, ln2b);                                                 // 5
    tgemm_kernel<2><<<dim3(3072 / 128, TOKX / 128), 128, SMEM_TG>>>(b1, nullptr, nullptr); // 6
    tgemm_kernel<3><<<dim3(768 / 128, TOKX / 128), 128, SMEM_TG>>>(b2, nullptr, out);      // 7
}